// round 3
// baseline (speedup 1.0000x reference)
#include <cuda_runtime.h>
#include <cstdint>

// Problem constants
constexpr int Bb  = 2;
constexpr int NC  = 256;
constexpr int CN  = 256;
constexpr int K   = 16;
constexpr int DN  = 64;
constexpr int HM  = 128;
constexpr int F   = 192;   // 3*DN
constexpr int HMOD = 64;
constexpr int MOD_OUT = 5;

constexpr int AP = 266;    // A-tile pitch (floats). 266*4=1064B: 8B-aligned rows, good bank spread.

// Scratch (static device globals; no runtime allocation)
__device__ float g_agg[(size_t)Bb * NC * CN * DN];   //  33.5 MB
__device__ float g_mh [(size_t)Bb * NC * CN * HM];   //  67.1 MB

__device__ __forceinline__ float gelu_f(float x) {
    float x3 = x * x * x;
    return 0.5f * x * (1.0f + tanhf(0.7978845608028654f * (x + 0.044715f * x3)));
}

typedef unsigned long long u64;

__device__ __forceinline__ void fma2(u64& d, u64 a, u64 b) {
    asm("fma.rn.f32x2 %0, %1, %2, %0;" : "+l"(d) : "l"(a), "l"(b));
}

// ---------------------------------------------------------------------------
// Kernel 1: connection-weighted aggregation.
// ---------------------------------------------------------------------------
__global__ __launch_bounds__(256) void agg_kernel(
    const float* __restrict__ h,
    const float* __restrict__ w_conn,
    const int*   __restrict__ conn)
{
    extern __shared__ float smf[];
    float4* h_sm = reinterpret_cast<float4*>(smf);   // [256][16] float4

    int bn = blockIdx.x;
    int n  = bn & (NC - 1);

    const float4* hg = reinterpret_cast<const float4*>(h) + (size_t)bn * CN * DN / 4;
    for (int i = threadIdx.x; i < CN * DN / 4; i += 256) h_sm[i] = hg[i];
    __syncthreads();

    int dq = threadIdx.x & 3;
    int cr = threadIdx.x >> 2;

    for (int cp = 0; cp < 4; cp++) {
        int c = cp * 64 + cr;
        float4 a0 = {0,0,0,0}, a1 = {0,0,0,0}, a2 = {0,0,0,0}, a3 = {0,0,0,0};
        const int*   ci = conn   + ((size_t)n  * CN + c) * K;
        const float* wc = w_conn + ((size_t)bn * CN + c) * K;
        #pragma unroll
        for (int k = 0; k < K; k++) {
            int   idx = ci[k];
            float w   = wc[k];
            const float4* row = h_sm + idx * (DN / 4) + dq * 4;
            float4 r0 = row[0], r1 = row[1], r2 = row[2], r3 = row[3];
            a0.x += w * r0.x; a0.y += w * r0.y; a0.z += w * r0.z; a0.w += w * r0.w;
            a1.x += w * r1.x; a1.y += w * r1.y; a1.z += w * r1.z; a1.w += w * r1.w;
            a2.x += w * r2.x; a2.y += w * r2.y; a2.z += w * r2.z; a2.w += w * r2.w;
            a3.x += w * r3.x; a3.y += w * r3.y; a3.z += w * r3.z; a3.w += w * r3.w;
        }
        float4* out = reinterpret_cast<float4*>(g_agg + ((size_t)bn * CN + c) * DN) + dq * 4;
        out[0] = a0; out[1] = a1; out[2] = a2; out[3] = a3;
    }
}

// ---------------------------------------------------------------------------
// Kernel 2/4: grouped MLP layer 1.  C[256x128] = feat[256x192] @ W1^T, gelu.
// W pre-duplicated in smem as (w,w) float2 -> b operand is broadcast LDS.128.
// a operand: natural LDS.64 c-pair from scalar k-major A tile. Zero MOVs.
// ---------------------------------------------------------------------------
template<int MODE>
__global__ __launch_bounds__(512, 1) void mlp1_kernel(
    const float* __restrict__ h,
    const float* __restrict__ s1,     // MODE 1: msg; MODE 0: unused (g_agg)
    const float* __restrict__ s2,     // MODE 0: neuron_id; MODE 1: cell_context
    const float* __restrict__ w1,     // [G][HM][F]
    const float* __restrict__ b1,     // [G][HM]
    const int*   __restrict__ c2g)
{
    extern __shared__ float sm[];
    float*  A  = sm;                                  // [32][AP]
    float2* Wd = reinterpret_cast<float2*>(sm + 32 * AP);   // [F][HM] dup pairs
    float*  Bs = sm + 32 * AP + F * HM * 2;           // [HM]

    int bn  = blockIdx.x;
    int n   = bn & (NC - 1);
    int g   = c2g[n];
    int tid = threadIdx.x;

    // Stage W duplicated + transposed: Wd[k][j] = (W[j][k], W[j][k])
    {
        const float* Wg = w1 + (size_t)g * HM * F;
        #pragma unroll
        for (int p = 0; p < 12; p++) {
            int i  = p * 512 + tid;          // 0..6143
            int j  = i & 127;
            int kq = i >> 7;                 // 0..47
            float4 v = *reinterpret_cast<const float4*>(Wg + (size_t)j * F + kq * 4);
            Wd[(kq * 4 + 0) * HM + j] = make_float2(v.x, v.x);
            Wd[(kq * 4 + 1) * HM + j] = make_float2(v.y, v.y);
            Wd[(kq * 4 + 2) * HM + j] = make_float2(v.z, v.z);
            Wd[(kq * 4 + 3) * HM + j] = make_float2(v.w, v.w);
        }
        if (tid < HM) Bs[tid] = b1[g * HM + tid];
    }

    int tc = tid & 31, tj = tid >> 5;     // 16 warps
    int j0 = tj * 8;

    u64 acc[4][8];
    #pragma unroll
    for (int u = 0; u < 4; u++)
        #pragma unroll
        for (int j = 0; j < 8; j++) acc[u][j] = 0ULL;

    // staging decomposition: c = cp*64 + ch*8 + cl, k-quad = kq4
    int cl  = tid & 7;
    int kq4 = (tid >> 3) & 7;
    int ch  = tid >> 6;                   // 0..7

    const float* base_h = h + (size_t)bn * CN * DN;
    const float* base1  = (MODE == 0) ? (g_agg + (size_t)bn * CN * DN)
                                      : (s1    + (size_t)bn * CN * DN);
    const float* base2  = (MODE == 0) ? (s2 + (size_t)n * CN * DN)
                                      : (s2 + (size_t)bn * DN);

    for (int t = 0; t < 6; t++) {
        __syncthreads();
        const float* src = (t < 2) ? base_h : ((t < 4) ? base1 : base2);
        int fo = (t & 1) * 32;
        #pragma unroll
        for (int cp = 0; cp < 4; cp++) {
            int c = cp * 64 + ch * 8 + cl;
            float4 v;
            if (MODE == 1 && t >= 4)
                v = *reinterpret_cast<const float4*>(base2 + fo + kq4 * 4);  // ctx bcast
            else
                v = *reinterpret_cast<const float4*>(src + (size_t)c * DN + fo + kq4 * 4);
            A[(kq4 * 4 + 0) * AP + c] = v.x;
            A[(kq4 * 4 + 1) * AP + c] = v.y;
            A[(kq4 * 4 + 2) * AP + c] = v.z;
            A[(kq4 * 4 + 3) * AP + c] = v.w;
        }
        __syncthreads();

        const float2* wbase = Wd + (size_t)(t * 32) * HM + j0;
        #pragma unroll 4
        for (int k = 0; k < 32; k++) {
            const float* ar = A + k * AP + 2 * tc;
            u64 a0 = *reinterpret_cast<const u64*>(ar);
            u64 a1 = *reinterpret_cast<const u64*>(ar + 64);
            u64 a2 = *reinterpret_cast<const u64*>(ar + 128);
            u64 a3 = *reinterpret_cast<const u64*>(ar + 192);
            const ulonglong2* wl = reinterpret_cast<const ulonglong2*>(wbase + (size_t)k * HM);
            ulonglong2 b0 = wl[0], b1v = wl[1], b2 = wl[2], b3 = wl[3];
            #pragma unroll
            for (int u = 0; u < 4; u++) {
                u64 a = (u == 0) ? a0 : (u == 1) ? a1 : (u == 2) ? a2 : a3;
                fma2(acc[u][0], a, b0.x);
                fma2(acc[u][1], a, b0.y);
                fma2(acc[u][2], a, b1v.x);
                fma2(acc[u][3], a, b1v.y);
                fma2(acc[u][4], a, b2.x);
                fma2(acc[u][5], a, b2.y);
                fma2(acc[u][6], a, b3.x);
                fma2(acc[u][7], a, b3.y);
            }
        }
    }

    float bb[8];
    #pragma unroll
    for (int jj = 0; jj < 8; jj++) bb[jj] = Bs[j0 + jj];

    #pragma unroll
    for (int u = 0; u < 4; u++) {
        int c = 2 * tc + 64 * u;
        float lo[8], hi[8];
        #pragma unroll
        for (int jj = 0; jj < 8; jj++) {
            float2 v = *reinterpret_cast<float2*>(&acc[u][jj]);
            lo[jj] = gelu_f(v.x + bb[jj]);
            hi[jj] = gelu_f(v.y + bb[jj]);
        }
        float* op0 = g_mh + ((size_t)bn * CN + c)     * HM + j0;
        float* op1 = g_mh + ((size_t)bn * CN + c + 1) * HM + j0;
        *reinterpret_cast<float4*>(op0)     = make_float4(lo[0], lo[1], lo[2], lo[3]);
        *reinterpret_cast<float4*>(op0 + 4) = make_float4(lo[4], lo[5], lo[6], lo[7]);
        *reinterpret_cast<float4*>(op1)     = make_float4(hi[0], hi[1], hi[2], hi[3]);
        *reinterpret_cast<float4*>(op1 + 4) = make_float4(hi[4], hi[5], hi[6], hi[7]);
    }
}

// ---------------------------------------------------------------------------
// Kernel 3/5: grouped MLP layer 2.  C[256x64] = mh[256x128] @ W2^T (+bias,+res).
// Full K=128 A-tile staged once. 512 threads: 8 j-warps x 2 c-halves.
// ---------------------------------------------------------------------------
template<int MODE>
__global__ __launch_bounds__(512, 1) void mlp2_kernel(
    const float* __restrict__ w2,     // [G][DN][HM]
    const float* __restrict__ b2,     // [G][DN]
    const int*   __restrict__ c2g,
    const float* __restrict__ h,      // residual source (MODE 1)
    float*       __restrict__ out)
{
    extern __shared__ float sm[];
    float*  A  = sm;                                    // [128][AP]
    float2* Wd = reinterpret_cast<float2*>(sm + 128 * AP);   // [HM][DN] dup pairs
    float*  Bs = sm + 128 * AP + HM * DN * 2;           // [DN]

    int bn  = blockIdx.x;
    int n   = bn & (NC - 1);
    int g   = c2g[n];
    int tid = threadIdx.x;

    // Stage W2 duplicated + transposed: Wd[k][j] = (W2[j][k], W2[j][k])
    {
        const float* Wg = w2 + (size_t)g * DN * HM;
        #pragma unroll
        for (int p = 0; p < 4; p++) {
            int i  = p * 512 + tid;          // 0..2047
            int j  = i & 63;
            int kq = i >> 6;                 // 0..31
            float4 v = *reinterpret_cast<const float4*>(Wg + (size_t)j * HM + kq * 4);
            Wd[(kq * 4 + 0) * DN + j] = make_float2(v.x, v.x);
            Wd[(kq * 4 + 1) * DN + j] = make_float2(v.y, v.y);
            Wd[(kq * 4 + 2) * DN + j] = make_float2(v.z, v.z);
            Wd[(kq * 4 + 3) * DN + j] = make_float2(v.w, v.w);
        }
        if (tid < DN) Bs[tid] = b2[g * DN + tid];
    }

    // Stage A: A[k][c] = mh[c][k], k=0..127
    {
        int cl = tid & 7;
        int kq = (tid >> 3) & 31;
        int ch = tid >> 8;                   // 0..1
        const float* mh = g_mh + (size_t)bn * CN * HM;
        #pragma unroll 4
        for (int cp = 0; cp < 16; cp++) {
            int c = cp * 16 + ch * 8 + cl;
            float4 v = *reinterpret_cast<const float4*>(mh + (size_t)c * HM + kq * 4);
            A[(kq * 4 + 0) * AP + c] = v.x;
            A[(kq * 4 + 1) * AP + c] = v.y;
            A[(kq * 4 + 2) * AP + c] = v.z;
            A[(kq * 4 + 3) * AP + c] = v.w;
        }
    }
    __syncthreads();

    int tc = tid & 31, tw = tid >> 5;      // 16 warps
    int j0 = (tw & 7) * 8;                 // 8 j-groups cover 64
    int chalf = (tw >> 3) * 128;           // 2 c-halves

    u64 acc[2][8];
    #pragma unroll
    for (int u = 0; u < 2; u++)
        #pragma unroll
        for (int j = 0; j < 8; j++) acc[u][j] = 0ULL;

    const float2* wbase = Wd + j0;

    #pragma unroll 4
    for (int k = 0; k < 128; k++) {
        const float* ar = A + k * AP + chalf + 2 * tc;
        u64 a0 = *reinterpret_cast<const u64*>(ar);
        u64 a1 = *reinterpret_cast<const u64*>(ar + 64);
        const ulonglong2* wl = reinterpret_cast<const ulonglong2*>(wbase + (size_t)k * DN);
        ulonglong2 b0 = wl[0], b1v = wl[1], b2 = wl[2], b3 = wl[3];
        #pragma unroll
        for (int u = 0; u < 2; u++) {
            u64 a = (u == 0) ? a0 : a1;
            fma2(acc[u][0], a, b0.x);
            fma2(acc[u][1], a, b0.y);
            fma2(acc[u][2], a, b1v.x);
            fma2(acc[u][3], a, b1v.y);
            fma2(acc[u][4], a, b2.x);
            fma2(acc[u][5], a, b2.y);
            fma2(acc[u][6], a, b3.x);
            fma2(acc[u][7], a, b3.y);
        }
    }

    float bb[8];
    #pragma unroll
    for (int jj = 0; jj < 8; jj++) bb[jj] = Bs[j0 + jj];

    #pragma unroll
    for (int u = 0; u < 2; u++) {
        int c = chalf + 2 * tc + 64 * u;
        float lo[8], hi[8];
        #pragma unroll
        for (int jj = 0; jj < 8; jj++) {
            float2 v = *reinterpret_cast<float2*>(&acc[u][jj]);
            lo[jj] = v.x + bb[jj];
            hi[jj] = v.y + bb[jj];
        }
        if (MODE == 1) {
            const float* hp0 = h + ((size_t)bn * CN + c)     * DN + j0;
            const float* hp1 = h + ((size_t)bn * CN + c + 1) * DN + j0;
            #pragma unroll
            for (int jj = 0; jj < 8; jj++) { lo[jj] += hp0[jj]; hi[jj] += hp1[jj]; }
        }
        float* op0 = out + ((size_t)bn * CN + c)     * DN + j0;
        float* op1 = out + ((size_t)bn * CN + c + 1) * DN + j0;
        *reinterpret_cast<float4*>(op0)     = make_float4(lo[0], lo[1], lo[2], lo[3]);
        *reinterpret_cast<float4*>(op0 + 4) = make_float4(lo[4], lo[5], lo[6], lo[7]);
        *reinterpret_cast<float4*>(op1)     = make_float4(hi[0], hi[1], hi[2], hi[3]);
        *reinterpret_cast<float4*>(op1 + 4) = make_float4(hi[4], hi[5], hi[6], hi[7]);
    }
}

// ---------------------------------------------------------------------------
// Kernel 6: per-cell modulation MLP on pooled stats.
// ---------------------------------------------------------------------------
__global__ __launch_bounds__(256) void mod_kernel(
    const float* __restrict__ hnew,
    const float* __restrict__ msg,
    const float* __restrict__ mw1,    // [NC][2DN][HMOD]
    const float* __restrict__ mb1,
    const float* __restrict__ mw2,    // [NC][HMOD][MOD_OUT]
    const float* __restrict__ mb2,
    float*       __restrict__ mod)
{
    __shared__ float part[8][DN];
    __shared__ float pooled[2 * DN];
    __shared__ float ph[HMOD];

    int bn  = blockIdx.x;
    int n   = bn & (NC - 1);
    int tid = threadIdx.x;

    int d  = tid & 63;
    int cg = tid >> 6;
    {
        const float* p1 = hnew + (size_t)bn * CN * DN + (size_t)cg * 64 * DN + d;
        const float* p2 = msg  + (size_t)bn * CN * DN + (size_t)cg * 64 * DN + d;
        float s1 = 0.0f, s2 = 0.0f;
        #pragma unroll 8
        for (int i = 0; i < 64; i++) {
            s1 += p1[(size_t)i * DN];
            s2 += p2[(size_t)i * DN];
        }
        part[cg][d]     = s1;
        part[4 + cg][d] = s2;
    }
    __syncthreads();

    if (tid < 2 * DN) {
        int base = (tid < DN) ? 0 : 4;
        int dd   = tid & 63;
        pooled[tid] = (part[base][dd] + part[base + 1][dd] +
                       part[base + 2][dd] + part[base + 3][dd]) * (1.0f / CN);
    }
    __syncthreads();

    if (tid < HMOD) {
        const float* w = mw1 + (size_t)n * (2 * DN) * HMOD + tid;
        float acc = mb1[n * HMOD + tid];
        #pragma unroll 8
        for (int f = 0; f < 2 * DN; f++) acc = fmaf(pooled[f], w[f * HMOD], acc);
        ph[tid] = gelu_f(acc);
    }
    __syncthreads();

    if (tid < MOD_OUT) {
        const float* w = mw2 + (size_t)n * HMOD * MOD_OUT + tid;
        float acc = mb2[n * MOD_OUT + tid];
        #pragma unroll 8
        for (int k = 0; k < HMOD; k++) acc = fmaf(ph[k], w[k * MOD_OUT], acc);
        mod[bn * MOD_OUT + tid] = acc;
    }
}

// ---------------------------------------------------------------------------
// Launch
// ---------------------------------------------------------------------------
extern "C" void kernel_launch(void* const* d_in, const int* in_sizes, int n_in,
                              void* d_out, int out_size)
{
    const float* h      = (const float*)d_in[0];
    const float* w_conn = (const float*)d_in[1];
    const float* ctx    = (const float*)d_in[2];
    const float* nid    = (const float*)d_in[3];
    const float* mw1    = (const float*)d_in[4];
    const float* mb1    = (const float*)d_in[5];
    const float* mw2    = (const float*)d_in[6];
    const float* mb2    = (const float*)d_in[7];
    const float* sw1    = (const float*)d_in[8];
    const float* sb1    = (const float*)d_in[9];
    const float* sw2    = (const float*)d_in[10];
    const float* sb2    = (const float*)d_in[11];
    const float* modw1  = (const float*)d_in[12];
    const float* modb1  = (const float*)d_in[13];
    const float* modw2  = (const float*)d_in[14];
    const float* modb2  = (const float*)d_in[15];
    const int*   conn   = (const int*)d_in[16];
    const int*   c2g    = (const int*)d_in[17];

    float* out   = (float*)d_out;
    float* o_h   = out;
    float* o_msg = out + (size_t)Bb * NC * CN * DN;
    float* o_mod = o_msg + (size_t)Bb * NC * CN * DN;

    const int grid = Bb * NC;  // 512

    const size_t smA = (size_t)CN * DN * sizeof(float);                          // 64 KB
    const size_t sm1 = (size_t)(32 * AP + F * HM * 2 + HM) * sizeof(float);      // ~231 KB
    const size_t sm2 = (size_t)(128 * AP + HM * DN * 2 + DN) * sizeof(float);    // ~198 KB

    static bool attr_done = false;
    if (!attr_done) {
        cudaFuncSetAttribute(agg_kernel,     cudaFuncAttributeMaxDynamicSharedMemorySize, (int)smA);
        cudaFuncSetAttribute(mlp1_kernel<0>, cudaFuncAttributeMaxDynamicSharedMemorySize, (int)sm1);
        cudaFuncSetAttribute(mlp1_kernel<1>, cudaFuncAttributeMaxDynamicSharedMemorySize, (int)sm1);
        cudaFuncSetAttribute(mlp2_kernel<0>, cudaFuncAttributeMaxDynamicSharedMemorySize, (int)sm2);
        cudaFuncSetAttribute(mlp2_kernel<1>, cudaFuncAttributeMaxDynamicSharedMemorySize, (int)sm2);
        attr_done = true;
    }

    agg_kernel<<<grid, 256, smA>>>(h, w_conn, conn);
    mlp1_kernel<0><<<grid, 512, sm1>>>(h, nullptr, nid, mw1, mb1, c2g);
    mlp2_kernel<0><<<grid, 512, sm2>>>(mw2, mb2, c2g, h, o_msg);
    mlp1_kernel<1><<<grid, 512, sm1>>>(h, o_msg, ctx, sw1, sb1, c2g);
    mlp2_kernel<1><<<grid, 512, sm2>>>(sw2, sb2, c2g, h, o_h);
    mod_kernel<<<grid, 256>>>(o_h, o_msg, modw1, modb1, modw2, modb2, o_mod);
}

// round 6
// speedup vs baseline: 2.1651x; 2.1651x over previous
#include <cuda_runtime.h>
#include <cstdint>

typedef unsigned long long u64;

// Problem constants
constexpr int Bb  = 2;
constexpr int NC  = 256;
constexpr int CN  = 256;
constexpr int K   = 16;
constexpr int DN  = 64;
constexpr int HM  = 128;
constexpr int F   = 192;
constexpr int HMOD = 64;
constexpr int MOD_OUT = 5;

// Scratch
__device__ float g_agg[(size_t)Bb * NC * CN * DN];

// ---------------- SMEM layout (bytes) --------------------------------------
constexpr int OFF_TMEM = 0;
constexpr int OFF_MBAR = 8;
constexpr int OFF_B1S  = 16;              // 128 floats
constexpr int OFF_B2S  = 528;             // 64 floats
constexpr int OFF_AH   = 1024;            // 32KB: W1-chunk [128x64] / W2 [64x128]
constexpr int OFF_AL   = 1024 + 32768;    // 32KB
constexpr int OFF_BH   = 1024 + 65536;    // 64KB: feat [256x64] / hidden [128x128]
constexpr int OFF_BL   = 1024 + 131072;   // 64KB
constexpr int SMEM_MLP = 1024 + 196608;   // 197632 B

// tcgen05 only exists in arch-specific targets; the harness's extra plain
// compute_103 pass takes the SIMT fallback branch.
#if defined(__CUDA_ARCH_FEAT_SM103_ALL) || defined(__CUDA_ARCH_FEAT_SM100_ALL) || defined(__CUDA_ARCH_FEAT_SM101_ALL)
#define HAS_TCGEN05 1
#else
#define HAS_TCGEN05 0
#endif

__device__ __forceinline__ uint32_t smem_u32(const void* p) {
    uint32_t a;
    asm("{ .reg .u64 t; cvta.to.shared.u64 t, %1; cvt.u32.u64 %0, t; }"
        : "=r"(a) : "l"(p));
    return a;
}

#if HAS_TCGEN05
__device__ __forceinline__ uint32_t elect1() {
    uint32_t p;
    asm volatile("{ .reg .pred p; elect.sync _|p, 0xFFFFFFFF; selp.b32 %0, 1, 0, p; }"
                 : "=r"(p));
    return p;
}

#define TC_ALLOC(smem_addr, n) \
    asm volatile("tcgen05.alloc.cta_group::1.sync.aligned.shared::cta.b32 [%0], %1;" \
                 :: "r"((uint32_t)(smem_addr)), "r"((uint32_t)(n)) : "memory")
#define TC_RELINQ() \
    asm volatile("tcgen05.relinquish_alloc_permit.cta_group::1.sync.aligned;")
#define TC_DEALLOC(tmem, n) \
    asm volatile("tcgen05.dealloc.cta_group::1.sync.aligned.b32 %0, %1;" \
                 :: "r"(tmem), "r"((uint32_t)(n)))
#define TC_COMMIT(mbar) \
    asm volatile("tcgen05.commit.cta_group::1.mbarrier::arrive::one.shared::cluster.b64 [%0];" \
                 :: "r"((uint32_t)(mbar)) : "memory")
#define TC_FENCE_AFTER()  asm volatile("tcgen05.fence::after_thread_sync;" ::: "memory")
#define TC_WAIT_LD()      asm volatile("tcgen05.wait::ld.sync.aligned;" ::: "memory")

#define LDTM_X32(r, addr) \
    asm volatile( \
        "tcgen05.ld.sync.aligned.32x32b.x32.b32 " \
        "{%0, %1, %2, %3, %4, %5, %6, %7, " \
        " %8, %9, %10, %11, %12, %13, %14, %15, " \
        " %16, %17, %18, %19, %20, %21, %22, %23, " \
        " %24, %25, %26, %27, %28, %29, %30, %31}, [%32];" \
        : "=r"((r)[0]),  "=r"((r)[1]),  "=r"((r)[2]),  "=r"((r)[3]), \
          "=r"((r)[4]),  "=r"((r)[5]),  "=r"((r)[6]),  "=r"((r)[7]), \
          "=r"((r)[8]),  "=r"((r)[9]),  "=r"((r)[10]), "=r"((r)[11]), \
          "=r"((r)[12]), "=r"((r)[13]), "=r"((r)[14]), "=r"((r)[15]), \
          "=r"((r)[16]), "=r"((r)[17]), "=r"((r)[18]), "=r"((r)[19]), \
          "=r"((r)[20]), "=r"((r)[21]), "=r"((r)[22]), "=r"((r)[23]), \
          "=r"((r)[24]), "=r"((r)[25]), "=r"((r)[26]), "=r"((r)[27]), \
          "=r"((r)[28]), "=r"((r)[29]), "=r"((r)[30]), "=r"((r)[31]) \
        : "r"(addr))

__device__ __forceinline__ void mma_tf32_ss(uint32_t d_tmem, u64 a_desc, u64 b_desc,
                                            uint32_t idesc, uint32_t enable) {
    asm volatile(
        "{\n\t"
        ".reg .pred p;\n\t"
        "setp.ne.u32 p, %4, 0;\n\t"
        "tcgen05.mma.cta_group::1.kind::tf32 [%0], %1, %2, %3, {%5, %5, %5, %5}, p;\n\t"
        "}"
        :: "r"(d_tmem), "l"(a_desc), "l"(b_desc), "r"(idesc), "r"(enable), "r"(0u)
        : "memory");
}
#endif  // HAS_TCGEN05

#define MBAR_INIT(mbar, cnt) \
    asm volatile("mbarrier.init.shared.b64 [%0], %1;" \
                 :: "r"((uint32_t)(mbar)), "r"((uint32_t)(cnt)) : "memory")

#define MBAR_WAIT(mbar, parity) do {                                           \
    uint32_t _m = (uint32_t)(mbar), _p = (uint32_t)(parity), _d;               \
    asm volatile("{ .reg .pred p;"                                             \
        " mbarrier.try_wait.parity.acquire.cta.shared::cta.b64 p, [%1], %2;"   \
        " selp.b32 %0, 1, 0, p; }" : "=r"(_d) : "r"(_m), "r"(_p) : "memory");  \
    while (!_d) {                                                              \
        asm volatile("{ .reg .pred p;"                                         \
            " mbarrier.try_wait.parity.acquire.cta.shared::cta.b64 p, [%1], %2, 0x989680;" \
            " selp.b32 %0, 1, 0, p; }" : "=r"(_d) : "r"(_m), "r"(_p) : "memory"); \
    }                                                                          \
} while (0)

// SMEM descriptor: SW128, version=1, SBO=64, LBO=1 (matches examples)
constexpr u64 DESC_BASE = (2ull << 61) | (1ull << 46) | (64ull << 32) | (1ull << 16);
__device__ __forceinline__ u64 mk_desc(uint32_t addr) {
    return DESC_BASE | ((u64)(addr >> 4) & 0x3FFF);
}

// Blocked-atom + SW128 byte offset. atom = 8 rows x 32 tf32 (128B).
__device__ __forceinline__ uint32_t tile_off(int row, int k, int atom_rows) {
    uint32_t o = ((uint32_t)((k >> 5) * atom_rows + (row >> 3)) << 10)
               + ((uint32_t)(row & 7) << 7) + ((uint32_t)(k & 31) << 2);
    return o ^ ((o >> 3) & 0x70);
}

__device__ __forceinline__ float to_tf32(float x) {
    float r;
    asm("cvt.rna.tf32.f32 %0, %1;" : "=f"(r) : "f"(x));
    return r;
}

__device__ __forceinline__ void split_sts(char* smem, uint32_t off_hi, uint32_t lo_delta,
                                          float4 v) {
    float4 hv, lv;
    hv.x = to_tf32(v.x); hv.y = to_tf32(v.y); hv.z = to_tf32(v.z); hv.w = to_tf32(v.w);
    lv.x = v.x - hv.x;   lv.y = v.y - hv.y;   lv.z = v.z - hv.z;   lv.w = v.w - hv.w;
    *reinterpret_cast<float4*>(smem + off_hi)            = hv;
    *reinterpret_cast<float4*>(smem + off_hi + lo_delta) = lv;
}

__device__ __forceinline__ float gelu_f(float x) {
    float x3 = x * x * x;
    return 0.5f * x * (1.0f + tanhf(0.7978845608028654f * (x + 0.044715f * x3)));
}

// idesc (both GEMMs now M=128, N=64): dtype=F32(1)@4, atype=TF32(2)@7,
// btype=TF32(2)@10, N>>3=8@17, M>>4=8@24
constexpr uint32_t ID_TC = (1u << 4) | (2u << 7) | (2u << 10) | (8u << 17) | (8u << 24);

// ---------------------------------------------------------------------------
// Kernel 1: connection-weighted aggregation (unchanged, proven).
// ---------------------------------------------------------------------------
__global__ __launch_bounds__(256) void agg_kernel(
    const float* __restrict__ h,
    const float* __restrict__ w_conn,
    const int*   __restrict__ conn)
{
    extern __shared__ float smf[];
    float4* h_sm = reinterpret_cast<float4*>(smf);

    int bn = blockIdx.x;
    int n  = bn & (NC - 1);

    const float4* hg = reinterpret_cast<const float4*>(h) + (size_t)bn * CN * DN / 4;
    for (int i = threadIdx.x; i < CN * DN / 4; i += 256) h_sm[i] = hg[i];
    __syncthreads();

    int dq = threadIdx.x & 3;
    int cr = threadIdx.x >> 2;

    for (int cp = 0; cp < 4; cp++) {
        int c = cp * 64 + cr;
        float4 a0 = {0,0,0,0}, a1 = {0,0,0,0}, a2 = {0,0,0,0}, a3 = {0,0,0,0};
        const int*   ci = conn   + ((size_t)n  * CN + c) * K;
        const float* wc = w_conn + ((size_t)bn * CN + c) * K;
        #pragma unroll
        for (int k = 0; k < K; k++) {
            int   idx = ci[k];
            float w   = wc[k];
            const float4* row = h_sm + idx * (DN / 4) + dq * 4;
            float4 r0 = row[0], r1 = row[1], r2 = row[2], r3 = row[3];
            a0.x += w * r0.x; a0.y += w * r0.y; a0.z += w * r0.z; a0.w += w * r0.w;
            a1.x += w * r1.x; a1.y += w * r1.y; a1.z += w * r1.z; a1.w += w * r1.w;
            a2.x += w * r2.x; a2.y += w * r2.y; a2.z += w * r2.z; a2.w += w * r2.w;
            a3.x += w * r3.x; a3.y += w * r3.y; a3.z += w * r3.z; a3.w += w * r3.w;
        }
        float4* out = reinterpret_cast<float4*>(g_agg + ((size_t)bn * CN + c) * DN) + dq * 4;
        out[0] = a0; out[1] = a1; out[2] = a2; out[3] = a3;
    }
}

// ---------------------------------------------------------------------------
// Fused grouped-MLP via tcgen05 TF32 (3-pass hi/lo). All MMAs are M=128,N=64.
// GEMM1: A=W1[128xK], B=feat c-chunks -> D1[j][c] cols 0..255.
// GEMM2: A=hidden[c-half 128 x 128], B=W2[64x128] -> D2[c][j2] cols 256+ch*64.
// MODE 0: feat=[h|agg|nid],  out=msg.  MODE 1: feat=[h|msg|ctx], out=h+res.
// ---------------------------------------------------------------------------
template<int MODE>
__global__ __launch_bounds__(512, 1)
void mlp_tc_kernel(
    const float* __restrict__ h,
    const float* __restrict__ s1,
    const float* __restrict__ s2,
    const float* __restrict__ w1,     // [G][HM][F]
    const float* __restrict__ b1,     // [G][HM]
    const float* __restrict__ w2,     // [G][DN][HM]
    const float* __restrict__ b2,     // [G][DN]
    const int*   __restrict__ c2g,
    float*       __restrict__ out)
{
    extern __shared__ char smem[];
    uint32_t sbase = smem_u32(smem);

    int tid  = threadIdx.x;
    int wid  = tid >> 5;
    int lane = tid & 31;
    int bn   = blockIdx.x;
    int n    = bn & (NC - 1);
    int g    = c2g[n];

    const float* w1g    = w1 + (size_t)g * HM * F;
    const float* w2g    = w2 + (size_t)g * DN * HM;
    const float* base_h = h + (size_t)bn * CN * DN;
    const float* base1  = (MODE == 0) ? (g_agg + (size_t)bn * CN * DN)
                                      : (s1    + (size_t)bn * CN * DN);
    const float* base2  = (MODE == 0) ? (s2 + (size_t)n * CN * DN)
                                      : (s2 + (size_t)bn * DN);

#if HAS_TCGEN05
    if (wid == 0) {
        TC_ALLOC(sbase + OFF_TMEM, 512);
        TC_RELINQ();
    }
    if (tid == 0) MBAR_INIT(sbase + OFF_MBAR, 1);
    if (tid < HM) ((float*)(smem + OFF_B1S))[tid] = b1[g * HM + tid];
    if (tid < DN) ((float*)(smem + OFF_B2S))[tid] = b2[g * DN + tid];
    __syncthreads();

    uint32_t tmem;
    asm("ld.shared.b32 %0, [%1];" : "=r"(tmem) : "r"(sbase + OFF_TMEM));

    uint32_t ph = 0;

    // ============ GEMM1: D1[j=128][c=256], 3 K-tiles of 64 ============
    for (int t = 0; t < 3; t++) {
        // stage A = W1 chunk [128 rows x 64 k]
        #pragma unroll
        for (int p = 0; p < 4; p++) {
            int i = p * 512 + tid;
            int r = i >> 4, k4 = i & 15;
            float4 v = *reinterpret_cast<const float4*>(w1g + (size_t)r * F + t * 64 + k4 * 4);
            split_sts(smem, OFF_AH + tile_off(r, k4 * 4, 16), 32768, v);
        }
        // stage B = feat chunk [256 rows x 64 k]
        #pragma unroll
        for (int p = 0; p < 8; p++) {
            int i = p * 512 + tid;
            int r = i >> 4, k4 = i & 15;
            float4 v;
            if (t == 0)       v = *reinterpret_cast<const float4*>(base_h + (size_t)r * DN + k4 * 4);
            else if (t == 1)  v = *reinterpret_cast<const float4*>(base1  + (size_t)r * DN + k4 * 4);
            else {
                if (MODE == 0) v = *reinterpret_cast<const float4*>(base2 + (size_t)r * DN + k4 * 4);
                else           v = *reinterpret_cast<const float4*>(base2 + k4 * 4);  // ctx bcast
            }
            split_sts(smem, OFF_BH + tile_off(r, k4 * 4, 32), 65536, v);
        }
        asm volatile("fence.proxy.async.shared::cta;" ::: "memory");
        __syncthreads();

        if (wid == 0) {
            u64 dah = mk_desc(sbase + OFF_AH), dal = mk_desc(sbase + OFF_AL);
            u64 dbh = mk_desc(sbase + OFF_BH), dbl = mk_desc(sbase + OFF_BL);
            if (elect1()) {
                #pragma unroll
                for (int pass = 0; pass < 3; pass++) {
                    u64 da = (pass == 2) ? dal : dah;
                    u64 db = (pass == 1) ? dbl : dbh;
                    #pragma unroll
                    for (int q = 0; q < 4; q++) {          // N=64 c-chunk
                        #pragma unroll
                        for (int s = 0; s < 8; s++) {      // K=8 steps
                            u64 oa = (u64)((s >> 2) * 1024 + (s & 3) * 2);
                            u64 ob = (u64)((s >> 2) * 2048 + (s & 3) * 2 + q * 512);
                            mma_tf32_ss(tmem + q * 64, da + oa, db + ob, ID_TC,
                                        (t | pass | s) ? 1u : 0u);
                        }
                    }
                }
                TC_COMMIT(sbase + OFF_MBAR);
            }
        }
        MBAR_WAIT(sbase + OFF_MBAR, ph); ph ^= 1;
        TC_FENCE_AFTER();
    }

    // ============ GEMM2: D2[c][j2], 2 c-half phases ============
    int sub  = wid & 3;                 // TMEM subpartition (lane group)
    int cgrp = wid >> 2;                // column-chunk selector
    float bj1 = ((float*)(smem + OFF_B1S))[sub * 32 + lane];

    // stage B = W2 [64 rows x 128 k] once (A-buffers free after GEMM1 wait)
    #pragma unroll
    for (int p = 0; p < 4; p++) {
        int i = p * 512 + tid;
        int r = i >> 5, k4 = i & 31;
        float4 v = *reinterpret_cast<const float4*>(w2g + (size_t)r * HM + k4 * 4);
        split_sts(smem, OFF_AH + tile_off(r, k4 * 4, 8), 32768, v);
    }

    for (int ch = 0; ch < 2; ch++) {
        // GEMM1 epilogue for c-half ch: gelu(D1[j][c]+b1) -> A2[c_local][k=j] hi/lo
        {
            uint32_t r[32];
            LDTM_X32(r, tmem + ch * 128 + cgrp * 32);   // cols = c, lanes = j
            TC_WAIT_LD();
            int j = sub * 32 + lane;
            #pragma unroll
            for (int i2 = 0; i2 < 32; i2++) {
                float v = __uint_as_float(r[i2]) + bj1;
                v = gelu_f(v);
                float hv = to_tf32(v), lv = v - hv;
                uint32_t off = tile_off(cgrp * 32 + i2, j, 16);
                *reinterpret_cast<float*>(smem + OFF_BH + off) = hv;
                *reinterpret_cast<float*>(smem + OFF_BL + off) = lv;
            }
        }
        asm volatile("fence.proxy.async.shared::cta;" ::: "memory");
        __syncthreads();

        if (wid == 0) {
            u64 dah = mk_desc(sbase + OFF_BH), dal = mk_desc(sbase + OFF_BL);  // A = hidden
            u64 dbh = mk_desc(sbase + OFF_AH), dbl = mk_desc(sbase + OFF_AL);  // B = W2
            if (elect1()) {
                #pragma unroll
                for (int pass = 0; pass < 3; pass++) {
                    u64 da = (pass == 2) ? dal : dah;
                    u64 db = (pass == 1) ? dbl : dbh;
                    #pragma unroll
                    for (int s = 0; s < 16; s++) {       // K=128 -> 16 steps
                        u64 oa = (u64)((s >> 2) * 1024 + (s & 3) * 2);
                        u64 ob = (u64)((s >> 2) * 512  + (s & 3) * 2);
                        mma_tf32_ss(tmem + 256 + ch * 64, da + oa, db + ob, ID_TC,
                                    (pass | s) ? 1u : 0u);
                    }
                }
                TC_COMMIT(sbase + OFF_MBAR);
            }
        }
        MBAR_WAIT(sbase + OFF_MBAR, ph); ph ^= 1;
        TC_FENCE_AFTER();
    }

    // ============ final epilogue: D2[c][j2] -> out ============
    {
        int ch  = cgrp >> 1;
        int jh2 = cgrp & 1;
        uint32_t r[32];
        LDTM_X32(r, tmem + 256 + ch * 64 + jh2 * 32);   // lanes = c_local, regs = j2
        TC_WAIT_LD();
        int c  = ch * 128 + sub * 32 + lane;
        int jb = jh2 * 32;
        const float* b2s = (float*)(smem + OFF_B2S);
        float* op = out + ((size_t)bn * CN + c) * DN + jb;
        const float* hp = base_h + (size_t)c * DN + jb;
        #pragma unroll
        for (int i4 = 0; i4 < 8; i4++) {
            float4 v;
            v.x = __uint_as_float(r[i4 * 4 + 0]) + b2s[jb + i4 * 4 + 0];
            v.y = __uint_as_float(r[i4 * 4 + 1]) + b2s[jb + i4 * 4 + 1];
            v.z = __uint_as_float(r[i4 * 4 + 2]) + b2s[jb + i4 * 4 + 2];
            v.w = __uint_as_float(r[i4 * 4 + 3]) + b2s[jb + i4 * 4 + 3];
            if (MODE == 1) {
                float4 hv = *reinterpret_cast<const float4*>(hp + i4 * 4);
                v.x += hv.x; v.y += hv.y; v.z += hv.z; v.w += hv.w;
            }
            *reinterpret_cast<float4*>(op + i4 * 4) = v;
        }
    }

    __syncthreads();
    if (wid == 0) TC_DEALLOC(tmem, 512);

#else  // ---------------- SIMT fallback (plain compute_103 pass only) -------
    float* Hs  = (float*)(smem + OFF_AH);
    float* B1s = (float*)(smem + OFF_B1S);
    float* B2s = (float*)(smem + OFF_B2S);
    if (tid < HM) B1s[tid] = b1[g * HM + tid];
    if (tid < DN) B2s[tid] = b2[g * DN + tid];
    __syncthreads();

    for (int idx = tid; idx < CN * HM; idx += 512) {
        int c = idx >> 7, j = idx & 127;
        float acc = B1s[j];
        const float* wr = w1g + (size_t)j * F;
        for (int f = 0; f < DN; f++)  acc = fmaf(wr[f],       base_h[(size_t)c * DN + f], acc);
        for (int f = 0; f < DN; f++)  acc = fmaf(wr[64 + f],  base1 [(size_t)c * DN + f], acc);
        for (int f = 0; f < DN; f++) {
            float fv = (MODE == 0) ? base2[(size_t)c * DN + f] : base2[f];
            acc = fmaf(wr[128 + f], fv, acc);
        }
        Hs[idx] = gelu_f(acc);
    }
    __syncthreads();

    for (int idx = tid; idx < CN * DN; idx += 512) {
        int c = idx >> 6, j2 = idx & 63;
        float acc = B2s[j2];
        const float* wr = w2g + (size_t)j2 * HM;
        const float* hr = Hs + (size_t)c * HM;
        for (int k = 0; k < HM; k++) acc = fmaf(wr[k], hr[k], acc);
        if (MODE == 1) acc += base_h[(size_t)c * DN + j2];
        out[((size_t)bn * CN + c) * DN + j2] = acc;
    }
#endif
}

// ---------------------------------------------------------------------------
// Modulation MLP (unchanged, proven).
// ---------------------------------------------------------------------------
__global__ __launch_bounds__(256) void mod_kernel(
    const float* __restrict__ hnew,
    const float* __restrict__ msg,
    const float* __restrict__ mw1,
    const float* __restrict__ mb1,
    const float* __restrict__ mw2,
    const float* __restrict__ mb2,
    float*       __restrict__ mod)
{
    __shared__ float part[8][DN];
    __shared__ float pooled[2 * DN];
    __shared__ float phh[HMOD];

    int bn  = blockIdx.x;
    int n   = bn & (NC - 1);
    int tid = threadIdx.x;

    int d  = tid & 63;
    int cg = tid >> 6;
    {
        const float* p1 = hnew + (size_t)bn * CN * DN + (size_t)cg * 64 * DN + d;
        const float* p2 = msg  + (size_t)bn * CN * DN + (size_t)cg * 64 * DN + d;
        float s1 = 0.0f, s2 = 0.0f;
        #pragma unroll 8
        for (int i = 0; i < 64; i++) {
            s1 += p1[(size_t)i * DN];
            s2 += p2[(size_t)i * DN];
        }
        part[cg][d]     = s1;
        part[4 + cg][d] = s2;
    }
    __syncthreads();

    if (tid < 2 * DN) {
        int base = (tid < DN) ? 0 : 4;
        int dd   = tid & 63;
        pooled[tid] = (part[base][dd] + part[base + 1][dd] +
                       part[base + 2][dd] + part[base + 3][dd]) * (1.0f / CN);
    }
    __syncthreads();

    if (tid < HMOD) {
        const float* w = mw1 + (size_t)n * (2 * DN) * HMOD + tid;
        float acc = mb1[n * HMOD + tid];
        #pragma unroll 8
        for (int f = 0; f < 2 * DN; f++) acc = fmaf(pooled[f], w[f * HMOD], acc);
        phh[tid] = gelu_f(acc);
    }
    __syncthreads();

    if (tid < MOD_OUT) {
        const float* w = mw2 + (size_t)n * HMOD * MOD_OUT + tid;
        float acc = mb2[n * MOD_OUT + tid];
        #pragma unroll 8
        for (int k = 0; k < HMOD; k++) acc = fmaf(phh[k], w[k * MOD_OUT], acc);
        mod[bn * MOD_OUT + tid] = acc;
    }
}

// ---------------------------------------------------------------------------
// Launch
// ---------------------------------------------------------------------------
extern "C" void kernel_launch(void* const* d_in, const int* in_sizes, int n_in,
                              void* d_out, int out_size)
{
    const float* h      = (const float*)d_in[0];
    const float* w_conn = (const float*)d_in[1];
    const float* ctx    = (const float*)d_in[2];
    const float* nid    = (const float*)d_in[3];
    const float* mw1    = (const float*)d_in[4];
    const float* mb1    = (const float*)d_in[5];
    const float* mw2    = (const float*)d_in[6];
    const float* mb2    = (const float*)d_in[7];
    const float* sw1    = (const float*)d_in[8];
    const float* sb1    = (const float*)d_in[9];
    const float* sw2    = (const float*)d_in[10];
    const float* sb2    = (const float*)d_in[11];
    const float* modw1  = (const float*)d_in[12];
    const float* modb1  = (const float*)d_in[13];
    const float* modw2  = (const float*)d_in[14];
    const float* modb2  = (const float*)d_in[15];
    const int*   conn   = (const int*)d_in[16];
    const int*   c2g    = (const int*)d_in[17];

    float* out   = (float*)d_out;
    float* o_h   = out;
    float* o_msg = out + (size_t)Bb * NC * CN * DN;
    float* o_mod = o_msg + (size_t)Bb * NC * CN * DN;

    const int grid = Bb * NC;  // 512
    const size_t smA = (size_t)CN * DN * sizeof(float);   // 64 KB

    static bool attr_done = false;
    if (!attr_done) {
        cudaFuncSetAttribute(agg_kernel, cudaFuncAttributeMaxDynamicSharedMemorySize, (int)smA);
        cudaFuncSetAttribute(mlp_tc_kernel<0>, cudaFuncAttributeMaxDynamicSharedMemorySize, SMEM_MLP);
        cudaFuncSetAttribute(mlp_tc_kernel<1>, cudaFuncAttributeMaxDynamicSharedMemorySize, SMEM_MLP);
        attr_done = true;
    }

    agg_kernel<<<grid, 256, smA>>>(h, w_conn, conn);
    mlp_tc_kernel<0><<<grid, 512, SMEM_MLP>>>(h, nullptr, nid, mw1, mb1, mw2, mb2, c2g, o_msg);
    mlp_tc_kernel<1><<<grid, 512, SMEM_MLP>>>(h, o_msg, ctx, sw1, sb1, sw2, sb2, c2g, o_h);
    mod_kernel<<<grid, 256>>>(o_h, o_msg, modw1, modb1, modw2, modb2, o_mod);
}

// round 7
// speedup vs baseline: 2.3758x; 1.0973x over previous
#include <cuda_runtime.h>
#include <cstdint>

typedef unsigned long long u64;

// Problem constants
constexpr int Bb  = 2;
constexpr int NC  = 256;
constexpr int CN  = 256;
constexpr int K   = 16;
constexpr int DN  = 64;
constexpr int HM  = 128;
constexpr int F   = 192;
constexpr int HMOD = 64;
constexpr int MOD_OUT = 5;

// Scratch
__device__ float g_agg[(size_t)Bb * NC * CN * DN];

// ---------------- SMEM layout (bytes) --------------------------------------
constexpr int OFF_TMEM  = 0;
constexpr int OFF_MBARA = 8;
constexpr int OFF_MBARB = 16;
constexpr int OFF_MBARC = 24;
constexpr int OFF_B1S   = 32;              // 128 floats
constexpr int OFF_B2S   = 544;             // 64 floats
constexpr int OFF_AH    = 1024;            // 32KB: W1-chunk [128x64] / W2 [64x128]
constexpr int OFF_AL    = 1024 + 32768;    // 32KB
constexpr int OFF_BH    = 1024 + 65536;    // 64KB: feat [256x64] / hidden [128x128]
constexpr int OFF_BL    = 1024 + 131072;   // 64KB
constexpr int SMEM_MLP  = 1024 + 196608;   // 197632 B

// tcgen05 only exists in arch-specific targets; the harness's extra plain
// compute_103 pass takes the SIMT fallback branch.
#if defined(__CUDA_ARCH_FEAT_SM103_ALL) || defined(__CUDA_ARCH_FEAT_SM100_ALL) || defined(__CUDA_ARCH_FEAT_SM101_ALL)
#define HAS_TCGEN05 1
#else
#define HAS_TCGEN05 0
#endif

__device__ __forceinline__ uint32_t smem_u32(const void* p) {
    uint32_t a;
    asm("{ .reg .u64 t; cvta.to.shared.u64 t, %1; cvt.u32.u64 %0, t; }"
        : "=r"(a) : "l"(p));
    return a;
}

#if HAS_TCGEN05
__device__ __forceinline__ uint32_t elect1() {
    uint32_t p;
    asm volatile("{ .reg .pred p; elect.sync _|p, 0xFFFFFFFF; selp.b32 %0, 1, 0, p; }"
                 : "=r"(p));
    return p;
}

#define TC_ALLOC(smem_addr, n) \
    asm volatile("tcgen05.alloc.cta_group::1.sync.aligned.shared::cta.b32 [%0], %1;" \
                 :: "r"((uint32_t)(smem_addr)), "r"((uint32_t)(n)) : "memory")
#define TC_RELINQ() \
    asm volatile("tcgen05.relinquish_alloc_permit.cta_group::1.sync.aligned;")
#define TC_DEALLOC(tmem, n) \
    asm volatile("tcgen05.dealloc.cta_group::1.sync.aligned.b32 %0, %1;" \
                 :: "r"(tmem), "r"((uint32_t)(n)))
#define TC_COMMIT(mbar) \
    asm volatile("tcgen05.commit.cta_group::1.mbarrier::arrive::one.shared::cluster.b64 [%0];" \
                 :: "r"((uint32_t)(mbar)) : "memory")
#define TC_FENCE_AFTER()  asm volatile("tcgen05.fence::after_thread_sync;" ::: "memory")
#define TC_WAIT_LD()      asm volatile("tcgen05.wait::ld.sync.aligned;" ::: "memory")

#define LDTM_X32(r, addr) \
    asm volatile( \
        "tcgen05.ld.sync.aligned.32x32b.x32.b32 " \
        "{%0, %1, %2, %3, %4, %5, %6, %7, " \
        " %8, %9, %10, %11, %12, %13, %14, %15, " \
        " %16, %17, %18, %19, %20, %21, %22, %23, " \
        " %24, %25, %26, %27, %28, %29, %30, %31}, [%32];" \
        : "=r"((r)[0]),  "=r"((r)[1]),  "=r"((r)[2]),  "=r"((r)[3]), \
          "=r"((r)[4]),  "=r"((r)[5]),  "=r"((r)[6]),  "=r"((r)[7]), \
          "=r"((r)[8]),  "=r"((r)[9]),  "=r"((r)[10]), "=r"((r)[11]), \
          "=r"((r)[12]), "=r"((r)[13]), "=r"((r)[14]), "=r"((r)[15]), \
          "=r"((r)[16]), "=r"((r)[17]), "=r"((r)[18]), "=r"((r)[19]), \
          "=r"((r)[20]), "=r"((r)[21]), "=r"((r)[22]), "=r"((r)[23]), \
          "=r"((r)[24]), "=r"((r)[25]), "=r"((r)[26]), "=r"((r)[27]), \
          "=r"((r)[28]), "=r"((r)[29]), "=r"((r)[30]), "=r"((r)[31]) \
        : "r"(addr))

__device__ __forceinline__ void mma_tf32_ss(uint32_t d_tmem, u64 a_desc, u64 b_desc,
                                            uint32_t idesc, uint32_t enable) {
    asm volatile(
        "{\n\t"
        ".reg .pred p;\n\t"
        "setp.ne.u32 p, %4, 0;\n\t"
        "tcgen05.mma.cta_group::1.kind::tf32 [%0], %1, %2, %3, {%5, %5, %5, %5}, p;\n\t"
        "}"
        :: "r"(d_tmem), "l"(a_desc), "l"(b_desc), "r"(idesc), "r"(enable), "r"(0u)
        : "memory");
}
#endif  // HAS_TCGEN05

#define MBAR_INIT(mbar, cnt) \
    asm volatile("mbarrier.init.shared.b64 [%0], %1;" \
                 :: "r"((uint32_t)(mbar)), "r"((uint32_t)(cnt)) : "memory")

#define MBAR_WAIT(mbar, parity) do {                                           \
    uint32_t _m = (uint32_t)(mbar), _p = (uint32_t)(parity), _d;               \
    asm volatile("{ .reg .pred p;"                                             \
        " mbarrier.try_wait.parity.acquire.cta.shared::cta.b64 p, [%1], %2;"   \
        " selp.b32 %0, 1, 0, p; }" : "=r"(_d) : "r"(_m), "r"(_p) : "memory");  \
    while (!_d) {                                                              \
        asm volatile("{ .reg .pred p;"                                         \
            " mbarrier.try_wait.parity.acquire.cta.shared::cta.b64 p, [%1], %2, 0x989680;" \
            " selp.b32 %0, 1, 0, p; }" : "=r"(_d) : "r"(_m), "r"(_p) : "memory"); \
    }                                                                          \
} while (0)

// SMEM descriptor: SW128, version=1, SBO=64, LBO=1
constexpr u64 DESC_BASE = (2ull << 61) | (1ull << 46) | (64ull << 32) | (1ull << 16);
__device__ __forceinline__ u64 mk_desc(uint32_t addr) {
    return DESC_BASE | ((u64)(addr >> 4) & 0x3FFF);
}

// Blocked-atom + SW128 byte offset. atom = 8 rows x 32 tf32 (128B).
__device__ __forceinline__ uint32_t tile_off(int row, int k, int atom_rows) {
    uint32_t o = ((uint32_t)((k >> 5) * atom_rows + (row >> 3)) << 10)
               + ((uint32_t)(row & 7) << 7) + ((uint32_t)(k & 31) << 2);
    return o ^ ((o >> 3) & 0x70);
}

__device__ __forceinline__ float to_tf32(float x) {
    float r;
    asm("cvt.rna.tf32.f32 %0, %1;" : "=f"(r) : "f"(x));
    return r;
}

__device__ __forceinline__ void split_sts(char* smem, uint32_t off_hi, uint32_t lo_delta,
                                          float4 v) {
    float4 hv, lv;
    hv.x = to_tf32(v.x); hv.y = to_tf32(v.y); hv.z = to_tf32(v.z); hv.w = to_tf32(v.w);
    lv.x = v.x - hv.x;   lv.y = v.y - hv.y;   lv.z = v.z - hv.z;   lv.w = v.w - hv.w;
    *reinterpret_cast<float4*>(smem + off_hi)            = hv;
    *reinterpret_cast<float4*>(smem + off_hi + lo_delta) = lv;
}

// exact-ish tanh gelu (reference)
__device__ __forceinline__ float gelu_f(float x) {
    float x3 = x * x * x;
    return 0.5f * x * (1.0f + tanhf(0.7978845608028654f * (x + 0.044715f * x3)));
}

// fast gelu: 0.5x(1+tanh(z)) = x - x/(e^{2z}+1), e^{2z} via ex2.approx
__device__ __forceinline__ float gelu_fast(float x) {
    float z = x + 0.044715f * x * x * x;
    float a = 2.3022081852f * z;              // 2*0.7978845608*log2(e)
    float e;
    asm("ex2.approx.f32 %0, %1;" : "=f"(e) : "f"(a));
    float r;
    asm("rcp.approx.f32 %0, %1;" : "=f"(r) : "f"(e + 1.0f));
    return x - x * r;
}

// idesc (all MMAs M=128, N=64): dtype=F32@4, atype=TF32@7, btype=TF32@10,
// N>>3=8@17, M>>4=8@24
constexpr uint32_t ID_TC = (1u << 4) | (2u << 7) | (2u << 10) | (8u << 17) | (8u << 24);

// ---------------------------------------------------------------------------
// Kernel 1: connection-weighted aggregation (unchanged, proven).
// ---------------------------------------------------------------------------
__global__ __launch_bounds__(256) void agg_kernel(
    const float* __restrict__ h,
    const float* __restrict__ w_conn,
    const int*   __restrict__ conn)
{
    extern __shared__ float smf[];
    float4* h_sm = reinterpret_cast<float4*>(smf);

    int bn = blockIdx.x;
    int n  = bn & (NC - 1);

    const float4* hg = reinterpret_cast<const float4*>(h) + (size_t)bn * CN * DN / 4;
    for (int i = threadIdx.x; i < CN * DN / 4; i += 256) h_sm[i] = hg[i];
    __syncthreads();

    int dq = threadIdx.x & 3;
    int cr = threadIdx.x >> 2;

    for (int cp = 0; cp < 4; cp++) {
        int c = cp * 64 + cr;
        float4 a0 = {0,0,0,0}, a1 = {0,0,0,0}, a2 = {0,0,0,0}, a3 = {0,0,0,0};
        const int*   ci = conn   + ((size_t)n  * CN + c) * K;
        const float* wc = w_conn + ((size_t)bn * CN + c) * K;
        #pragma unroll
        for (int k = 0; k < K; k++) {
            int   idx = ci[k];
            float w   = wc[k];
            const float4* row = h_sm + idx * (DN / 4) + dq * 4;
            float4 r0 = row[0], r1 = row[1], r2 = row[2], r3 = row[3];
            a0.x += w * r0.x; a0.y += w * r0.y; a0.z += w * r0.z; a0.w += w * r0.w;
            a1.x += w * r1.x; a1.y += w * r1.y; a1.z += w * r1.z; a1.w += w * r1.w;
            a2.x += w * r2.x; a2.y += w * r2.y; a2.z += w * r2.z; a2.w += w * r2.w;
            a3.x += w * r3.x; a3.y += w * r3.y; a3.z += w * r3.z; a3.w += w * r3.w;
        }
        float4* out = reinterpret_cast<float4*>(g_agg + ((size_t)bn * CN + c) * DN) + dq * 4;
        out[0] = a0; out[1] = a1; out[2] = a2; out[3] = a3;
    }
}

// ---------------------------------------------------------------------------
// Fused grouped-MLP via tcgen05 TF32 (3-pass hi/lo), software-pipelined.
// ---------------------------------------------------------------------------
template<int MODE>
__global__ __launch_bounds__(512, 1)
void mlp_tc_kernel(
    const float* __restrict__ h,
    const float* __restrict__ s1,
    const float* __restrict__ s2,
    const float* __restrict__ w1,     // [G][HM][F]
    const float* __restrict__ b1,     // [G][HM]
    const float* __restrict__ w2,     // [G][DN][HM]
    const float* __restrict__ b2,     // [G][DN]
    const int*   __restrict__ c2g,
    float*       __restrict__ out)
{
    extern __shared__ char smem[];
    uint32_t sbase = smem_u32(smem);

    int tid  = threadIdx.x;
    int wid  = tid >> 5;
    int lane = tid & 31;
    int bn   = blockIdx.x;
    int n    = bn & (NC - 1);
    int g    = c2g[n];

    const float* w1g    = w1 + (size_t)g * HM * F;
    const float* w2g    = w2 + (size_t)g * DN * HM;
    const float* base_h = h + (size_t)bn * CN * DN;
    const float* base1  = (MODE == 0) ? (g_agg + (size_t)bn * CN * DN)
                                      : (s1    + (size_t)bn * CN * DN);
    const float* base2  = (MODE == 0) ? (s2 + (size_t)n * CN * DN)
                                      : (s2 + (size_t)bn * DN);

#if HAS_TCGEN05
    if (wid == 0) {
        TC_ALLOC(sbase + OFF_TMEM, 512);
        TC_RELINQ();
    }
    if (tid == 0) {
        MBAR_INIT(sbase + OFF_MBARA, 1);
        MBAR_INIT(sbase + OFF_MBARB, 1);
        MBAR_INIT(sbase + OFF_MBARC, 1);
    }
    if (tid < HM) ((float*)(smem + OFF_B1S))[tid] = b1[g * HM + tid];
    if (tid < DN) ((float*)(smem + OFF_B2S))[tid] = b2[g * DN + tid];
    __syncthreads();

    uint32_t tmem;
    asm("ld.shared.b32 %0, [%1];" : "=r"(tmem) : "r"(sbase + OFF_TMEM));

    // staging index decomposition (fixed per thread)
    const int rA = tid >> 4, kA = tid & 15;     // A chunks: 128 rows x 16 k4
    uint32_t ph = 0;

    float4 va[4], vb[8];
    // ---- prefetch tile 0 ----
    #pragma unroll
    for (int p = 0; p < 4; p++) {
        int i = p * 512 + tid; int r = i >> 4, k4 = i & 15;
        va[p] = *reinterpret_cast<const float4*>(w1g + (size_t)r * F + k4 * 4);
    }
    #pragma unroll
    for (int p = 0; p < 8; p++) {
        int i = p * 512 + tid; int r = i >> 4, k4 = i & 15;
        vb[p] = *reinterpret_cast<const float4*>(base_h + (size_t)r * DN + k4 * 4);
    }

    // ============ GEMM1: D1[j=128][c=256], 3 K-tiles of 64, pipelined ========
    float4 vw[4];   // W2 prefetch
    for (int t = 0; t < 3; t++) {
        if (t > 0) { MBAR_WAIT(sbase + OFF_MBARA, ph); ph ^= 1; TC_FENCE_AFTER(); }
        // STS current tile
        #pragma unroll
        for (int p = 0; p < 4; p++) {
            int i = p * 512 + tid; int r = i >> 4, k4 = i & 15;
            split_sts(smem, OFF_AH + tile_off(r, k4 * 4, 16), 32768, va[p]);
        }
        #pragma unroll
        for (int p = 0; p < 8; p++) {
            int i = p * 512 + tid; int r = i >> 4, k4 = i & 15;
            split_sts(smem, OFF_BH + tile_off(r, k4 * 4, 32), 65536, vb[p]);
        }
        asm volatile("fence.proxy.async.shared::cta;" ::: "memory");
        __syncthreads();

        if (wid == 0) {
            u64 dah = mk_desc(sbase + OFF_AH), dal = mk_desc(sbase + OFF_AL);
            u64 dbh = mk_desc(sbase + OFF_BH), dbl = mk_desc(sbase + OFF_BL);
            if (elect1()) {
                #pragma unroll
                for (int pass = 0; pass < 3; pass++) {
                    u64 da = (pass == 2) ? dal : dah;
                    u64 db = (pass == 1) ? dbl : dbh;
                    #pragma unroll
                    for (int q = 0; q < 4; q++) {
                        #pragma unroll
                        for (int s = 0; s < 8; s++) {
                            u64 oa = (u64)((s >> 2) * 1024 + (s & 3) * 2);
                            u64 ob = (u64)((s >> 2) * 2048 + (s & 3) * 2 + q * 512);
                            mma_tf32_ss(tmem + q * 64, da + oa, db + ob, ID_TC,
                                        (t | pass | s) ? 1u : 0u);
                        }
                    }
                }
                TC_COMMIT(sbase + OFF_MBARA);
            }
        }

        // ---- prefetch next tile (overlaps MMA t) ----
        if (t < 2) {
            int tn = t + 1;
            #pragma unroll
            for (int p = 0; p < 4; p++) {
                int i = p * 512 + tid; int r = i >> 4, k4 = i & 15;
                va[p] = *reinterpret_cast<const float4*>(w1g + (size_t)r * F + tn * 64 + k4 * 4);
            }
            #pragma unroll
            for (int p = 0; p < 8; p++) {
                int i = p * 512 + tid; int r = i >> 4, k4 = i & 15;
                if (tn == 1)
                    vb[p] = *reinterpret_cast<const float4*>(base1 + (size_t)r * DN + k4 * 4);
                else if (MODE == 0)
                    vb[p] = *reinterpret_cast<const float4*>(base2 + (size_t)r * DN + k4 * 4);
                else
                    vb[p] = *reinterpret_cast<const float4*>(base2 + k4 * 4);  // ctx bcast
            }
        } else {
            // prefetch W2 [64 rows x 128 k]
            #pragma unroll
            for (int p = 0; p < 4; p++) {
                int i = p * 512 + tid; int r = i >> 5, k4 = i & 31;
                vw[p] = *reinterpret_cast<const float4*>(w2g + (size_t)r * HM + k4 * 4);
            }
        }
    }
    MBAR_WAIT(sbase + OFF_MBARA, ph); ph ^= 1;   // GEMM1 fully done
    TC_FENCE_AFTER();

    // ============ GEMM2 setup ============
    int sub  = wid & 3;
    int cgrp = wid >> 2;
    float bj1 = ((float*)(smem + OFF_B1S))[sub * 32 + lane];
    int j = sub * 32 + lane;

    // STS W2 into A buffers (free now)
    #pragma unroll
    for (int p = 0; p < 4; p++) {
        int i = p * 512 + tid; int r = i >> 5, k4 = i & 31;
        split_sts(smem, OFF_AH + tile_off(r, k4 * 4, 8), 32768, vw[p]);
    }

    // ---- epilogue ch0: gelu(D1 cols 0..127) -> hidden tile in B buffers ----
    {
        uint32_t r0[32];
        LDTM_X32(r0, tmem + cgrp * 32);
        TC_WAIT_LD();
        #pragma unroll
        for (int i2 = 0; i2 < 32; i2++) {
            float v = gelu_fast(__uint_as_float(r0[i2]) + bj1);
            float hv = to_tf32(v), lv = v - hv;
            uint32_t off = tile_off(cgrp * 32 + i2, j, 16);
            *reinterpret_cast<float*>(smem + OFF_BH + off) = hv;
            *reinterpret_cast<float*>(smem + OFF_BL + off) = lv;
        }
    }
    asm volatile("fence.proxy.async.shared::cta;" ::: "memory");
    __syncthreads();

    if (wid == 0) {
        u64 dah = mk_desc(sbase + OFF_BH), dal = mk_desc(sbase + OFF_BL);  // A = hidden
        u64 dbh = mk_desc(sbase + OFF_AH), dbl = mk_desc(sbase + OFF_AL);  // B = W2
        if (elect1()) {
            #pragma unroll
            for (int pass = 0; pass < 3; pass++) {
                u64 da = (pass == 2) ? dal : dah;
                u64 db = (pass == 1) ? dbl : dbh;
                #pragma unroll
                for (int s = 0; s < 16; s++) {
                    u64 oa = (u64)((s >> 2) * 1024 + (s & 3) * 2);
                    u64 ob = (u64)((s >> 2) * 512  + (s & 3) * 2);
                    mma_tf32_ss(tmem + 256, da + oa, db + ob, ID_TC, (pass | s) ? 1u : 0u);
                }
            }
            TC_COMMIT(sbase + OFF_MBARB);
        }
    }

    // ---- epilogue ch1 (overlaps GEMM2-ch0 MMA): D1 cols 128..255 ----
    float fv[32];
    {
        uint32_t r1[32];
        LDTM_X32(r1, tmem + 128 + cgrp * 32);
        TC_WAIT_LD();
        #pragma unroll
        for (int i2 = 0; i2 < 32; i2++)
            fv[i2] = gelu_fast(__uint_as_float(r1[i2]) + bj1);
    }
    MBAR_WAIT(sbase + OFF_MBARB, 0);   // ch0 MMA done reading B buffers
    TC_FENCE_AFTER();
    #pragma unroll
    for (int i2 = 0; i2 < 32; i2++) {
        float hv = to_tf32(fv[i2]), lv = fv[i2] - hv;
        uint32_t off = tile_off(cgrp * 32 + i2, j, 16);
        *reinterpret_cast<float*>(smem + OFF_BH + off) = hv;
        *reinterpret_cast<float*>(smem + OFF_BL + off) = lv;
    }
    asm volatile("fence.proxy.async.shared::cta;" ::: "memory");
    __syncthreads();

    if (wid == 0) {
        u64 dah = mk_desc(sbase + OFF_BH), dal = mk_desc(sbase + OFF_BL);
        u64 dbh = mk_desc(sbase + OFF_AH), dbl = mk_desc(sbase + OFF_AL);
        if (elect1()) {
            #pragma unroll
            for (int pass = 0; pass < 3; pass++) {
                u64 da = (pass == 2) ? dal : dah;
                u64 db = (pass == 1) ? dbl : dbh;
                #pragma unroll
                for (int s = 0; s < 16; s++) {
                    u64 oa = (u64)((s >> 2) * 1024 + (s & 3) * 2);
                    u64 ob = (u64)((s >> 2) * 512  + (s & 3) * 2);
                    mma_tf32_ss(tmem + 320, da + oa, db + ob, ID_TC, (pass | s) ? 1u : 0u);
                }
            }
            TC_COMMIT(sbase + OFF_MBARC);
        }
    }

    // ---- final output: warps cgrp<2 write ch0 immediately (mbarB passed),
    //      warps cgrp>=2 wait for ch1 MMA ----
    {
        int ch, jh2;
        if (cgrp < 2) { ch = 0; jh2 = cgrp; }
        else          { ch = 1; jh2 = cgrp - 2;
                        MBAR_WAIT(sbase + OFF_MBARC, 0); TC_FENCE_AFTER(); }
        uint32_t r[32];
        LDTM_X32(r, tmem + 256 + ch * 64 + jh2 * 32);
        TC_WAIT_LD();
        int c  = ch * 128 + sub * 32 + lane;
        int jb = jh2 * 32;
        const float* b2s = (float*)(smem + OFF_B2S);
        float* op = out + ((size_t)bn * CN + c) * DN + jb;
        const float* hp = base_h + (size_t)c * DN + jb;
        #pragma unroll
        for (int i4 = 0; i4 < 8; i4++) {
            float4 v;
            v.x = __uint_as_float(r[i4 * 4 + 0]) + b2s[jb + i4 * 4 + 0];
            v.y = __uint_as_float(r[i4 * 4 + 1]) + b2s[jb + i4 * 4 + 1];
            v.z = __uint_as_float(r[i4 * 4 + 2]) + b2s[jb + i4 * 4 + 2];
            v.w = __uint_as_float(r[i4 * 4 + 3]) + b2s[jb + i4 * 4 + 3];
            if (MODE == 1) {
                float4 hv = *reinterpret_cast<const float4*>(hp + i4 * 4);
                v.x += hv.x; v.y += hv.y; v.z += hv.z; v.w += hv.w;
            }
            *reinterpret_cast<float4*>(op + i4 * 4) = v;
        }
    }

    __syncthreads();
    if (wid == 0) TC_DEALLOC(tmem, 512);

#else  // ---------------- SIMT fallback (plain compute_103 pass only) -------
    float* Hs  = (float*)(smem + OFF_AH);
    float* B1s = (float*)(smem + OFF_B1S);
    float* B2s = (float*)(smem + OFF_B2S);
    if (tid < HM) B1s[tid] = b1[g * HM + tid];
    if (tid < DN) B2s[tid] = b2[g * DN + tid];
    __syncthreads();

    for (int idx = tid; idx < CN * HM; idx += 512) {
        int c = idx >> 7, jj = idx & 127;
        float acc = B1s[jj];
        const float* wr = w1g + (size_t)jj * F;
        for (int f = 0; f < DN; f++)  acc = fmaf(wr[f],       base_h[(size_t)c * DN + f], acc);
        for (int f = 0; f < DN; f++)  acc = fmaf(wr[64 + f],  base1 [(size_t)c * DN + f], acc);
        for (int f = 0; f < DN; f++) {
            float fvv = (MODE == 0) ? base2[(size_t)c * DN + f] : base2[f];
            acc = fmaf(wr[128 + f], fvv, acc);
        }
        Hs[idx] = gelu_f(acc);
    }
    __syncthreads();

    for (int idx = tid; idx < CN * DN; idx += 512) {
        int c = idx >> 6, j2 = idx & 63;
        float acc = B2s[j2];
        const float* wr = w2g + (size_t)j2 * HM;
        const float* hr = Hs + (size_t)c * HM;
        for (int k = 0; k < HM; k++) acc = fmaf(wr[k], hr[k], acc);
        if (MODE == 1) acc += base_h[(size_t)c * DN + j2];
        out[((size_t)bn * CN + c) * DN + j2] = acc;
    }
#endif
}

// ---------------------------------------------------------------------------
// Modulation MLP: coalesced float4 pooling (512 threads) + tiny MLP.
// ---------------------------------------------------------------------------
__global__ __launch_bounds__(512) void mod_kernel(
    const float* __restrict__ hnew,
    const float* __restrict__ msg,
    const float* __restrict__ mw1,
    const float* __restrict__ mb1,
    const float* __restrict__ mw2,
    const float* __restrict__ mb2,
    float*       __restrict__ mod)
{
    __shared__ float4 part4[2][32][16];   // 16 KB
    __shared__ float pooled[2 * DN];
    __shared__ float phh[HMOD];

    int bn  = blockIdx.x;
    int n   = bn & (NC - 1);
    int tid = threadIdx.x;

    int d4 = tid & 15;
    int rg = tid >> 4;                    // 0..31

    const float4* ph4 = reinterpret_cast<const float4*>(hnew + (size_t)bn * CN * DN);
    const float4* pm4 = reinterpret_cast<const float4*>(msg  + (size_t)bn * CN * DN);
    float4 sh = {0,0,0,0}, sm = {0,0,0,0};
    #pragma unroll 8
    for (int i = 0; i < 8; i++) {
        int c = i * 32 + rg;
        float4 a = ph4[(size_t)c * 16 + d4];
        float4 b = pm4[(size_t)c * 16 + d4];
        sh.x += a.x; sh.y += a.y; sh.z += a.z; sh.w += a.w;
        sm.x += b.x; sm.y += b.y; sm.z += b.z; sm.w += b.w;
    }
    part4[0][rg][d4] = sh;
    part4[1][rg][d4] = sm;
    __syncthreads();

    if (tid < 2 * DN) {
        int src = tid >> 6, d = tid & 63;
        const float* base = reinterpret_cast<const float*>(&part4[src][0][0]) + d;
        float s = 0.0f;
        #pragma unroll 8
        for (int r = 0; r < 32; r++) s += base[r * 64];
        pooled[tid] = s * (1.0f / CN);
    }
    __syncthreads();

    if (tid < HMOD) {
        const float* w = mw1 + (size_t)n * (2 * DN) * HMOD + tid;
        float acc = mb1[n * HMOD + tid];
        #pragma unroll 8
        for (int f = 0; f < 2 * DN; f++) acc = fmaf(pooled[f], w[f * HMOD], acc);
        phh[tid] = gelu_f(acc);
    }
    __syncthreads();

    if (tid < MOD_OUT) {
        const float* w = mw2 + (size_t)n * HMOD * MOD_OUT + tid;
        float acc = mb2[n * MOD_OUT + tid];
        #pragma unroll 8
        for (int k = 0; k < HMOD; k++) acc = fmaf(phh[k], w[k * MOD_OUT], acc);
        mod[bn * MOD_OUT + tid] = acc;
    }
}

// ---------------------------------------------------------------------------
// Launch
// ---------------------------------------------------------------------------
extern "C" void kernel_launch(void* const* d_in, const int* in_sizes, int n_in,
                              void* d_out, int out_size)
{
    const float* h      = (const float*)d_in[0];
    const float* w_conn = (const float*)d_in[1];
    const float* ctx    = (const float*)d_in[2];
    const float* nid    = (const float*)d_in[3];
    const float* mw1    = (const float*)d_in[4];
    const float* mb1    = (const float*)d_in[5];
    const float* mw2    = (const float*)d_in[6];
    const float* mb2    = (const float*)d_in[7];
    const float* sw1    = (const float*)d_in[8];
    const float* sb1    = (const float*)d_in[9];
    const float* sw2    = (const float*)d_in[10];
    const float* sb2    = (const float*)d_in[11];
    const float* modw1  = (const float*)d_in[12];
    const float* modb1  = (const float*)d_in[13];
    const float* modw2  = (const float*)d_in[14];
    const float* modb2  = (const float*)d_in[15];
    const int*   conn   = (const int*)d_in[16];
    const int*   c2g    = (const int*)d_in[17];

    float* out   = (float*)d_out;
    float* o_h   = out;
    float* o_msg = out + (size_t)Bb * NC * CN * DN;
    float* o_mod = o_msg + (size_t)Bb * NC * CN * DN;

    const int grid = Bb * NC;  // 512
    const size_t smA = (size_t)CN * DN * sizeof(float);   // 64 KB

    static bool attr_done = false;
    if (!attr_done) {
        cudaFuncSetAttribute(agg_kernel, cudaFuncAttributeMaxDynamicSharedMemorySize, (int)smA);
        cudaFuncSetAttribute(mlp_tc_kernel<0>, cudaFuncAttributeMaxDynamicSharedMemorySize, SMEM_MLP);
        cudaFuncSetAttribute(mlp_tc_kernel<1>, cudaFuncAttributeMaxDynamicSharedMemorySize, SMEM_MLP);
        attr_done = true;
    }

    agg_kernel<<<grid, 256, smA>>>(h, w_conn, conn);
    mlp_tc_kernel<0><<<grid, 512, SMEM_MLP>>>(h, nullptr, nid, mw1, mb1, mw2, mb2, c2g, o_msg);
    mlp_tc_kernel<1><<<grid, 512, SMEM_MLP>>>(h, o_msg, ctx, sw1, sb1, sw2, sb2, c2g, o_h);
    mod_kernel<<<grid, 512>>>(o_h, o_msg, modw1, modb1, modw2, modb2, o_mod);
}

// round 9
// speedup vs baseline: 2.4563x; 1.0339x over previous
#include <cuda_runtime.h>
#include <cstdint>

typedef unsigned long long u64;

// Problem constants
constexpr int Bb  = 2;
constexpr int NC  = 256;
constexpr int CN  = 256;
constexpr int K   = 16;
constexpr int DN  = 64;
constexpr int HM  = 128;
constexpr int F   = 192;
constexpr int HMOD = 64;
constexpr int MOD_OUT = 5;

// Scratch
__device__ float g_agg[(size_t)Bb * NC * CN * DN];
__device__ float g_pooled[(size_t)Bb * NC * 2 * DN];   // [bn][h_mean|msg_mean]

// ---------------- SMEM layout (bytes) --------------------------------------
constexpr int OFF_TMEM  = 0;
constexpr int OFF_MBARA = 8;
constexpr int OFF_MBARB = 16;
constexpr int OFF_MBARC = 24;
constexpr int OFF_B1M   = 32;     // 128 f
constexpr int OFF_B2M   = 544;    // 64 f
constexpr int OFF_B1SS  = 800;    // 128 f
constexpr int OFF_B2SS  = 1312;   // 64 f
constexpr int OFF_POOL  = 1568;   // 128 f
constexpr int OFF_AH    = 3072;            // 32KB
constexpr int OFF_AL    = 3072 + 32768;    // 32KB
constexpr int OFF_BH    = 3072 + 65536;    // 64KB
constexpr int OFF_BL    = 3072 + 131072;   // 64KB
constexpr int SMEM_MLP  = 3072 + 196608;   // 199680 B

#if defined(__CUDA_ARCH_FEAT_SM103_ALL) || defined(__CUDA_ARCH_FEAT_SM100_ALL) || defined(__CUDA_ARCH_FEAT_SM101_ALL)
#define HAS_TCGEN05 1
#else
#define HAS_TCGEN05 0
#endif

__device__ __forceinline__ uint32_t smem_u32(const void* p) {
    uint32_t a;
    asm("{ .reg .u64 t; cvta.to.shared.u64 t, %1; cvt.u32.u64 %0, t; }"
        : "=r"(a) : "l"(p));
    return a;
}

#if HAS_TCGEN05
__device__ __forceinline__ uint32_t elect1() {
    uint32_t p;
    asm volatile("{ .reg .pred p; elect.sync _|p, 0xFFFFFFFF; selp.b32 %0, 1, 0, p; }"
                 : "=r"(p));
    return p;
}

#define TC_ALLOC(smem_addr, n) \
    asm volatile("tcgen05.alloc.cta_group::1.sync.aligned.shared::cta.b32 [%0], %1;" \
                 :: "r"((uint32_t)(smem_addr)), "r"((uint32_t)(n)) : "memory")
#define TC_RELINQ() \
    asm volatile("tcgen05.relinquish_alloc_permit.cta_group::1.sync.aligned;")
#define TC_DEALLOC(tmem, n) \
    asm volatile("tcgen05.dealloc.cta_group::1.sync.aligned.b32 %0, %1;" \
                 :: "r"(tmem), "r"((uint32_t)(n)))
#define TC_COMMIT(mbar) \
    asm volatile("tcgen05.commit.cta_group::1.mbarrier::arrive::one.shared::cluster.b64 [%0];" \
                 :: "r"((uint32_t)(mbar)) : "memory")
#define TC_FENCE_AFTER()  asm volatile("tcgen05.fence::after_thread_sync;" ::: "memory")
#define TC_WAIT_LD()      asm volatile("tcgen05.wait::ld.sync.aligned;" ::: "memory")

#define LDTM_X32(r, addr) \
    asm volatile( \
        "tcgen05.ld.sync.aligned.32x32b.x32.b32 " \
        "{%0, %1, %2, %3, %4, %5, %6, %7, " \
        " %8, %9, %10, %11, %12, %13, %14, %15, " \
        " %16, %17, %18, %19, %20, %21, %22, %23, " \
        " %24, %25, %26, %27, %28, %29, %30, %31}, [%32];" \
        : "=r"((r)[0]),  "=r"((r)[1]),  "=r"((r)[2]),  "=r"((r)[3]), \
          "=r"((r)[4]),  "=r"((r)[5]),  "=r"((r)[6]),  "=r"((r)[7]), \
          "=r"((r)[8]),  "=r"((r)[9]),  "=r"((r)[10]), "=r"((r)[11]), \
          "=r"((r)[12]), "=r"((r)[13]), "=r"((r)[14]), "=r"((r)[15]), \
          "=r"((r)[16]), "=r"((r)[17]), "=r"((r)[18]), "=r"((r)[19]), \
          "=r"((r)[20]), "=r"((r)[21]), "=r"((r)[22]), "=r"((r)[23]), \
          "=r"((r)[24]), "=r"((r)[25]), "=r"((r)[26]), "=r"((r)[27]), \
          "=r"((r)[28]), "=r"((r)[29]), "=r"((r)[30]), "=r"((r)[31]) \
        : "r"(addr))

__device__ __forceinline__ void mma_tf32_ss(uint32_t d_tmem, u64 a_desc, u64 b_desc,
                                            uint32_t idesc, uint32_t enable) {
    asm volatile(
        "{\n\t"
        ".reg .pred p;\n\t"
        "setp.ne.u32 p, %4, 0;\n\t"
        "tcgen05.mma.cta_group::1.kind::tf32 [%0], %1, %2, %3, {%5, %5, %5, %5}, p;\n\t"
        "}"
        :: "r"(d_tmem), "l"(a_desc), "l"(b_desc), "r"(idesc), "r"(enable), "r"(0u)
        : "memory");
}
#endif  // HAS_TCGEN05

#define MBAR_INIT(mbar, cnt) \
    asm volatile("mbarrier.init.shared.b64 [%0], %1;" \
                 :: "r"((uint32_t)(mbar)), "r"((uint32_t)(cnt)) : "memory")

#define MBAR_WAIT(mbar, parity) do {                                           \
    uint32_t _m = (uint32_t)(mbar), _p = (uint32_t)(parity), _d;               \
    asm volatile("{ .reg .pred p;"                                             \
        " mbarrier.try_wait.parity.acquire.cta.shared::cta.b64 p, [%1], %2;"   \
        " selp.b32 %0, 1, 0, p; }" : "=r"(_d) : "r"(_m), "r"(_p) : "memory");  \
    while (!_d) {                                                              \
        asm volatile("{ .reg .pred p;"                                         \
            " mbarrier.try_wait.parity.acquire.cta.shared::cta.b64 p, [%1], %2, 0x989680;" \
            " selp.b32 %0, 1, 0, p; }" : "=r"(_d) : "r"(_m), "r"(_p) : "memory"); \
    }                                                                          \
} while (0)

constexpr u64 DESC_BASE = (2ull << 61) | (1ull << 46) | (64ull << 32) | (1ull << 16);
__device__ __forceinline__ u64 mk_desc(uint32_t addr) {
    return DESC_BASE | ((u64)(addr >> 4) & 0x3FFF);
}

// Blocked-atom + SW128 byte offset. atom = 8 rows x 32 tf32 (128B).
__device__ __forceinline__ uint32_t tile_off(int row, int k, int atom_rows) {
    uint32_t o = ((uint32_t)((k >> 5) * atom_rows + (row >> 3)) << 10)
               + ((uint32_t)(row & 7) << 7) + ((uint32_t)(k & 31) << 2);
    return o ^ ((o >> 3) & 0x70);
}

__device__ __forceinline__ float to_tf32(float x) {
    float r;
    asm("cvt.rna.tf32.f32 %0, %1;" : "=f"(r) : "f"(x));
    return r;
}

__device__ __forceinline__ void split_sts(char* smem, uint32_t off_hi, uint32_t lo_delta,
                                          float4 v) {
    float4 hv, lv;
    hv.x = to_tf32(v.x); hv.y = to_tf32(v.y); hv.z = to_tf32(v.z); hv.w = to_tf32(v.w);
    lv.x = v.x - hv.x;   lv.y = v.y - hv.y;   lv.z = v.z - hv.z;   lv.w = v.w - hv.w;
    *reinterpret_cast<float4*>(smem + off_hi)            = hv;
    *reinterpret_cast<float4*>(smem + off_hi + lo_delta) = lv;
}

__device__ __forceinline__ float gelu_f(float x) {
    float x3 = x * x * x;
    return 0.5f * x * (1.0f + tanhf(0.7978845608028654f * (x + 0.044715f * x3)));
}

__device__ __forceinline__ float gelu_fast(float x) {
    float z = x + 0.044715f * x * x * x;
    float a = 2.3022081852f * z;
    float e;
    asm("ex2.approx.f32 %0, %1;" : "=f"(e) : "f"(a));
    float r;
    asm("rcp.approx.f32 %0, %1;" : "=f"(r) : "f"(e + 1.0f));
    return x - x * r;
}

constexpr uint32_t ID_TC = (1u << 4) | (2u << 7) | (2u << 10) | (8u << 17) | (8u << 24);

// ---------------------------------------------------------------------------
// Kernel 1: connection-weighted aggregation (unchanged, proven).
// ---------------------------------------------------------------------------
__global__ __launch_bounds__(256) void agg_kernel(
    const float* __restrict__ h,
    const float* __restrict__ w_conn,
    const int*   __restrict__ conn)
{
    extern __shared__ float smf[];
    float4* h_sm = reinterpret_cast<float4*>(smf);

    int bn = blockIdx.x;
    int n  = bn & (NC - 1);

    const float4* hg = reinterpret_cast<const float4*>(h) + (size_t)bn * CN * DN / 4;
    for (int i = threadIdx.x; i < CN * DN / 4; i += 256) h_sm[i] = hg[i];
    __syncthreads();

    int dq = threadIdx.x & 3;
    int cr = threadIdx.x >> 2;

    for (int cp = 0; cp < 4; cp++) {
        int c = cp * 64 + cr;
        float4 a0 = {0,0,0,0}, a1 = {0,0,0,0}, a2 = {0,0,0,0}, a3 = {0,0,0,0};
        const int*   ci = conn   + ((size_t)n  * CN + c) * K;
        const float* wc = w_conn + ((size_t)bn * CN + c) * K;
        #pragma unroll
        for (int k = 0; k < K; k++) {
            int   idx = ci[k];
            float w   = wc[k];
            const float4* row = h_sm + idx * (DN / 4) + dq * 4;
            float4 r0 = row[0], r1 = row[1], r2 = row[2], r3 = row[3];
            a0.x += w * r0.x; a0.y += w * r0.y; a0.z += w * r0.z; a0.w += w * r0.w;
            a1.x += w * r1.x; a1.y += w * r1.y; a1.z += w * r1.z; a1.w += w * r1.w;
            a2.x += w * r2.x; a2.y += w * r2.y; a2.z += w * r2.z; a2.w += w * r2.w;
            a3.x += w * r3.x; a3.y += w * r3.y; a3.z += w * r3.z; a3.w += w * r3.w;
        }
        float4* out = reinterpret_cast<float4*>(g_agg + ((size_t)bn * CN + c) * DN) + dq * 4;
        out[0] = a0; out[1] = a1; out[2] = a2; out[3] = a3;
    }
}

#if HAS_TCGEN05
// GEMM2 phase: hidden = gelu(D1 + b1) staged hi/lo into B buffers; two N=64
// column chunks of D2 at tmem+256 / tmem+320. On return all warps have passed
// MBARC (A and B buffers free, D2 complete).
__device__ __forceinline__ void gemm2_phase(
    char* smem, uint32_t sbase, uint32_t tmem,
    int wid, int lane, int sub, int cgrp, float bj1, uint32_t parity)
{
    int j = sub * 32 + lane;
    // epilogue ch0
    {
        uint32_t r0[32];
        LDTM_X32(r0, tmem + cgrp * 32);
        TC_WAIT_LD();
        #pragma unroll
        for (int i2 = 0; i2 < 32; i2++) {
            float v = gelu_fast(__uint_as_float(r0[i2]) + bj1);
            float hv = to_tf32(v), lv = v - hv;
            uint32_t off = tile_off(cgrp * 32 + i2, j, 16);
            *reinterpret_cast<float*>(smem + OFF_BH + off) = hv;
            *reinterpret_cast<float*>(smem + OFF_BL + off) = lv;
        }
    }
    asm volatile("fence.proxy.async.shared::cta;" ::: "memory");
    __syncthreads();

    if (wid == 0) {
        u64 dah = mk_desc(sbase + OFF_BH), dal = mk_desc(sbase + OFF_BL);
        u64 dbh = mk_desc(sbase + OFF_AH), dbl = mk_desc(sbase + OFF_AL);
        if (elect1()) {
            #pragma unroll
            for (int pass = 0; pass < 3; pass++) {
                u64 da = (pass == 2) ? dal : dah;
                u64 db = (pass == 1) ? dbl : dbh;
                #pragma unroll
                for (int s = 0; s < 16; s++) {
                    u64 oa = (u64)((s >> 2) * 1024 + (s & 3) * 2);
                    u64 ob = (u64)((s >> 2) * 512  + (s & 3) * 2);
                    mma_tf32_ss(tmem + 256, da + oa, db + ob, ID_TC, (pass | s) ? 1u : 0u);
                }
            }
            TC_COMMIT(sbase + OFF_MBARB);
        }
    }

    // epilogue ch1 (overlaps ch0 MMA)
    float fv[32];
    {
        uint32_t r1[32];
        LDTM_X32(r1, tmem + 128 + cgrp * 32);
        TC_WAIT_LD();
        #pragma unroll
        for (int i2 = 0; i2 < 32; i2++)
            fv[i2] = gelu_fast(__uint_as_float(r1[i2]) + bj1);
    }
    MBAR_WAIT(sbase + OFF_MBARB, parity);
    TC_FENCE_AFTER();
    #pragma unroll
    for (int i2 = 0; i2 < 32; i2++) {
        float hv = to_tf32(fv[i2]), lv = fv[i2] - hv;
        uint32_t off = tile_off(cgrp * 32 + i2, j, 16);
        *reinterpret_cast<float*>(smem + OFF_BH + off) = hv;
        *reinterpret_cast<float*>(smem + OFF_BL + off) = lv;
    }
    asm volatile("fence.proxy.async.shared::cta;" ::: "memory");
    __syncthreads();

    if (wid == 0) {
        u64 dah = mk_desc(sbase + OFF_BH), dal = mk_desc(sbase + OFF_BL);
        u64 dbh = mk_desc(sbase + OFF_AH), dbl = mk_desc(sbase + OFF_AL);
        if (elect1()) {
            #pragma unroll
            for (int pass = 0; pass < 3; pass++) {
                u64 da = (pass == 2) ? dal : dah;
                u64 db = (pass == 1) ? dbl : dbh;
                #pragma unroll
                for (int s = 0; s < 16; s++) {
                    u64 oa = (u64)((s >> 2) * 1024 + (s & 3) * 2);
                    u64 ob = (u64)((s >> 2) * 512  + (s & 3) * 2);
                    mma_tf32_ss(tmem + 320, da + oa, db + ob, ID_TC, (pass | s) ? 1u : 0u);
                }
            }
            TC_COMMIT(sbase + OFF_MBARC);
        }
    }
    MBAR_WAIT(sbase + OFF_MBARC, parity);
    TC_FENCE_AFTER();
}

// GEMM1 MMA issue for one K=64 tile: D1[j=128][c=256] over 4 N=64 chunks.
// NOTE: when `first` is set, EVERY q-chunk's first (pass=0,s=0) MMA must have
// enable_d=0 — each chunk owns distinct TMEM columns (round-8 bug was q==0 only).
__device__ __forceinline__ void gemm1_mma(uint32_t sbase, uint32_t tmem, bool first) {
    u64 dah = mk_desc(sbase + OFF_AH), dal = mk_desc(sbase + OFF_AL);
    u64 dbh = mk_desc(sbase + OFF_BH), dbl = mk_desc(sbase + OFF_BL);
    if (elect1()) {
        #pragma unroll
        for (int pass = 0; pass < 3; pass++) {
            u64 da = (pass == 2) ? dal : dah;
            u64 db = (pass == 1) ? dbl : dbh;
            #pragma unroll
            for (int q = 0; q < 4; q++) {
                #pragma unroll
                for (int s = 0; s < 8; s++) {
                    u64 oa = (u64)((s >> 2) * 1024 + (s & 3) * 2);
                    u64 ob = (u64)((s >> 2) * 2048 + (s & 3) * 2 + q * 512);
                    mma_tf32_ss(tmem + q * 64, da + oa, db + ob, ID_TC,
                                (first && pass == 0 && s == 0) ? 0u : 1u);
                }
            }
        }
        TC_COMMIT(sbase + OFF_MBARA);
    }
}
#endif  // HAS_TCGEN05

// ---------------------------------------------------------------------------
// Fully fused per-(b,n) kernel: msg MLP -> state MLP (+residual) + pooled stats.
// ---------------------------------------------------------------------------
__global__ __launch_bounds__(512, 1)
void fused_mlp_kernel(
    const float* __restrict__ h,
    const float* __restrict__ ctx,
    const float* __restrict__ nid,
    const float* __restrict__ mw1, const float* __restrict__ mb1,
    const float* __restrict__ mw2, const float* __restrict__ mb2,
    const float* __restrict__ sw1, const float* __restrict__ sb1,
    const float* __restrict__ sw2, const float* __restrict__ sb2,
    const int*   __restrict__ c2g,
    float*       __restrict__ o_msg,
    float*       __restrict__ o_h)
{
    extern __shared__ char smem[];
    uint32_t sbase = smem_u32(smem);

    int tid  = threadIdx.x;
    int wid  = tid >> 5;
    int lane = tid & 31;
    int bn   = blockIdx.x;
    int n    = bn & (NC - 1);
    int g    = c2g[n];

    const float* w1m    = mw1 + (size_t)g * HM * F;
    const float* w2m    = mw2 + (size_t)g * DN * HM;
    const float* w1s    = sw1 + (size_t)g * HM * F;
    const float* w2s    = sw2 + (size_t)g * DN * HM;
    const float* base_h = h + (size_t)bn * CN * DN;
    const float* base_a = g_agg + (size_t)bn * CN * DN;
    const float* base_n = nid + (size_t)n * CN * DN;
    const float* base_c = ctx + (size_t)bn * DN;
    float* pool = (float*)(smem + OFF_POOL);

#if HAS_TCGEN05
    if (wid == 0) {
        TC_ALLOC(sbase + OFF_TMEM, 512);
        TC_RELINQ();
    }
    if (tid == 0) {
        MBAR_INIT(sbase + OFF_MBARA, 1);
        MBAR_INIT(sbase + OFF_MBARB, 1);
        MBAR_INIT(sbase + OFF_MBARC, 1);
    }
    if (tid < HM) {
        ((float*)(smem + OFF_B1M))[tid]  = mb1[g * HM + tid];
        ((float*)(smem + OFF_B1SS))[tid] = sb1[g * HM + tid];
    }
    if (tid < DN) {
        ((float*)(smem + OFF_B2M))[tid]  = mb2[g * DN + tid];
        ((float*)(smem + OFF_B2SS))[tid] = sb2[g * DN + tid];
    }
    if (tid < 2 * DN) pool[tid] = 0.0f;
    __syncthreads();

    uint32_t tmem;
    asm("ld.shared.b32 %0, [%1];" : "=r"(tmem) : "r"(sbase + OFF_TMEM));

    uint32_t ph = 0;
    int sub  = wid & 3;
    int cgrp = wid >> 2;
    int j    = sub * 32 + lane;

    float4 va[4], vb[8], vw[4];
    // prefetch msg tile 0: W1m cols 0:64 + h
    #pragma unroll
    for (int p = 0; p < 4; p++) {
        int i = p * 512 + tid; int r = i >> 4, k4 = i & 15;
        va[p] = *reinterpret_cast<const float4*>(w1m + (size_t)r * F + k4 * 4);
    }
    #pragma unroll
    for (int p = 0; p < 8; p++) {
        int i = p * 512 + tid; int r = i >> 4, k4 = i & 15;
        vb[p] = *reinterpret_cast<const float4*>(base_h + (size_t)r * DN + k4 * 4);
    }

    // ===================== MSG GEMM1 =====================
    for (int t = 0; t < 3; t++) {
        if (t > 0) { MBAR_WAIT(sbase + OFF_MBARA, ph); ph ^= 1; TC_FENCE_AFTER(); }
        #pragma unroll
        for (int p = 0; p < 4; p++) {
            int i = p * 512 + tid; int r = i >> 4, k4 = i & 15;
            split_sts(smem, OFF_AH + tile_off(r, k4 * 4, 16), 32768, va[p]);
        }
        #pragma unroll
        for (int p = 0; p < 8; p++) {
            int i = p * 512 + tid; int r = i >> 4, k4 = i & 15;
            split_sts(smem, OFF_BH + tile_off(r, k4 * 4, 32), 65536, vb[p]);
        }
        asm volatile("fence.proxy.async.shared::cta;" ::: "memory");
        __syncthreads();
        if (wid == 0) gemm1_mma(sbase, tmem, t == 0);

        if (t < 2) {
            int tn = t + 1;
            #pragma unroll
            for (int p = 0; p < 4; p++) {
                int i = p * 512 + tid; int r = i >> 4, k4 = i & 15;
                va[p] = *reinterpret_cast<const float4*>(w1m + (size_t)r * F + tn * 64 + k4 * 4);
            }
            #pragma unroll
            for (int p = 0; p < 8; p++) {
                int i = p * 512 + tid; int r = i >> 4, k4 = i & 15;
                const float* src = (tn == 1) ? base_a : base_n;
                vb[p] = *reinterpret_cast<const float4*>(src + (size_t)r * DN + k4 * 4);
            }
        } else {
            #pragma unroll
            for (int p = 0; p < 4; p++) {
                int i = p * 512 + tid; int r = i >> 5, k4 = i & 31;
                vw[p] = *reinterpret_cast<const float4*>(w2m + (size_t)r * HM + k4 * 4);
            }
        }
    }
    MBAR_WAIT(sbase + OFF_MBARA, ph); ph ^= 1;
    TC_FENCE_AFTER();

    // ===================== MSG GEMM2 =====================
    // stage W2m into A buffers
    #pragma unroll
    for (int p = 0; p < 4; p++) {
        int i = p * 512 + tid; int r = i >> 5, k4 = i & 31;
        split_sts(smem, OFF_AH + tile_off(r, k4 * 4, 8), 32768, vw[p]);
    }
    // prefetch state t0 A-chunk: W1s cols 64:128 (the msg part of state feat)
    #pragma unroll
    for (int p = 0; p < 4; p++) {
        int i = p * 512 + tid; int r = i >> 4, k4 = i & 15;
        va[p] = *reinterpret_cast<const float4*>(w1s + (size_t)r * F + 64 + k4 * 4);
    }
    float bj1m = ((float*)(smem + OFF_B1M))[j];
    gemm2_phase(smem, sbase, tmem, wid, lane, sub, cgrp, bj1m, 0);

    // ---- msg epilogue: D2 -> o_msg, pooled, and state feat tile in B ----
    {
        int ch  = cgrp >> 1;
        int jh2 = cgrp & 1;
        uint32_t r[32];
        LDTM_X32(r, tmem + 256 + ch * 64 + jh2 * 32);
        TC_WAIT_LD();
        int c  = ch * 128 + sub * 32 + lane;
        int jb = jh2 * 32;
        const float* b2s = (float*)(smem + OFF_B2M);
        float mv[32];
        #pragma unroll
        for (int i2 = 0; i2 < 32; i2++)
            mv[i2] = __uint_as_float(r[i2]) + b2s[jb + i2];
        // STG msg
        float* op = o_msg + ((size_t)bn * CN + c) * DN + jb;
        #pragma unroll
        for (int i4 = 0; i4 < 8; i4++)
            *reinterpret_cast<float4*>(op + i4 * 4) =
                make_float4(mv[i4 * 4], mv[i4 * 4 + 1], mv[i4 * 4 + 2], mv[i4 * 4 + 3]);
        // stage as state feat tile row=c, k=jb+i2 (B tile [256 x 64], atoms=32)
        #pragma unroll
        for (int i2 = 0; i2 < 32; i2++) {
            float hv = to_tf32(mv[i2]), lv = mv[i2] - hv;
            uint32_t off = tile_off(c, jb + i2, 32);
            *reinterpret_cast<float*>(smem + OFF_BH + off) = hv;
            *reinterpret_cast<float*>(smem + OFF_BL + off) = lv;
        }
        // pooled msg mean: butterfly over lanes (c), pick reg == lane
        float psum = 0.0f;
        #pragma unroll
        for (int i2 = 0; i2 < 32; i2++) {
            float v = mv[i2];
            v += __shfl_xor_sync(0xFFFFFFFFu, v, 16);
            v += __shfl_xor_sync(0xFFFFFFFFu, v, 8);
            v += __shfl_xor_sync(0xFFFFFFFFu, v, 4);
            v += __shfl_xor_sync(0xFFFFFFFFu, v, 2);
            v += __shfl_xor_sync(0xFFFFFFFFu, v, 1);
            if (lane == i2) psum = v;
        }
        atomicAdd(&pool[DN + jb + lane], psum);
    }
    asm volatile("fence.proxy.async.shared::cta;" ::: "memory");
    __syncthreads();

    // ===================== STATE GEMM1 =====================
    // t=0: B = msg tile (already staged), A = W1s cols 64:128 (in va)
    #pragma unroll
    for (int p = 0; p < 4; p++) {
        int i = p * 512 + tid; int r = i >> 4, k4 = i & 15;
        split_sts(smem, OFF_AH + tile_off(r, k4 * 4, 16), 32768, va[p]);
    }
    asm volatile("fence.proxy.async.shared::cta;" ::: "memory");
    __syncthreads();
    if (wid == 0) gemm1_mma(sbase, tmem, true);
    // prefetch t1: W1s cols 0:64 + h
    #pragma unroll
    for (int p = 0; p < 4; p++) {
        int i = p * 512 + tid; int r = i >> 4, k4 = i & 15;
        va[p] = *reinterpret_cast<const float4*>(w1s + (size_t)r * F + k4 * 4);
    }
    #pragma unroll
    for (int p = 0; p < 8; p++) {
        int i = p * 512 + tid; int r = i >> 4, k4 = i & 15;
        vb[p] = *reinterpret_cast<const float4*>(base_h + (size_t)r * DN + k4 * 4);
    }
    for (int t = 1; t < 3; t++) {
        MBAR_WAIT(sbase + OFF_MBARA, ph); ph ^= 1; TC_FENCE_AFTER();
        #pragma unroll
        for (int p = 0; p < 4; p++) {
            int i = p * 512 + tid; int r = i >> 4, k4 = i & 15;
            split_sts(smem, OFF_AH + tile_off(r, k4 * 4, 16), 32768, va[p]);
        }
        #pragma unroll
        for (int p = 0; p < 8; p++) {
            int i = p * 512 + tid; int r = i >> 4, k4 = i & 15;
            split_sts(smem, OFF_BH + tile_off(r, k4 * 4, 32), 65536, vb[p]);
        }
        asm volatile("fence.proxy.async.shared::cta;" ::: "memory");
        __syncthreads();
        if (wid == 0) gemm1_mma(sbase, tmem, false);

        if (t == 1) {
            #pragma unroll
            for (int p = 0; p < 4; p++) {
                int i = p * 512 + tid; int r = i >> 4, k4 = i & 15;
                va[p] = *reinterpret_cast<const float4*>(w1s + (size_t)r * F + 128 + k4 * 4);
            }
            #pragma unroll
            for (int p = 0; p < 8; p++) {
                int i = p * 512 + tid; int k4 = i & 15;
                vb[p] = *reinterpret_cast<const float4*>(base_c + k4 * 4);   // ctx bcast
            }
        } else {
            #pragma unroll
            for (int p = 0; p < 4; p++) {
                int i = p * 512 + tid; int r = i >> 5, k4 = i & 31;
                vw[p] = *reinterpret_cast<const float4*>(w2s + (size_t)r * HM + k4 * 4);
            }
        }
    }
    MBAR_WAIT(sbase + OFF_MBARA, ph); ph ^= 1;
    TC_FENCE_AFTER();

    // ===================== STATE GEMM2 =====================
    #pragma unroll
    for (int p = 0; p < 4; p++) {
        int i = p * 512 + tid; int r = i >> 5, k4 = i & 31;
        split_sts(smem, OFF_AH + tile_off(r, k4 * 4, 8), 32768, vw[p]);
    }
    float bj1s = ((float*)(smem + OFF_B1SS))[j];
    gemm2_phase(smem, sbase, tmem, wid, lane, sub, cgrp, bj1s, 1);

    // ---- state epilogue: D2 + b2s + h residual -> o_h, pooled ----
    {
        int ch  = cgrp >> 1;
        int jh2 = cgrp & 1;
        uint32_t r[32];
        LDTM_X32(r, tmem + 256 + ch * 64 + jh2 * 32);
        TC_WAIT_LD();
        int c  = ch * 128 + sub * 32 + lane;
        int jb = jh2 * 32;
        const float* b2s = (float*)(smem + OFF_B2SS);
        const float* hp = base_h + (size_t)c * DN + jb;
        float hv[32];
        #pragma unroll
        for (int i4 = 0; i4 < 8; i4++) {
            float4 hr = *reinterpret_cast<const float4*>(hp + i4 * 4);
            hv[i4 * 4 + 0] = __uint_as_float(r[i4 * 4 + 0]) + b2s[jb + i4 * 4 + 0] + hr.x;
            hv[i4 * 4 + 1] = __uint_as_float(r[i4 * 4 + 1]) + b2s[jb + i4 * 4 + 1] + hr.y;
            hv[i4 * 4 + 2] = __uint_as_float(r[i4 * 4 + 2]) + b2s[jb + i4 * 4 + 2] + hr.z;
            hv[i4 * 4 + 3] = __uint_as_float(r[i4 * 4 + 3]) + b2s[jb + i4 * 4 + 3] + hr.w;
        }
        float* op = o_h + ((size_t)bn * CN + c) * DN + jb;
        #pragma unroll
        for (int i4 = 0; i4 < 8; i4++)
            *reinterpret_cast<float4*>(op + i4 * 4) =
                make_float4(hv[i4 * 4], hv[i4 * 4 + 1], hv[i4 * 4 + 2], hv[i4 * 4 + 3]);
        float psum = 0.0f;
        #pragma unroll
        for (int i2 = 0; i2 < 32; i2++) {
            float v = hv[i2];
            v += __shfl_xor_sync(0xFFFFFFFFu, v, 16);
            v += __shfl_xor_sync(0xFFFFFFFFu, v, 8);
            v += __shfl_xor_sync(0xFFFFFFFFu, v, 4);
            v += __shfl_xor_sync(0xFFFFFFFFu, v, 2);
            v += __shfl_xor_sync(0xFFFFFFFFu, v, 1);
            if (lane == i2) psum = v;
        }
        atomicAdd(&pool[jb + lane], psum);
    }

    __syncthreads();
    if (tid < 2 * DN)
        g_pooled[(size_t)bn * 2 * DN + tid] = pool[tid] * (1.0f / CN);
    if (wid == 0) TC_DEALLOC(tmem, 512);

#else  // ---------------- SIMT fallback (plain compute_103 pass only) -------
    float* Hs  = (float*)(smem + OFF_AH);     // [256][128]
    if (tid < 2 * DN) pool[tid] = 0.0f;
    __syncthreads();

    // msg MLP
    for (int idx = tid; idx < CN * HM; idx += 512) {
        int c = idx >> 7, jj = idx & 127;
        float acc = mb1[g * HM + jj];
        const float* wr = w1m + (size_t)jj * F;
        for (int f = 0; f < DN; f++) acc = fmaf(wr[f],       base_h[(size_t)c * DN + f], acc);
        for (int f = 0; f < DN; f++) acc = fmaf(wr[64 + f],  base_a[(size_t)c * DN + f], acc);
        for (int f = 0; f < DN; f++) acc = fmaf(wr[128 + f], base_n[(size_t)c * DN + f], acc);
        Hs[idx] = gelu_f(acc);
    }
    __syncthreads();
    for (int idx = tid; idx < CN * DN; idx += 512) {
        int c = idx >> 6, j2 = idx & 63;
        float acc = mb2[g * DN + j2];
        const float* wr = w2m + (size_t)j2 * HM;
        const float* hr = Hs + (size_t)c * HM;
        for (int k = 0; k < HM; k++) acc = fmaf(wr[k], hr[k], acc);
        o_msg[((size_t)bn * CN + c) * DN + j2] = acc;
        atomicAdd(&pool[DN + j2], acc);
    }
    __syncthreads();
    // state MLP
    for (int idx = tid; idx < CN * HM; idx += 512) {
        int c = idx >> 7, jj = idx & 127;
        float acc = sb1[g * HM + jj];
        const float* wr = w1s + (size_t)jj * F;
        for (int f = 0; f < DN; f++) acc = fmaf(wr[f],       base_h[(size_t)c * DN + f], acc);
        for (int f = 0; f < DN; f++) acc = fmaf(wr[64 + f],  o_msg[((size_t)bn * CN + c) * DN + f], acc);
        for (int f = 0; f < DN; f++) acc = fmaf(wr[128 + f], base_c[f], acc);
        Hs[idx] = gelu_f(acc);
    }
    __syncthreads();
    for (int idx = tid; idx < CN * DN; idx += 512) {
        int c = idx >> 6, j2 = idx & 63;
        float acc = sb2[g * DN + j2];
        const float* wr = w2s + (size_t)j2 * HM;
        const float* hr = Hs + (size_t)c * HM;
        for (int k = 0; k < HM; k++) acc = fmaf(wr[k], hr[k], acc);
        acc += base_h[(size_t)c * DN + j2];
        o_h[((size_t)bn * CN + c) * DN + j2] = acc;
        atomicAdd(&pool[j2], acc);
    }
    __syncthreads();
    if (tid < 2 * DN)
        g_pooled[(size_t)bn * 2 * DN + tid] = pool[tid] * (1.0f / CN);
#endif
}

// ---------------------------------------------------------------------------
// Slim modulation MLP: reads pooled stats only.
// ---------------------------------------------------------------------------
__global__ __launch_bounds__(128) void mod_kernel(
    const float* __restrict__ mw1,
    const float* __restrict__ mb1,
    const float* __restrict__ mw2,
    const float* __restrict__ mb2,
    float*       __restrict__ mod)
{
    __shared__ float pooled[2 * DN];
    __shared__ float phh[HMOD];

    int bn  = blockIdx.x;
    int n   = bn & (NC - 1);
    int tid = threadIdx.x;

    if (tid < 2 * DN) pooled[tid] = g_pooled[(size_t)bn * 2 * DN + tid];
    __syncthreads();

    if (tid < HMOD) {
        const float* w = mw1 + (size_t)n * (2 * DN) * HMOD + tid;
        float acc = mb1[n * HMOD + tid];
        #pragma unroll 8
        for (int f = 0; f < 2 * DN; f++) acc = fmaf(pooled[f], w[f * HMOD], acc);
        phh[tid] = gelu_f(acc);
    }
    __syncthreads();

    if (tid < MOD_OUT) {
        const float* w = mw2 + (size_t)n * HMOD * MOD_OUT + tid;
        float acc = mb2[n * MOD_OUT + tid];
        #pragma unroll 8
        for (int k = 0; k < HMOD; k++) acc = fmaf(phh[k], w[k * MOD_OUT], acc);
        mod[bn * MOD_OUT + tid] = acc;
    }
}

// ---------------------------------------------------------------------------
// Launch
// ---------------------------------------------------------------------------
extern "C" void kernel_launch(void* const* d_in, const int* in_sizes, int n_in,
                              void* d_out, int out_size)
{
    const float* h      = (const float*)d_in[0];
    const float* w_conn = (const float*)d_in[1];
    const float* ctx    = (const float*)d_in[2];
    const float* nid    = (const float*)d_in[3];
    const float* mw1    = (const float*)d_in[4];
    const float* mb1    = (const float*)d_in[5];
    const float* mw2    = (const float*)d_in[6];
    const float* mb2    = (const float*)d_in[7];
    const float* sw1    = (const float*)d_in[8];
    const float* sb1    = (const float*)d_in[9];
    const float* sw2    = (const float*)d_in[10];
    const float* sb2    = (const float*)d_in[11];
    const float* modw1  = (const float*)d_in[12];
    const float* modb1  = (const float*)d_in[13];
    const float* modw2  = (const float*)d_in[14];
    const float* modb2  = (const float*)d_in[15];
    const int*   conn   = (const int*)d_in[16];
    const int*   c2g    = (const int*)d_in[17];

    float* out   = (float*)d_out;
    float* o_h   = out;
    float* o_msg = out + (size_t)Bb * NC * CN * DN;
    float* o_mod = o_msg + (size_t)Bb * NC * CN * DN;

    const int grid = Bb * NC;  // 512
    const size_t smA = (size_t)CN * DN * sizeof(float);   // 64 KB

    static bool attr_done = false;
    if (!attr_done) {
        cudaFuncSetAttribute(agg_kernel, cudaFuncAttributeMaxDynamicSharedMemorySize, (int)smA);
        cudaFuncSetAttribute(fused_mlp_kernel, cudaFuncAttributeMaxDynamicSharedMemorySize, SMEM_MLP);
        attr_done = true;
    }

    agg_kernel<<<grid, 256, smA>>>(h, w_conn, conn);
    fused_mlp_kernel<<<grid, 512, SMEM_MLP>>>(h, ctx, nid, mw1, mb1, mw2, mb2,
                                              sw1, sb1, sw2, sb2, c2g, o_msg, o_h);
    mod_kernel<<<grid, 128>>>(modw1, modb1, modw2, modb2, o_mod);
}

// round 10
// speedup vs baseline: 2.5770x; 1.0491x over previous
#include <cuda_runtime.h>
#include <cstdint>

typedef unsigned long long u64;

// Problem constants
constexpr int Bb  = 2;
constexpr int NC  = 256;
constexpr int CN  = 256;
constexpr int K   = 16;
constexpr int DN  = 64;
constexpr int HM  = 128;
constexpr int F   = 192;
constexpr int HMOD = 64;
constexpr int MOD_OUT = 5;

// Scratch
__device__ float g_agg[(size_t)Bb * NC * CN * DN];
__device__ float g_pooled[(size_t)Bb * NC * 2 * DN];   // [bn][h_mean|msg_mean]

// ---------------- SMEM layout (bytes) --------------------------------------
constexpr int OFF_TMEM  = 0;
constexpr int OFF_MBARA = 8;
constexpr int OFF_MBARB = 16;
constexpr int OFF_MBARC = 24;
constexpr int OFF_B1M   = 32;     // 128 f
constexpr int OFF_B2M   = 544;    // 64 f
constexpr int OFF_B1SS  = 800;    // 128 f
constexpr int OFF_B2SS  = 1312;   // 64 f
constexpr int OFF_POOL  = 1568;   // 128 f
constexpr int OFF_AH    = 3072;            // 32KB
constexpr int OFF_AL    = 3072 + 32768;    // 32KB
constexpr int OFF_BH    = 3072 + 65536;    // 64KB
constexpr int OFF_BL    = 3072 + 131072;   // 64KB
constexpr int SMEM_MLP  = 3072 + 196608;   // 199680 B

#if defined(__CUDA_ARCH_FEAT_SM103_ALL) || defined(__CUDA_ARCH_FEAT_SM100_ALL) || defined(__CUDA_ARCH_FEAT_SM101_ALL)
#define HAS_TCGEN05 1
#else
#define HAS_TCGEN05 0
#endif

__device__ __forceinline__ uint32_t smem_u32(const void* p) {
    uint32_t a;
    asm("{ .reg .u64 t; cvta.to.shared.u64 t, %1; cvt.u32.u64 %0, t; }"
        : "=r"(a) : "l"(p));
    return a;
}

#if HAS_TCGEN05
__device__ __forceinline__ uint32_t elect1() {
    uint32_t p;
    asm volatile("{ .reg .pred p; elect.sync _|p, 0xFFFFFFFF; selp.b32 %0, 1, 0, p; }"
                 : "=r"(p));
    return p;
}

#define TC_ALLOC(smem_addr, n) \
    asm volatile("tcgen05.alloc.cta_group::1.sync.aligned.shared::cta.b32 [%0], %1;" \
                 :: "r"((uint32_t)(smem_addr)), "r"((uint32_t)(n)) : "memory")
#define TC_RELINQ() \
    asm volatile("tcgen05.relinquish_alloc_permit.cta_group::1.sync.aligned;")
#define TC_DEALLOC(tmem, n) \
    asm volatile("tcgen05.dealloc.cta_group::1.sync.aligned.b32 %0, %1;" \
                 :: "r"(tmem), "r"((uint32_t)(n)))
#define TC_COMMIT(mbar) \
    asm volatile("tcgen05.commit.cta_group::1.mbarrier::arrive::one.shared::cluster.b64 [%0];" \
                 :: "r"((uint32_t)(mbar)) : "memory")
#define TC_FENCE_AFTER()  asm volatile("tcgen05.fence::after_thread_sync;" ::: "memory")
#define TC_WAIT_LD()      asm volatile("tcgen05.wait::ld.sync.aligned;" ::: "memory")

#define LDTM_X32(r, addr) \
    asm volatile( \
        "tcgen05.ld.sync.aligned.32x32b.x32.b32 " \
        "{%0, %1, %2, %3, %4, %5, %6, %7, " \
        " %8, %9, %10, %11, %12, %13, %14, %15, " \
        " %16, %17, %18, %19, %20, %21, %22, %23, " \
        " %24, %25, %26, %27, %28, %29, %30, %31}, [%32];" \
        : "=r"((r)[0]),  "=r"((r)[1]),  "=r"((r)[2]),  "=r"((r)[3]), \
          "=r"((r)[4]),  "=r"((r)[5]),  "=r"((r)[6]),  "=r"((r)[7]), \
          "=r"((r)[8]),  "=r"((r)[9]),  "=r"((r)[10]), "=r"((r)[11]), \
          "=r"((r)[12]), "=r"((r)[13]), "=r"((r)[14]), "=r"((r)[15]), \
          "=r"((r)[16]), "=r"((r)[17]), "=r"((r)[18]), "=r"((r)[19]), \
          "=r"((r)[20]), "=r"((r)[21]), "=r"((r)[22]), "=r"((r)[23]), \
          "=r"((r)[24]), "=r"((r)[25]), "=r"((r)[26]), "=r"((r)[27]), \
          "=r"((r)[28]), "=r"((r)[29]), "=r"((r)[30]), "=r"((r)[31]) \
        : "r"(addr))

__device__ __forceinline__ void mma_tf32_ss(uint32_t d_tmem, u64 a_desc, u64 b_desc,
                                            uint32_t idesc, uint32_t enable) {
    asm volatile(
        "{\n\t"
        ".reg .pred p;\n\t"
        "setp.ne.u32 p, %4, 0;\n\t"
        "tcgen05.mma.cta_group::1.kind::tf32 [%0], %1, %2, %3, {%5, %5, %5, %5}, p;\n\t"
        "}"
        :: "r"(d_tmem), "l"(a_desc), "l"(b_desc), "r"(idesc), "r"(enable), "r"(0u)
        : "memory");
}
#endif  // HAS_TCGEN05

#define MBAR_INIT(mbar, cnt) \
    asm volatile("mbarrier.init.shared.b64 [%0], %1;" \
                 :: "r"((uint32_t)(mbar)), "r"((uint32_t)(cnt)) : "memory")

#define MBAR_WAIT(mbar, parity) do {                                           \
    uint32_t _m = (uint32_t)(mbar), _p = (uint32_t)(parity), _d;               \
    asm volatile("{ .reg .pred p;"                                             \
        " mbarrier.try_wait.parity.acquire.cta.shared::cta.b64 p, [%1], %2;"   \
        " selp.b32 %0, 1, 0, p; }" : "=r"(_d) : "r"(_m), "r"(_p) : "memory");  \
    while (!_d) {                                                              \
        asm volatile("{ .reg .pred p;"                                         \
            " mbarrier.try_wait.parity.acquire.cta.shared::cta.b64 p, [%1], %2, 0x989680;" \
            " selp.b32 %0, 1, 0, p; }" : "=r"(_d) : "r"(_m), "r"(_p) : "memory"); \
    }                                                                          \
} while (0)

constexpr u64 DESC_BASE = (2ull << 61) | (1ull << 46) | (64ull << 32) | (1ull << 16);
__device__ __forceinline__ u64 mk_desc(uint32_t addr) {
    return DESC_BASE | ((u64)(addr >> 4) & 0x3FFF);
}

// Blocked-atom + SW128 byte offset. atom = 8 rows x 32 tf32 (128B).
__device__ __forceinline__ uint32_t tile_off(int row, int k, int atom_rows) {
    uint32_t o = ((uint32_t)((k >> 5) * atom_rows + (row >> 3)) << 10)
               + ((uint32_t)(row & 7) << 7) + ((uint32_t)(k & 31) << 2);
    return o ^ ((o >> 3) & 0x70);
}

__device__ __forceinline__ float to_tf32(float x) {
    float r;
    asm("cvt.rna.tf32.f32 %0, %1;" : "=f"(r) : "f"(x));
    return r;
}

__device__ __forceinline__ void split_sts(char* smem, uint32_t off_hi, uint32_t lo_delta,
                                          float4 v) {
    float4 hv, lv;
    hv.x = to_tf32(v.x); hv.y = to_tf32(v.y); hv.z = to_tf32(v.z); hv.w = to_tf32(v.w);
    lv.x = v.x - hv.x;   lv.y = v.y - hv.y;   lv.z = v.z - hv.z;   lv.w = v.w - hv.w;
    *reinterpret_cast<float4*>(smem + off_hi)            = hv;
    *reinterpret_cast<float4*>(smem + off_hi + lo_delta) = lv;
}

__device__ __forceinline__ float gelu_f(float x) {
    float x3 = x * x * x;
    return 0.5f * x * (1.0f + tanhf(0.7978845608028654f * (x + 0.044715f * x3)));
}

__device__ __forceinline__ float gelu_fast(float x) {
    float z = x + 0.044715f * x * x * x;
    float a = 2.3022081852f * z;
    float e;
    asm("ex2.approx.f32 %0, %1;" : "=f"(e) : "f"(a));
    float r;
    asm("rcp.approx.f32 %0, %1;" : "=f"(r) : "f"(e + 1.0f));
    return x - x * r;
}

constexpr uint32_t ID_TC = (1u << 4) | (2u << 7) | (2u << 10) | (8u << 17) | (8u << 24);

// ---------------------------------------------------------------------------
// Kernel 1: connection-weighted aggregation.
// Warp-per-neuron: idx/w are warp-uniform (broadcast), lanes own d=lane*2.
// Gather = LDS.64 of consecutive float2 -> conflict-free (2 wavefronts).
// ---------------------------------------------------------------------------
__global__ __launch_bounds__(256) void agg_kernel(
    const float* __restrict__ h,
    const float* __restrict__ w_conn,
    const int*   __restrict__ conn)
{
    extern __shared__ float smf[];   // h tile [256][64]

    int bn   = blockIdx.x;
    int n    = bn & (NC - 1);
    int tid  = threadIdx.x;
    int wid  = tid >> 5;
    int lane = tid & 31;

    const float4* hg = reinterpret_cast<const float4*>(h) + (size_t)bn * CN * DN / 4;
    float4* h_sm4 = reinterpret_cast<float4*>(smf);
    for (int i = tid; i < CN * DN / 4; i += 256) h_sm4[i] = hg[i];
    __syncthreads();

    // 8 warps x 16 iterations x 2 c each = 256 c
    #pragma unroll 4
    for (int it = 0; it < 16; it++) {
        int c0 = wid * 32 + it * 2;        // two consecutive c per iteration
        const int*   ci0 = conn   + ((size_t)n  * CN + c0) * K;
        const float* wc0 = w_conn + ((size_t)bn * CN + c0) * K;

        float2 acc0 = {0.0f, 0.0f}, acc1 = {0.0f, 0.0f};
        const float* hl = smf + lane * 2;
        #pragma unroll
        for (int k = 0; k < K; k++) {
            int   i0 = ci0[k];
            int   i1 = ci0[K + k];
            float w0 = wc0[k];
            float w1 = wc0[K + k];
            float2 v0 = *reinterpret_cast<const float2*>(hl + (size_t)i0 * DN);
            float2 v1 = *reinterpret_cast<const float2*>(hl + (size_t)i1 * DN);
            acc0.x = fmaf(w0, v0.x, acc0.x);
            acc0.y = fmaf(w0, v0.y, acc0.y);
            acc1.x = fmaf(w1, v1.x, acc1.x);
            acc1.y = fmaf(w1, v1.y, acc1.y);
        }
        float* out = g_agg + ((size_t)bn * CN + c0) * DN + lane * 2;
        *reinterpret_cast<float2*>(out)      = acc0;
        *reinterpret_cast<float2*>(out + DN) = acc1;
    }
}

#if HAS_TCGEN05
// GEMM2 phase: hidden = gelu(D1 + b1) staged hi/lo into B buffers; two N=64
// column chunks of D2 at tmem+256 / tmem+320. On return all warps have passed
// MBARC (A and B buffers free, D2 complete).
__device__ __forceinline__ void gemm2_phase(
    char* smem, uint32_t sbase, uint32_t tmem,
    int wid, int lane, int sub, int cgrp, float bj1, uint32_t parity)
{
    int j = sub * 32 + lane;
    // epilogue ch0
    {
        uint32_t r0[32];
        LDTM_X32(r0, tmem + cgrp * 32);
        TC_WAIT_LD();
        #pragma unroll
        for (int i2 = 0; i2 < 32; i2++) {
            float v = gelu_fast(__uint_as_float(r0[i2]) + bj1);
            float hv = to_tf32(v), lv = v - hv;
            uint32_t off = tile_off(cgrp * 32 + i2, j, 16);
            *reinterpret_cast<float*>(smem + OFF_BH + off) = hv;
            *reinterpret_cast<float*>(smem + OFF_BL + off) = lv;
        }
    }
    asm volatile("fence.proxy.async.shared::cta;" ::: "memory");
    __syncthreads();

    if (wid == 0) {
        u64 dah = mk_desc(sbase + OFF_BH), dal = mk_desc(sbase + OFF_BL);
        u64 dbh = mk_desc(sbase + OFF_AH), dbl = mk_desc(sbase + OFF_AL);
        if (elect1()) {
            #pragma unroll
            for (int pass = 0; pass < 3; pass++) {
                u64 da = (pass == 2) ? dal : dah;
                u64 db = (pass == 1) ? dbl : dbh;
                #pragma unroll
                for (int s = 0; s < 16; s++) {
                    u64 oa = (u64)((s >> 2) * 1024 + (s & 3) * 2);
                    u64 ob = (u64)((s >> 2) * 512  + (s & 3) * 2);
                    mma_tf32_ss(tmem + 256, da + oa, db + ob, ID_TC, (pass | s) ? 1u : 0u);
                }
            }
            TC_COMMIT(sbase + OFF_MBARB);
        }
    }

    // epilogue ch1 (overlaps ch0 MMA)
    float fv[32];
    {
        uint32_t r1[32];
        LDTM_X32(r1, tmem + 128 + cgrp * 32);
        TC_WAIT_LD();
        #pragma unroll
        for (int i2 = 0; i2 < 32; i2++)
            fv[i2] = gelu_fast(__uint_as_float(r1[i2]) + bj1);
    }
    MBAR_WAIT(sbase + OFF_MBARB, parity);
    TC_FENCE_AFTER();
    #pragma unroll
    for (int i2 = 0; i2 < 32; i2++) {
        float hv = to_tf32(fv[i2]), lv = fv[i2] - hv;
        uint32_t off = tile_off(cgrp * 32 + i2, j, 16);
        *reinterpret_cast<float*>(smem + OFF_BH + off) = hv;
        *reinterpret_cast<float*>(smem + OFF_BL + off) = lv;
    }
    asm volatile("fence.proxy.async.shared::cta;" ::: "memory");
    __syncthreads();

    if (wid == 0) {
        u64 dah = mk_desc(sbase + OFF_BH), dal = mk_desc(sbase + OFF_BL);
        u64 dbh = mk_desc(sbase + OFF_AH), dbl = mk_desc(sbase + OFF_AL);
        if (elect1()) {
            #pragma unroll
            for (int pass = 0; pass < 3; pass++) {
                u64 da = (pass == 2) ? dal : dah;
                u64 db = (pass == 1) ? dbl : dbh;
                #pragma unroll
                for (int s = 0; s < 16; s++) {
                    u64 oa = (u64)((s >> 2) * 1024 + (s & 3) * 2);
                    u64 ob = (u64)((s >> 2) * 512  + (s & 3) * 2);
                    mma_tf32_ss(tmem + 320, da + oa, db + ob, ID_TC, (pass | s) ? 1u : 0u);
                }
            }
            TC_COMMIT(sbase + OFF_MBARC);
        }
    }
    MBAR_WAIT(sbase + OFF_MBARC, parity);
    TC_FENCE_AFTER();
}

// GEMM1 MMA issue for one K=64 tile: D1[j=128][c=256] over 4 N=64 chunks.
// When `first` is set, EVERY q-chunk's first (pass=0,s=0) MMA has enable_d=0.
__device__ __forceinline__ void gemm1_mma(uint32_t sbase, uint32_t tmem, bool first) {
    u64 dah = mk_desc(sbase + OFF_AH), dal = mk_desc(sbase + OFF_AL);
    u64 dbh = mk_desc(sbase + OFF_BH), dbl = mk_desc(sbase + OFF_BL);
    if (elect1()) {
        #pragma unroll
        for (int pass = 0; pass < 3; pass++) {
            u64 da = (pass == 2) ? dal : dah;
            u64 db = (pass == 1) ? dbl : dbh;
            #pragma unroll
            for (int q = 0; q < 4; q++) {
                #pragma unroll
                for (int s = 0; s < 8; s++) {
                    u64 oa = (u64)((s >> 2) * 1024 + (s & 3) * 2);
                    u64 ob = (u64)((s >> 2) * 2048 + (s & 3) * 2 + q * 512);
                    mma_tf32_ss(tmem + q * 64, da + oa, db + ob, ID_TC,
                                (first && pass == 0 && s == 0) ? 0u : 1u);
                }
            }
        }
        TC_COMMIT(sbase + OFF_MBARA);
    }
}
#endif  // HAS_TCGEN05

// ---------------------------------------------------------------------------
// Fully fused per-(b,n) kernel: msg MLP -> state MLP (+residual) + pooled stats.
// ---------------------------------------------------------------------------
__global__ __launch_bounds__(512, 1)
void fused_mlp_kernel(
    const float* __restrict__ h,
    const float* __restrict__ ctx,
    const float* __restrict__ nid,
    const float* __restrict__ mw1, const float* __restrict__ mb1,
    const float* __restrict__ mw2, const float* __restrict__ mb2,
    const float* __restrict__ sw1, const float* __restrict__ sb1,
    const float* __restrict__ sw2, const float* __restrict__ sb2,
    const int*   __restrict__ c2g,
    float*       __restrict__ o_msg,
    float*       __restrict__ o_h)
{
    extern __shared__ char smem[];
    uint32_t sbase = smem_u32(smem);

    int tid  = threadIdx.x;
    int wid  = tid >> 5;
    int lane = tid & 31;
    int bn   = blockIdx.x;
    int n    = bn & (NC - 1);
    int g    = c2g[n];

    const float* w1m    = mw1 + (size_t)g * HM * F;
    const float* w2m    = mw2 + (size_t)g * DN * HM;
    const float* w1s    = sw1 + (size_t)g * HM * F;
    const float* w2s    = sw2 + (size_t)g * DN * HM;
    const float* base_h = h + (size_t)bn * CN * DN;
    const float* base_a = g_agg + (size_t)bn * CN * DN;
    const float* base_n = nid + (size_t)n * CN * DN;
    const float* base_c = ctx + (size_t)bn * DN;
    float* pool = (float*)(smem + OFF_POOL);

#if HAS_TCGEN05
    if (wid == 0) {
        TC_ALLOC(sbase + OFF_TMEM, 512);
        TC_RELINQ();
    }
    if (tid == 0) {
        MBAR_INIT(sbase + OFF_MBARA, 1);
        MBAR_INIT(sbase + OFF_MBARB, 1);
        MBAR_INIT(sbase + OFF_MBARC, 1);
    }
    if (tid < HM) {
        ((float*)(smem + OFF_B1M))[tid]  = mb1[g * HM + tid];
        ((float*)(smem + OFF_B1SS))[tid] = sb1[g * HM + tid];
    }
    if (tid < DN) {
        ((float*)(smem + OFF_B2M))[tid]  = mb2[g * DN + tid];
        ((float*)(smem + OFF_B2SS))[tid] = sb2[g * DN + tid];
    }
    if (tid < 2 * DN) pool[tid] = 0.0f;
    __syncthreads();

    uint32_t tmem;
    asm("ld.shared.b32 %0, [%1];" : "=r"(tmem) : "r"(sbase + OFF_TMEM));

    uint32_t ph = 0;
    int sub  = wid & 3;
    int cgrp = wid >> 2;
    int j    = sub * 32 + lane;

    float4 va[4], vb[8], vw[4];
    // prefetch msg tile 0: W1m cols 0:64 + h
    #pragma unroll
    for (int p = 0; p < 4; p++) {
        int i = p * 512 + tid; int r = i >> 4, k4 = i & 15;
        va[p] = *reinterpret_cast<const float4*>(w1m + (size_t)r * F + k4 * 4);
    }
    #pragma unroll
    for (int p = 0; p < 8; p++) {
        int i = p * 512 + tid; int r = i >> 4, k4 = i & 15;
        vb[p] = *reinterpret_cast<const float4*>(base_h + (size_t)r * DN + k4 * 4);
    }

    // ===================== MSG GEMM1 =====================
    for (int t = 0; t < 3; t++) {
        if (t > 0) { MBAR_WAIT(sbase + OFF_MBARA, ph); ph ^= 1; TC_FENCE_AFTER(); }
        #pragma unroll
        for (int p = 0; p < 4; p++) {
            int i = p * 512 + tid; int r = i >> 4, k4 = i & 15;
            split_sts(smem, OFF_AH + tile_off(r, k4 * 4, 16), 32768, va[p]);
        }
        #pragma unroll
        for (int p = 0; p < 8; p++) {
            int i = p * 512 + tid; int r = i >> 4, k4 = i & 15;
            split_sts(smem, OFF_BH + tile_off(r, k4 * 4, 32), 65536, vb[p]);
        }
        asm volatile("fence.proxy.async.shared::cta;" ::: "memory");
        __syncthreads();
        if (wid == 0) gemm1_mma(sbase, tmem, t == 0);

        if (t < 2) {
            int tn = t + 1;
            #pragma unroll
            for (int p = 0; p < 4; p++) {
                int i = p * 512 + tid; int r = i >> 4, k4 = i & 15;
                va[p] = *reinterpret_cast<const float4*>(w1m + (size_t)r * F + tn * 64 + k4 * 4);
            }
            #pragma unroll
            for (int p = 0; p < 8; p++) {
                int i = p * 512 + tid; int r = i >> 4, k4 = i & 15;
                const float* src = (tn == 1) ? base_a : base_n;
                vb[p] = *reinterpret_cast<const float4*>(src + (size_t)r * DN + k4 * 4);
            }
        } else {
            #pragma unroll
            for (int p = 0; p < 4; p++) {
                int i = p * 512 + tid; int r = i >> 5, k4 = i & 31;
                vw[p] = *reinterpret_cast<const float4*>(w2m + (size_t)r * HM + k4 * 4);
            }
        }
    }
    MBAR_WAIT(sbase + OFF_MBARA, ph); ph ^= 1;
    TC_FENCE_AFTER();

    // ===================== MSG GEMM2 =====================
    // stage W2m into A buffers
    #pragma unroll
    for (int p = 0; p < 4; p++) {
        int i = p * 512 + tid; int r = i >> 5, k4 = i & 31;
        split_sts(smem, OFF_AH + tile_off(r, k4 * 4, 8), 32768, vw[p]);
    }
    // prefetch state t0 A-chunk: W1s cols 64:128 (the msg part of state feat)
    #pragma unroll
    for (int p = 0; p < 4; p++) {
        int i = p * 512 + tid; int r = i >> 4, k4 = i & 15;
        va[p] = *reinterpret_cast<const float4*>(w1s + (size_t)r * F + 64 + k4 * 4);
    }
    float bj1m = ((float*)(smem + OFF_B1M))[j];
    gemm2_phase(smem, sbase, tmem, wid, lane, sub, cgrp, bj1m, 0);

    // ---- msg epilogue: D2 -> o_msg, pooled, and state feat tile in B ----
    {
        int ch  = cgrp >> 1;
        int jh2 = cgrp & 1;
        uint32_t r[32];
        LDTM_X32(r, tmem + 256 + ch * 64 + jh2 * 32);
        TC_WAIT_LD();
        int c  = ch * 128 + sub * 32 + lane;
        int jb = jh2 * 32;
        const float* b2s = (float*)(smem + OFF_B2M);
        float mv[32];
        #pragma unroll
        for (int i2 = 0; i2 < 32; i2++)
            mv[i2] = __uint_as_float(r[i2]) + b2s[jb + i2];
        // STG msg
        float* op = o_msg + ((size_t)bn * CN + c) * DN + jb;
        #pragma unroll
        for (int i4 = 0; i4 < 8; i4++)
            *reinterpret_cast<float4*>(op + i4 * 4) =
                make_float4(mv[i4 * 4], mv[i4 * 4 + 1], mv[i4 * 4 + 2], mv[i4 * 4 + 3]);
        // stage as state feat tile row=c, k=jb+i2 (B tile [256 x 64], atoms=32)
        #pragma unroll
        for (int i2 = 0; i2 < 32; i2++) {
            float hv = to_tf32(mv[i2]), lv = mv[i2] - hv;
            uint32_t off = tile_off(c, jb + i2, 32);
            *reinterpret_cast<float*>(smem + OFF_BH + off) = hv;
            *reinterpret_cast<float*>(smem + OFF_BL + off) = lv;
        }
        // pooled msg mean: butterfly over lanes (c), pick reg == lane
        float psum = 0.0f;
        #pragma unroll
        for (int i2 = 0; i2 < 32; i2++) {
            float v = mv[i2];
            v += __shfl_xor_sync(0xFFFFFFFFu, v, 16);
            v += __shfl_xor_sync(0xFFFFFFFFu, v, 8);
            v += __shfl_xor_sync(0xFFFFFFFFu, v, 4);
            v += __shfl_xor_sync(0xFFFFFFFFu, v, 2);
            v += __shfl_xor_sync(0xFFFFFFFFu, v, 1);
            if (lane == i2) psum = v;
        }
        atomicAdd(&pool[DN + jb + lane], psum);
    }
    asm volatile("fence.proxy.async.shared::cta;" ::: "memory");
    __syncthreads();

    // ===================== STATE GEMM1 =====================
    // t=0: B = msg tile (already staged), A = W1s cols 64:128 (in va)
    #pragma unroll
    for (int p = 0; p < 4; p++) {
        int i = p * 512 + tid; int r = i >> 4, k4 = i & 15;
        split_sts(smem, OFF_AH + tile_off(r, k4 * 4, 16), 32768, va[p]);
    }
    asm volatile("fence.proxy.async.shared::cta;" ::: "memory");
    __syncthreads();
    if (wid == 0) gemm1_mma(sbase, tmem, true);
    // prefetch t1: W1s cols 0:64 + h
    #pragma unroll
    for (int p = 0; p < 4; p++) {
        int i = p * 512 + tid; int r = i >> 4, k4 = i & 15;
        va[p] = *reinterpret_cast<const float4*>(w1s + (size_t)r * F + k4 * 4);
    }
    #pragma unroll
    for (int p = 0; p < 8; p++) {
        int i = p * 512 + tid; int r = i >> 4, k4 = i & 15;
        vb[p] = *reinterpret_cast<const float4*>(base_h + (size_t)r * DN + k4 * 4);
    }
    for (int t = 1; t < 3; t++) {
        MBAR_WAIT(sbase + OFF_MBARA, ph); ph ^= 1; TC_FENCE_AFTER();
        #pragma unroll
        for (int p = 0; p < 4; p++) {
            int i = p * 512 + tid; int r = i >> 4, k4 = i & 15;
            split_sts(smem, OFF_AH + tile_off(r, k4 * 4, 16), 32768, va[p]);
        }
        #pragma unroll
        for (int p = 0; p < 8; p++) {
            int i = p * 512 + tid; int r = i >> 4, k4 = i & 15;
            split_sts(smem, OFF_BH + tile_off(r, k4 * 4, 32), 65536, vb[p]);
        }
        asm volatile("fence.proxy.async.shared::cta;" ::: "memory");
        __syncthreads();
        if (wid == 0) gemm1_mma(sbase, tmem, false);

        if (t == 1) {
            #pragma unroll
            for (int p = 0; p < 4; p++) {
                int i = p * 512 + tid; int r = i >> 4, k4 = i & 15;
                va[p] = *reinterpret_cast<const float4*>(w1s + (size_t)r * F + 128 + k4 * 4);
            }
            #pragma unroll
            for (int p = 0; p < 8; p++) {
                int i = p * 512 + tid; int k4 = i & 15;
                vb[p] = *reinterpret_cast<const float4*>(base_c + k4 * 4);   // ctx bcast
            }
        } else {
            #pragma unroll
            for (int p = 0; p < 4; p++) {
                int i = p * 512 + tid; int r = i >> 5, k4 = i & 31;
                vw[p] = *reinterpret_cast<const float4*>(w2s + (size_t)r * HM + k4 * 4);
            }
        }
    }
    MBAR_WAIT(sbase + OFF_MBARA, ph); ph ^= 1;
    TC_FENCE_AFTER();

    // ===================== STATE GEMM2 =====================
    #pragma unroll
    for (int p = 0; p < 4; p++) {
        int i = p * 512 + tid; int r = i >> 5, k4 = i & 31;
        split_sts(smem, OFF_AH + tile_off(r, k4 * 4, 8), 32768, vw[p]);
    }
    float bj1s = ((float*)(smem + OFF_B1SS))[j];
    gemm2_phase(smem, sbase, tmem, wid, lane, sub, cgrp, bj1s, 1);

    // ---- state epilogue: D2 + b2s + h residual -> o_h, pooled ----
    {
        int ch  = cgrp >> 1;
        int jh2 = cgrp & 1;
        uint32_t r[32];
        LDTM_X32(r, tmem + 256 + ch * 64 + jh2 * 32);
        TC_WAIT_LD();
        int c  = ch * 128 + sub * 32 + lane;
        int jb = jh2 * 32;
        const float* b2s = (float*)(smem + OFF_B2SS);
        const float* hp = base_h + (size_t)c * DN + jb;
        float hv[32];
        #pragma unroll
        for (int i4 = 0; i4 < 8; i4++) {
            float4 hr = *reinterpret_cast<const float4*>(hp + i4 * 4);
            hv[i4 * 4 + 0] = __uint_as_float(r[i4 * 4 + 0]) + b2s[jb + i4 * 4 + 0] + hr.x;
            hv[i4 * 4 + 1] = __uint_as_float(r[i4 * 4 + 1]) + b2s[jb + i4 * 4 + 1] + hr.y;
            hv[i4 * 4 + 2] = __uint_as_float(r[i4 * 4 + 2]) + b2s[jb + i4 * 4 + 2] + hr.z;
            hv[i4 * 4 + 3] = __uint_as_float(r[i4 * 4 + 3]) + b2s[jb + i4 * 4 + 3] + hr.w;
        }
        float* op = o_h + ((size_t)bn * CN + c) * DN + jb;
        #pragma unroll
        for (int i4 = 0; i4 < 8; i4++)
            *reinterpret_cast<float4*>(op + i4 * 4) =
                make_float4(hv[i4 * 4], hv[i4 * 4 + 1], hv[i4 * 4 + 2], hv[i4 * 4 + 3]);
        float psum = 0.0f;
        #pragma unroll
        for (int i2 = 0; i2 < 32; i2++) {
            float v = hv[i2];
            v += __shfl_xor_sync(0xFFFFFFFFu, v, 16);
            v += __shfl_xor_sync(0xFFFFFFFFu, v, 8);
            v += __shfl_xor_sync(0xFFFFFFFFu, v, 4);
            v += __shfl_xor_sync(0xFFFFFFFFu, v, 2);
            v += __shfl_xor_sync(0xFFFFFFFFu, v, 1);
            if (lane == i2) psum = v;
        }
        atomicAdd(&pool[jb + lane], psum);
    }

    __syncthreads();
    if (tid < 2 * DN)
        g_pooled[(size_t)bn * 2 * DN + tid] = pool[tid] * (1.0f / CN);
    if (wid == 0) TC_DEALLOC(tmem, 512);

#else  // ---------------- SIMT fallback (plain compute_103 pass only) -------
    float* Hs  = (float*)(smem + OFF_AH);     // [256][128]
    if (tid < 2 * DN) pool[tid] = 0.0f;
    __syncthreads();

    // msg MLP
    for (int idx = tid; idx < CN * HM; idx += 512) {
        int c = idx >> 7, jj = idx & 127;
        float acc = mb1[g * HM + jj];
        const float* wr = w1m + (size_t)jj * F;
        for (int f = 0; f < DN; f++) acc = fmaf(wr[f],       base_h[(size_t)c * DN + f], acc);
        for (int f = 0; f < DN; f++) acc = fmaf(wr[64 + f],  base_a[(size_t)c * DN + f], acc);
        for (int f = 0; f < DN; f++) acc = fmaf(wr[128 + f], base_n[(size_t)c * DN + f], acc);
        Hs[idx] = gelu_f(acc);
    }
    __syncthreads();
    for (int idx = tid; idx < CN * DN; idx += 512) {
        int c = idx >> 6, j2 = idx & 63;
        float acc = mb2[g * DN + j2];
        const float* wr = w2m + (size_t)j2 * HM;
        const float* hr = Hs + (size_t)c * HM;
        for (int k = 0; k < HM; k++) acc = fmaf(wr[k], hr[k], acc);
        o_msg[((size_t)bn * CN + c) * DN + j2] = acc;
        atomicAdd(&pool[DN + j2], acc);
    }
    __syncthreads();
    // state MLP
    for (int idx = tid; idx < CN * HM; idx += 512) {
        int c = idx >> 7, jj = idx & 127;
        float acc = sb1[g * HM + jj];
        const float* wr = w1s + (size_t)jj * F;
        for (int f = 0; f < DN; f++) acc = fmaf(wr[f],       base_h[(size_t)c * DN + f], acc);
        for (int f = 0; f < DN; f++) acc = fmaf(wr[64 + f],  o_msg[((size_t)bn * CN + c) * DN + f], acc);
        for (int f = 0; f < DN; f++) acc = fmaf(wr[128 + f], base_c[f], acc);
        Hs[idx] = gelu_f(acc);
    }
    __syncthreads();
    for (int idx = tid; idx < CN * DN; idx += 512) {
        int c = idx >> 6, j2 = idx & 63;
        float acc = sb2[g * DN + j2];
        const float* wr = w2s + (size_t)j2 * HM;
        const float* hr = Hs + (size_t)c * HM;
        for (int k = 0; k < HM; k++) acc = fmaf(wr[k], hr[k], acc);
        acc += base_h[(size_t)c * DN + j2];
        o_h[((size_t)bn * CN + c) * DN + j2] = acc;
        atomicAdd(&pool[j2], acc);
    }
    __syncthreads();
    if (tid < 2 * DN)
        g_pooled[(size_t)bn * 2 * DN + tid] = pool[tid] * (1.0f / CN);
#endif
}

// ---------------------------------------------------------------------------
// Slim modulation MLP: reads pooled stats only.
// ---------------------------------------------------------------------------
__global__ __launch_bounds__(128) void mod_kernel(
    const float* __restrict__ mw1,
    const float* __restrict__ mb1,
    const float* __restrict__ mw2,
    const float* __restrict__ mb2,
    float*       __restrict__ mod)
{
    __shared__ float pooled[2 * DN];
    __shared__ float phh[HMOD];

    int bn  = blockIdx.x;
    int n   = bn & (NC - 1);
    int tid = threadIdx.x;

    if (tid < 2 * DN) pooled[tid] = g_pooled[(size_t)bn * 2 * DN + tid];
    __syncthreads();

    if (tid < HMOD) {
        const float* w = mw1 + (size_t)n * (2 * DN) * HMOD + tid;
        float acc = mb1[n * HMOD + tid];
        #pragma unroll 8
        for (int f = 0; f < 2 * DN; f++) acc = fmaf(pooled[f], w[f * HMOD], acc);
        phh[tid] = gelu_f(acc);
    }
    __syncthreads();

    if (tid < MOD_OUT) {
        const float* w = mw2 + (size_t)n * HMOD * MOD_OUT + tid;
        float acc = mb2[n * MOD_OUT + tid];
        #pragma unroll 8
        for (int k = 0; k < HMOD; k++) acc = fmaf(phh[k], w[k * MOD_OUT], acc);
        mod[bn * MOD_OUT + tid] = acc;
    }
}

// ---------------------------------------------------------------------------
// Launch
// ---------------------------------------------------------------------------
extern "C" void kernel_launch(void* const* d_in, const int* in_sizes, int n_in,
                              void* d_out, int out_size)
{
    const float* h      = (const float*)d_in[0];
    const float* w_conn = (const float*)d_in[1];
    const float* ctx    = (const float*)d_in[2];
    const float* nid    = (const float*)d_in[3];
    const float* mw1    = (const float*)d_in[4];
    const float* mb1    = (const float*)d_in[5];
    const float* mw2    = (const float*)d_in[6];
    const float* mb2    = (const float*)d_in[7];
    const float* sw1    = (const float*)d_in[8];
    const float* sb1    = (const float*)d_in[9];
    const float* sw2    = (const float*)d_in[10];
    const float* sb2    = (const float*)d_in[11];
    const float* modw1  = (const float*)d_in[12];
    const float* modb1  = (const float*)d_in[13];
    const float* modw2  = (const float*)d_in[14];
    const float* modb2  = (const float*)d_in[15];
    const int*   conn   = (const int*)d_in[16];
    const int*   c2g    = (const int*)d_in[17];

    float* out   = (float*)d_out;
    float* o_h   = out;
    float* o_msg = out + (size_t)Bb * NC * CN * DN;
    float* o_mod = o_msg + (size_t)Bb * NC * CN * DN;

    const int grid = Bb * NC;  // 512
    const size_t smA = (size_t)CN * DN * sizeof(float);   // 64 KB

    static bool attr_done = false;
    if (!attr_done) {
        cudaFuncSetAttribute(agg_kernel, cudaFuncAttributeMaxDynamicSharedMemorySize, (int)smA);
        cudaFuncSetAttribute(fused_mlp_kernel, cudaFuncAttributeMaxDynamicSharedMemorySize, SMEM_MLP);
        attr_done = true;
    }

    agg_kernel<<<grid, 256, smA>>>(h, w_conn, conn);
    fused_mlp_kernel<<<grid, 512, SMEM_MLP>>>(h, ctx, nid, mw1, mb1, mw2, mb2,
                                              sw1, sb1, sw2, sb2, c2g, o_msg, o_h);
    mod_kernel<<<grid, 128>>>(modw1, modb1, modw2, modb2, o_mod);
}

// round 11
// speedup vs baseline: 2.8971x; 1.1243x over previous
#include <cuda_runtime.h>
#include <cstdint>

typedef unsigned long long u64;

// Problem constants
constexpr int Bb  = 2;
constexpr int NC  = 256;
constexpr int CN  = 256;
constexpr int K   = 16;
constexpr int DN  = 64;
constexpr int HM  = 128;
constexpr int F   = 192;
constexpr int HMOD = 64;
constexpr int MOD_OUT = 5;

// Scratch
__device__ float g_agg[(size_t)Bb * NC * CN * DN];
__device__ float g_pooled[(size_t)Bb * NC * 2 * DN];   // [bn][h_mean|msg_mean]

// ---------------- SMEM layout (bytes) --------------------------------------
constexpr int OFF_TMEM  = 0;
constexpr int OFF_MBARA = 8;
constexpr int OFF_MBARB = 16;
constexpr int OFF_MBARC = 24;
constexpr int OFF_B1M   = 32;     // 128 f
constexpr int OFF_B2M   = 544;    // 64 f
constexpr int OFF_B1SS  = 800;    // 128 f
constexpr int OFF_B2SS  = 1312;   // 64 f
constexpr int OFF_POOL  = 1568;   // 128 f
constexpr int OFF_AH    = 3072;            // 32KB
constexpr int OFF_AL    = 3072 + 32768;    // 32KB
constexpr int OFF_BH    = 3072 + 65536;    // 64KB
constexpr int OFF_BL    = 3072 + 131072;   // 64KB
constexpr int SMEM_MLP  = 3072 + 196608;   // 199680 B

// agg kernel smem: h tile 64KB + conn 16KB + w_conn 16KB
constexpr int SMEM_AGG  = 65536 + 16384 + 16384;   // 98304 B

#if defined(__CUDA_ARCH_FEAT_SM103_ALL) || defined(__CUDA_ARCH_FEAT_SM100_ALL) || defined(__CUDA_ARCH_FEAT_SM101_ALL)
#define HAS_TCGEN05 1
#else
#define HAS_TCGEN05 0
#endif

__device__ __forceinline__ uint32_t smem_u32(const void* p) {
    uint32_t a;
    asm("{ .reg .u64 t; cvta.to.shared.u64 t, %1; cvt.u32.u64 %0, t; }"
        : "=r"(a) : "l"(p));
    return a;
}

#if HAS_TCGEN05
__device__ __forceinline__ uint32_t elect1() {
    uint32_t p;
    asm volatile("{ .reg .pred p; elect.sync _|p, 0xFFFFFFFF; selp.b32 %0, 1, 0, p; }"
                 : "=r"(p));
    return p;
}

#define TC_ALLOC(smem_addr, n) \
    asm volatile("tcgen05.alloc.cta_group::1.sync.aligned.shared::cta.b32 [%0], %1;" \
                 :: "r"((uint32_t)(smem_addr)), "r"((uint32_t)(n)) : "memory")
#define TC_RELINQ() \
    asm volatile("tcgen05.relinquish_alloc_permit.cta_group::1.sync.aligned;")
#define TC_DEALLOC(tmem, n) \
    asm volatile("tcgen05.dealloc.cta_group::1.sync.aligned.b32 %0, %1;" \
                 :: "r"(tmem), "r"((uint32_t)(n)))
#define TC_COMMIT(mbar) \
    asm volatile("tcgen05.commit.cta_group::1.mbarrier::arrive::one.shared::cluster.b64 [%0];" \
                 :: "r"((uint32_t)(mbar)) : "memory")
#define TC_FENCE_AFTER()  asm volatile("tcgen05.fence::after_thread_sync;" ::: "memory")
#define TC_WAIT_LD()      asm volatile("tcgen05.wait::ld.sync.aligned;" ::: "memory")

#define LDTM_X32(r, addr) \
    asm volatile( \
        "tcgen05.ld.sync.aligned.32x32b.x32.b32 " \
        "{%0, %1, %2, %3, %4, %5, %6, %7, " \
        " %8, %9, %10, %11, %12, %13, %14, %15, " \
        " %16, %17, %18, %19, %20, %21, %22, %23, " \
        " %24, %25, %26, %27, %28, %29, %30, %31}, [%32];" \
        : "=r"((r)[0]),  "=r"((r)[1]),  "=r"((r)[2]),  "=r"((r)[3]), \
          "=r"((r)[4]),  "=r"((r)[5]),  "=r"((r)[6]),  "=r"((r)[7]), \
          "=r"((r)[8]),  "=r"((r)[9]),  "=r"((r)[10]), "=r"((r)[11]), \
          "=r"((r)[12]), "=r"((r)[13]), "=r"((r)[14]), "=r"((r)[15]), \
          "=r"((r)[16]), "=r"((r)[17]), "=r"((r)[18]), "=r"((r)[19]), \
          "=r"((r)[20]), "=r"((r)[21]), "=r"((r)[22]), "=r"((r)[23]), \
          "=r"((r)[24]), "=r"((r)[25]), "=r"((r)[26]), "=r"((r)[27]), \
          "=r"((r)[28]), "=r"((r)[29]), "=r"((r)[30]), "=r"((r)[31]) \
        : "r"(addr))

__device__ __forceinline__ void mma_tf32_ss(uint32_t d_tmem, u64 a_desc, u64 b_desc,
                                            uint32_t idesc, uint32_t enable) {
    asm volatile(
        "{\n\t"
        ".reg .pred p;\n\t"
        "setp.ne.u32 p, %4, 0;\n\t"
        "tcgen05.mma.cta_group::1.kind::tf32 [%0], %1, %2, %3, {%5, %5, %5, %5}, p;\n\t"
        "}"
        :: "r"(d_tmem), "l"(a_desc), "l"(b_desc), "r"(idesc), "r"(enable), "r"(0u)
        : "memory");
}
#endif  // HAS_TCGEN05

#define MBAR_INIT(mbar, cnt) \
    asm volatile("mbarrier.init.shared.b64 [%0], %1;" \
                 :: "r"((uint32_t)(mbar)), "r"((uint32_t)(cnt)) : "memory")

#define MBAR_WAIT(mbar, parity) do {                                           \
    uint32_t _m = (uint32_t)(mbar), _p = (uint32_t)(parity), _d;               \
    asm volatile("{ .reg .pred p;"                                             \
        " mbarrier.try_wait.parity.acquire.cta.shared::cta.b64 p, [%1], %2;"   \
        " selp.b32 %0, 1, 0, p; }" : "=r"(_d) : "r"(_m), "r"(_p) : "memory");  \
    while (!_d) {                                                              \
        asm volatile("{ .reg .pred p;"                                         \
            " mbarrier.try_wait.parity.acquire.cta.shared::cta.b64 p, [%1], %2, 0x989680;" \
            " selp.b32 %0, 1, 0, p; }" : "=r"(_d) : "r"(_m), "r"(_p) : "memory"); \
    }                                                                          \
} while (0)

constexpr u64 DESC_BASE = (2ull << 61) | (1ull << 46) | (64ull << 32) | (1ull << 16);
__device__ __forceinline__ u64 mk_desc(uint32_t addr) {
    return DESC_BASE | ((u64)(addr >> 4) & 0x3FFF);
}

// Blocked-atom + SW128 byte offset. atom = 8 rows x 32 tf32 (128B).
__device__ __forceinline__ uint32_t tile_off(int row, int k, int atom_rows) {
    uint32_t o = ((uint32_t)((k >> 5) * atom_rows + (row >> 3)) << 10)
               + ((uint32_t)(row & 7) << 7) + ((uint32_t)(k & 31) << 2);
    return o ^ ((o >> 3) & 0x70);
}

__device__ __forceinline__ float to_tf32(float x) {
    float r;
    asm("cvt.rna.tf32.f32 %0, %1;" : "=f"(r) : "f"(x));
    return r;
}

__device__ __forceinline__ void split_sts(char* smem, uint32_t off_hi, uint32_t lo_delta,
                                          float4 v) {
    float4 hv, lv;
    hv.x = to_tf32(v.x); hv.y = to_tf32(v.y); hv.z = to_tf32(v.z); hv.w = to_tf32(v.w);
    lv.x = v.x - hv.x;   lv.y = v.y - hv.y;   lv.z = v.z - hv.z;   lv.w = v.w - hv.w;
    *reinterpret_cast<float4*>(smem + off_hi)            = hv;
    *reinterpret_cast<float4*>(smem + off_hi + lo_delta) = lv;
}

__device__ __forceinline__ float gelu_f(float x) {
    float x3 = x * x * x;
    return 0.5f * x * (1.0f + tanhf(0.7978845608028654f * (x + 0.044715f * x3)));
}

__device__ __forceinline__ float gelu_fast(float x) {
    float z = x + 0.044715f * x * x * x;
    float a = 2.3022081852f * z;
    float e;
    asm("ex2.approx.f32 %0, %1;" : "=f"(e) : "f"(a));
    float r;
    asm("rcp.approx.f32 %0, %1;" : "=f"(r) : "f"(e + 1.0f));
    return x - x * r;
}

constexpr uint32_t ID_TC = (1u << 4) | (2u << 7) | (2u << 10) | (8u << 17) | (8u << 24);

// ---------------------------------------------------------------------------
// Kernel 1: connection-weighted aggregation.
// conn/w_conn rows staged to smem up-front (coalesced) -> inner loop is pure
// LDS (broadcast idx/w + conflict-free float2 gather). 512 threads.
// ---------------------------------------------------------------------------
__global__ __launch_bounds__(512) void agg_kernel(
    const float* __restrict__ h,
    const float* __restrict__ w_conn,
    const int*   __restrict__ conn)
{
    extern __shared__ float smf[];                 // h tile [256][64]
    int*   ci_sm = (int*)(smf + CN * DN);          // [256][16]
    float* wc_sm = (float*)(ci_sm + CN * K);       // [256][16]

    int bn   = blockIdx.x;
    int n    = bn & (NC - 1);
    int tid  = threadIdx.x;
    int wid  = tid >> 5;
    int lane = tid & 31;

    const float4* hg = reinterpret_cast<const float4*>(h) + (size_t)bn * CN * DN / 4;
    float4* h_sm4 = reinterpret_cast<float4*>(smf);
    #pragma unroll
    for (int p = 0; p < 8; p++) h_sm4[p * 512 + tid] = hg[p * 512 + tid];

    const int4*   cg4 = reinterpret_cast<const int4*>(conn   + (size_t)n  * CN * K);
    const float4* wg4 = reinterpret_cast<const float4*>(w_conn + (size_t)bn * CN * K);
    int4*   ci4 = reinterpret_cast<int4*>(ci_sm);
    float4* wc4 = reinterpret_cast<float4*>(wc_sm);
    #pragma unroll
    for (int p = 0; p < 2; p++) {
        ci4[p * 512 + tid] = cg4[p * 512 + tid];
        wc4[p * 512 + tid] = wg4[p * 512 + tid];
    }
    __syncthreads();

    // 16 warps x 8 iterations x 2 c = 256 c
    #pragma unroll 2
    for (int it = 0; it < 8; it++) {
        int c0 = wid * 16 + it * 2;
        const int*   ci0 = ci_sm + c0 * K;
        const float* wc0 = wc_sm + c0 * K;

        float2 acc0 = {0.0f, 0.0f}, acc1 = {0.0f, 0.0f};
        const float* hl = smf + lane * 2;
        #pragma unroll
        for (int k = 0; k < K; k++) {
            int   i0 = ci0[k];
            int   i1 = ci0[K + k];
            float w0 = wc0[k];
            float w1 = wc0[K + k];
            float2 v0 = *reinterpret_cast<const float2*>(hl + (size_t)i0 * DN);
            float2 v1 = *reinterpret_cast<const float2*>(hl + (size_t)i1 * DN);
            acc0.x = fmaf(w0, v0.x, acc0.x);
            acc0.y = fmaf(w0, v0.y, acc0.y);
            acc1.x = fmaf(w1, v1.x, acc1.x);
            acc1.y = fmaf(w1, v1.y, acc1.y);
        }
        float* out = g_agg + ((size_t)bn * CN + c0) * DN + lane * 2;
        *reinterpret_cast<float2*>(out)      = acc0;
        *reinterpret_cast<float2*>(out + DN) = acc1;
    }
}

#if HAS_TCGEN05
// GEMM2 phase: hidden = gelu(D1 + b1) staged hi/lo into B buffers; two N=64
// column chunks of D2 at tmem+256 / tmem+320. On return all warps have passed
// MBARC (A and B buffers free, D2 complete).
__device__ __forceinline__ void gemm2_phase(
    char* smem, uint32_t sbase, uint32_t tmem,
    int wid, int lane, int sub, int cgrp, float bj1, uint32_t parity)
{
    int j = sub * 32 + lane;
    // epilogue ch0
    {
        uint32_t r0[32];
        LDTM_X32(r0, tmem + cgrp * 32);
        TC_WAIT_LD();
        #pragma unroll
        for (int i2 = 0; i2 < 32; i2++) {
            float v = gelu_fast(__uint_as_float(r0[i2]) + bj1);
            float hv = to_tf32(v), lv = v - hv;
            uint32_t off = tile_off(cgrp * 32 + i2, j, 16);
            *reinterpret_cast<float*>(smem + OFF_BH + off) = hv;
            *reinterpret_cast<float*>(smem + OFF_BL + off) = lv;
        }
    }
    asm volatile("fence.proxy.async.shared::cta;" ::: "memory");
    __syncthreads();

    if (wid == 0) {
        u64 dah = mk_desc(sbase + OFF_BH), dal = mk_desc(sbase + OFF_BL);
        u64 dbh = mk_desc(sbase + OFF_AH), dbl = mk_desc(sbase + OFF_AL);
        if (elect1()) {
            #pragma unroll
            for (int pass = 0; pass < 3; pass++) {
                u64 da = (pass == 2) ? dal : dah;
                u64 db = (pass == 1) ? dbl : dbh;
                #pragma unroll
                for (int s = 0; s < 16; s++) {
                    u64 oa = (u64)((s >> 2) * 1024 + (s & 3) * 2);
                    u64 ob = (u64)((s >> 2) * 512  + (s & 3) * 2);
                    mma_tf32_ss(tmem + 256, da + oa, db + ob, ID_TC, (pass | s) ? 1u : 0u);
                }
            }
            TC_COMMIT(sbase + OFF_MBARB);
        }
    }

    // epilogue ch1 (overlaps ch0 MMA)
    float fv[32];
    {
        uint32_t r1[32];
        LDTM_X32(r1, tmem + 128 + cgrp * 32);
        TC_WAIT_LD();
        #pragma unroll
        for (int i2 = 0; i2 < 32; i2++)
            fv[i2] = gelu_fast(__uint_as_float(r1[i2]) + bj1);
    }
    MBAR_WAIT(sbase + OFF_MBARB, parity);
    TC_FENCE_AFTER();
    #pragma unroll
    for (int i2 = 0; i2 < 32; i2++) {
        float hv = to_tf32(fv[i2]), lv = fv[i2] - hv;
        uint32_t off = tile_off(cgrp * 32 + i2, j, 16);
        *reinterpret_cast<float*>(smem + OFF_BH + off) = hv;
        *reinterpret_cast<float*>(smem + OFF_BL + off) = lv;
    }
    asm volatile("fence.proxy.async.shared::cta;" ::: "memory");
    __syncthreads();

    if (wid == 0) {
        u64 dah = mk_desc(sbase + OFF_BH), dal = mk_desc(sbase + OFF_BL);
        u64 dbh = mk_desc(sbase + OFF_AH), dbl = mk_desc(sbase + OFF_AL);
        if (elect1()) {
            #pragma unroll
            for (int pass = 0; pass < 3; pass++) {
                u64 da = (pass == 2) ? dal : dah;
                u64 db = (pass == 1) ? dbl : dbh;
                #pragma unroll
                for (int s = 0; s < 16; s++) {
                    u64 oa = (u64)((s >> 2) * 1024 + (s & 3) * 2);
                    u64 ob = (u64)((s >> 2) * 512  + (s & 3) * 2);
                    mma_tf32_ss(tmem + 320, da + oa, db + ob, ID_TC, (pass | s) ? 1u : 0u);
                }
            }
            TC_COMMIT(sbase + OFF_MBARC);
        }
    }
    MBAR_WAIT(sbase + OFF_MBARC, parity);
    TC_FENCE_AFTER();
}

// GEMM1 MMA issue for one K=64 tile: D1[j=128][c=256] over 4 N=64 chunks.
// When `first` is set, EVERY q-chunk's first (pass=0,s=0) MMA has enable_d=0.
__device__ __forceinline__ void gemm1_mma(uint32_t sbase, uint32_t tmem, bool first) {
    u64 dah = mk_desc(sbase + OFF_AH), dal = mk_desc(sbase + OFF_AL);
    u64 dbh = mk_desc(sbase + OFF_BH), dbl = mk_desc(sbase + OFF_BL);
    if (elect1()) {
        #pragma unroll
        for (int pass = 0; pass < 3; pass++) {
            u64 da = (pass == 2) ? dal : dah;
            u64 db = (pass == 1) ? dbl : dbh;
            #pragma unroll
            for (int q = 0; q < 4; q++) {
                #pragma unroll
                for (int s = 0; s < 8; s++) {
                    u64 oa = (u64)((s >> 2) * 1024 + (s & 3) * 2);
                    u64 ob = (u64)((s >> 2) * 2048 + (s & 3) * 2 + q * 512);
                    mma_tf32_ss(tmem + q * 64, da + oa, db + ob, ID_TC,
                                (first && pass == 0 && s == 0) ? 0u : 1u);
                }
            }
        }
        TC_COMMIT(sbase + OFF_MBARA);
    }
}
#endif  // HAS_TCGEN05

// ---------------------------------------------------------------------------
// Fully fused per-(b,n) kernel: msg MLP -> state MLP (+residual) + pooled stats.
// ---------------------------------------------------------------------------
__global__ __launch_bounds__(512, 1)
void fused_mlp_kernel(
    const float* __restrict__ h,
    const float* __restrict__ ctx,
    const float* __restrict__ nid,
    const float* __restrict__ mw1, const float* __restrict__ mb1,
    const float* __restrict__ mw2, const float* __restrict__ mb2,
    const float* __restrict__ sw1, const float* __restrict__ sb1,
    const float* __restrict__ sw2, const float* __restrict__ sb2,
    const int*   __restrict__ c2g,
    float*       __restrict__ o_msg,
    float*       __restrict__ o_h)
{
    extern __shared__ char smem[];
    uint32_t sbase = smem_u32(smem);

    int tid  = threadIdx.x;
    int wid  = tid >> 5;
    int lane = tid & 31;
    int bn   = blockIdx.x;
    int n    = bn & (NC - 1);
    int g    = c2g[n];

    const float* w1m    = mw1 + (size_t)g * HM * F;
    const float* w2m    = mw2 + (size_t)g * DN * HM;
    const float* w1s    = sw1 + (size_t)g * HM * F;
    const float* w2s    = sw2 + (size_t)g * DN * HM;
    const float* base_h = h + (size_t)bn * CN * DN;
    const float* base_a = g_agg + (size_t)bn * CN * DN;
    const float* base_n = nid + (size_t)n * CN * DN;
    const float* base_c = ctx + (size_t)bn * DN;
    float* pool = (float*)(smem + OFF_POOL);

#if HAS_TCGEN05
    if (wid == 0) {
        TC_ALLOC(sbase + OFF_TMEM, 512);
        TC_RELINQ();
    }
    if (tid == 0) {
        MBAR_INIT(sbase + OFF_MBARA, 1);
        MBAR_INIT(sbase + OFF_MBARB, 1);
        MBAR_INIT(sbase + OFF_MBARC, 1);
    }
    if (tid < HM) {
        ((float*)(smem + OFF_B1M))[tid]  = mb1[g * HM + tid];
        ((float*)(smem + OFF_B1SS))[tid] = sb1[g * HM + tid];
    }
    if (tid < DN) {
        ((float*)(smem + OFF_B2M))[tid]  = mb2[g * DN + tid];
        ((float*)(smem + OFF_B2SS))[tid] = sb2[g * DN + tid];
    }
    if (tid < 2 * DN) pool[tid] = 0.0f;
    __syncthreads();

    uint32_t tmem;
    asm("ld.shared.b32 %0, [%1];" : "=r"(tmem) : "r"(sbase + OFF_TMEM));

    uint32_t ph = 0;
    int sub  = wid & 3;
    int cgrp = wid >> 2;
    int j    = sub * 32 + lane;

    float4 va[4], vb[8], vw[4];
    // prefetch msg tile 0: W1m cols 0:64 + h
    #pragma unroll
    for (int p = 0; p < 4; p++) {
        int i = p * 512 + tid; int r = i >> 4, k4 = i & 15;
        va[p] = *reinterpret_cast<const float4*>(w1m + (size_t)r * F + k4 * 4);
    }
    #pragma unroll
    for (int p = 0; p < 8; p++) {
        int i = p * 512 + tid; int r = i >> 4, k4 = i & 15;
        vb[p] = *reinterpret_cast<const float4*>(base_h + (size_t)r * DN + k4 * 4);
    }

    // ===================== MSG GEMM1 =====================
    for (int t = 0; t < 3; t++) {
        if (t > 0) { MBAR_WAIT(sbase + OFF_MBARA, ph); ph ^= 1; TC_FENCE_AFTER(); }
        #pragma unroll
        for (int p = 0; p < 4; p++) {
            int i = p * 512 + tid; int r = i >> 4, k4 = i & 15;
            split_sts(smem, OFF_AH + tile_off(r, k4 * 4, 16), 32768, va[p]);
        }
        #pragma unroll
        for (int p = 0; p < 8; p++) {
            int i = p * 512 + tid; int r = i >> 4, k4 = i & 15;
            split_sts(smem, OFF_BH + tile_off(r, k4 * 4, 32), 65536, vb[p]);
        }
        asm volatile("fence.proxy.async.shared::cta;" ::: "memory");
        __syncthreads();
        if (wid == 0) gemm1_mma(sbase, tmem, t == 0);

        if (t < 2) {
            int tn = t + 1;
            #pragma unroll
            for (int p = 0; p < 4; p++) {
                int i = p * 512 + tid; int r = i >> 4, k4 = i & 15;
                va[p] = *reinterpret_cast<const float4*>(w1m + (size_t)r * F + tn * 64 + k4 * 4);
            }
            #pragma unroll
            for (int p = 0; p < 8; p++) {
                int i = p * 512 + tid; int r = i >> 4, k4 = i & 15;
                const float* src = (tn == 1) ? base_a : base_n;
                vb[p] = *reinterpret_cast<const float4*>(src + (size_t)r * DN + k4 * 4);
            }
        } else {
            #pragma unroll
            for (int p = 0; p < 4; p++) {
                int i = p * 512 + tid; int r = i >> 5, k4 = i & 31;
                vw[p] = *reinterpret_cast<const float4*>(w2m + (size_t)r * HM + k4 * 4);
            }
        }
    }
    MBAR_WAIT(sbase + OFF_MBARA, ph); ph ^= 1;
    TC_FENCE_AFTER();

    // ===================== MSG GEMM2 =====================
    // stage W2m into A buffers
    #pragma unroll
    for (int p = 0; p < 4; p++) {
        int i = p * 512 + tid; int r = i >> 5, k4 = i & 31;
        split_sts(smem, OFF_AH + tile_off(r, k4 * 4, 8), 32768, vw[p]);
    }
    // prefetch state t0 A-chunk: W1s cols 64:128 (the msg part of state feat)
    #pragma unroll
    for (int p = 0; p < 4; p++) {
        int i = p * 512 + tid; int r = i >> 4, k4 = i & 15;
        va[p] = *reinterpret_cast<const float4*>(w1s + (size_t)r * F + 64 + k4 * 4);
    }
    float bj1m = ((float*)(smem + OFF_B1M))[j];
    gemm2_phase(smem, sbase, tmem, wid, lane, sub, cgrp, bj1m, 0);

    // ---- msg epilogue: D2 -> o_msg, pooled, and state feat tile in B ----
    {
        int ch  = cgrp >> 1;
        int jh2 = cgrp & 1;
        uint32_t r[32];
        LDTM_X32(r, tmem + 256 + ch * 64 + jh2 * 32);
        TC_WAIT_LD();
        int c  = ch * 128 + sub * 32 + lane;
        int jb = jh2 * 32;
        const float* b2s = (float*)(smem + OFF_B2M);
        float mv[32];
        #pragma unroll
        for (int i2 = 0; i2 < 32; i2++)
            mv[i2] = __uint_as_float(r[i2]) + b2s[jb + i2];
        // STG msg
        float* op = o_msg + ((size_t)bn * CN + c) * DN + jb;
        #pragma unroll
        for (int i4 = 0; i4 < 8; i4++)
            *reinterpret_cast<float4*>(op + i4 * 4) =
                make_float4(mv[i4 * 4], mv[i4 * 4 + 1], mv[i4 * 4 + 2], mv[i4 * 4 + 3]);
        // stage as state feat tile row=c, k=jb+i2 (B tile [256 x 64], atoms=32)
        #pragma unroll
        for (int i2 = 0; i2 < 32; i2++) {
            float hv = to_tf32(mv[i2]), lv = mv[i2] - hv;
            uint32_t off = tile_off(c, jb + i2, 32);
            *reinterpret_cast<float*>(smem + OFF_BH + off) = hv;
            *reinterpret_cast<float*>(smem + OFF_BL + off) = lv;
        }
        // pooled msg mean: butterfly over lanes (c), pick reg == lane
        float psum = 0.0f;
        #pragma unroll
        for (int i2 = 0; i2 < 32; i2++) {
            float v = mv[i2];
            v += __shfl_xor_sync(0xFFFFFFFFu, v, 16);
            v += __shfl_xor_sync(0xFFFFFFFFu, v, 8);
            v += __shfl_xor_sync(0xFFFFFFFFu, v, 4);
            v += __shfl_xor_sync(0xFFFFFFFFu, v, 2);
            v += __shfl_xor_sync(0xFFFFFFFFu, v, 1);
            if (lane == i2) psum = v;
        }
        atomicAdd(&pool[DN + jb + lane], psum);
    }
    asm volatile("fence.proxy.async.shared::cta;" ::: "memory");
    __syncthreads();

    // ===================== STATE GEMM1 =====================
    // t=0: B = msg tile (already staged), A = W1s cols 64:128 (in va)
    #pragma unroll
    for (int p = 0; p < 4; p++) {
        int i = p * 512 + tid; int r = i >> 4, k4 = i & 15;
        split_sts(smem, OFF_AH + tile_off(r, k4 * 4, 16), 32768, va[p]);
    }
    asm volatile("fence.proxy.async.shared::cta;" ::: "memory");
    __syncthreads();
    if (wid == 0) gemm1_mma(sbase, tmem, true);
    // prefetch t1: W1s cols 0:64 + h
    #pragma unroll
    for (int p = 0; p < 4; p++) {
        int i = p * 512 + tid; int r = i >> 4, k4 = i & 15;
        va[p] = *reinterpret_cast<const float4*>(w1s + (size_t)r * F + k4 * 4);
    }
    #pragma unroll
    for (int p = 0; p < 8; p++) {
        int i = p * 512 + tid; int r = i >> 4, k4 = i & 15;
        vb[p] = *reinterpret_cast<const float4*>(base_h + (size_t)r * DN + k4 * 4);
    }
    for (int t = 1; t < 3; t++) {
        MBAR_WAIT(sbase + OFF_MBARA, ph); ph ^= 1; TC_FENCE_AFTER();
        #pragma unroll
        for (int p = 0; p < 4; p++) {
            int i = p * 512 + tid; int r = i >> 4, k4 = i & 15;
            split_sts(smem, OFF_AH + tile_off(r, k4 * 4, 16), 32768, va[p]);
        }
        #pragma unroll
        for (int p = 0; p < 8; p++) {
            int i = p * 512 + tid; int r = i >> 4, k4 = i & 15;
            split_sts(smem, OFF_BH + tile_off(r, k4 * 4, 32), 65536, vb[p]);
        }
        asm volatile("fence.proxy.async.shared::cta;" ::: "memory");
        __syncthreads();
        if (wid == 0) gemm1_mma(sbase, tmem, false);

        if (t == 1) {
            #pragma unroll
            for (int p = 0; p < 4; p++) {
                int i = p * 512 + tid; int r = i >> 4, k4 = i & 15;
                va[p] = *reinterpret_cast<const float4*>(w1s + (size_t)r * F + 128 + k4 * 4);
            }
            #pragma unroll
            for (int p = 0; p < 8; p++) {
                int i = p * 512 + tid; int k4 = i & 15;
                vb[p] = *reinterpret_cast<const float4*>(base_c + k4 * 4);   // ctx bcast
            }
        } else {
            #pragma unroll
            for (int p = 0; p < 4; p++) {
                int i = p * 512 + tid; int r = i >> 5, k4 = i & 31;
                vw[p] = *reinterpret_cast<const float4*>(w2s + (size_t)r * HM + k4 * 4);
            }
        }
    }
    MBAR_WAIT(sbase + OFF_MBARA, ph); ph ^= 1;
    TC_FENCE_AFTER();

    // ===================== STATE GEMM2 =====================
    #pragma unroll
    for (int p = 0; p < 4; p++) {
        int i = p * 512 + tid; int r = i >> 5, k4 = i & 31;
        split_sts(smem, OFF_AH + tile_off(r, k4 * 4, 8), 32768, vw[p]);
    }
    float bj1s = ((float*)(smem + OFF_B1SS))[j];
    gemm2_phase(smem, sbase, tmem, wid, lane, sub, cgrp, bj1s, 1);

    // ---- state epilogue: D2 + b2s + h residual -> o_h, pooled ----
    {
        int ch  = cgrp >> 1;
        int jh2 = cgrp & 1;
        uint32_t r[32];
        LDTM_X32(r, tmem + 256 + ch * 64 + jh2 * 32);
        TC_WAIT_LD();
        int c  = ch * 128 + sub * 32 + lane;
        int jb = jh2 * 32;
        const float* b2s = (float*)(smem + OFF_B2SS);
        const float* hp = base_h + (size_t)c * DN + jb;
        float hv[32];
        #pragma unroll
        for (int i4 = 0; i4 < 8; i4++) {
            float4 hr = *reinterpret_cast<const float4*>(hp + i4 * 4);
            hv[i4 * 4 + 0] = __uint_as_float(r[i4 * 4 + 0]) + b2s[jb + i4 * 4 + 0] + hr.x;
            hv[i4 * 4 + 1] = __uint_as_float(r[i4 * 4 + 1]) + b2s[jb + i4 * 4 + 1] + hr.y;
            hv[i4 * 4 + 2] = __uint_as_float(r[i4 * 4 + 2]) + b2s[jb + i4 * 4 + 2] + hr.z;
            hv[i4 * 4 + 3] = __uint_as_float(r[i4 * 4 + 3]) + b2s[jb + i4 * 4 + 3] + hr.w;
        }
        float* op = o_h + ((size_t)bn * CN + c) * DN + jb;
        #pragma unroll
        for (int i4 = 0; i4 < 8; i4++)
            *reinterpret_cast<float4*>(op + i4 * 4) =
                make_float4(hv[i4 * 4], hv[i4 * 4 + 1], hv[i4 * 4 + 2], hv[i4 * 4 + 3]);
        float psum = 0.0f;
        #pragma unroll
        for (int i2 = 0; i2 < 32; i2++) {
            float v = hv[i2];
            v += __shfl_xor_sync(0xFFFFFFFFu, v, 16);
            v += __shfl_xor_sync(0xFFFFFFFFu, v, 8);
            v += __shfl_xor_sync(0xFFFFFFFFu, v, 4);
            v += __shfl_xor_sync(0xFFFFFFFFu, v, 2);
            v += __shfl_xor_sync(0xFFFFFFFFu, v, 1);
            if (lane == i2) psum = v;
        }
        atomicAdd(&pool[jb + lane], psum);
    }

    __syncthreads();
    if (tid < 2 * DN)
        g_pooled[(size_t)bn * 2 * DN + tid] = pool[tid] * (1.0f / CN);
    if (wid == 0) TC_DEALLOC(tmem, 512);

#else  // ---------------- SIMT fallback (plain compute_103 pass only) -------
    float* Hs  = (float*)(smem + OFF_AH);     // [256][128]
    if (tid < 2 * DN) pool[tid] = 0.0f;
    __syncthreads();

    // msg MLP
    for (int idx = tid; idx < CN * HM; idx += 512) {
        int c = idx >> 7, jj = idx & 127;
        float acc = mb1[g * HM + jj];
        const float* wr = w1m + (size_t)jj * F;
        for (int f = 0; f < DN; f++) acc = fmaf(wr[f],       base_h[(size_t)c * DN + f], acc);
        for (int f = 0; f < DN; f++) acc = fmaf(wr[64 + f],  base_a[(size_t)c * DN + f], acc);
        for (int f = 0; f < DN; f++) acc = fmaf(wr[128 + f], base_n[(size_t)c * DN + f], acc);
        Hs[idx] = gelu_f(acc);
    }
    __syncthreads();
    for (int idx = tid; idx < CN * DN; idx += 512) {
        int c = idx >> 6, j2 = idx & 63;
        float acc = mb2[g * DN + j2];
        const float* wr = w2m + (size_t)j2 * HM;
        const float* hr = Hs + (size_t)c * HM;
        for (int k = 0; k < HM; k++) acc = fmaf(wr[k], hr[k], acc);
        o_msg[((size_t)bn * CN + c) * DN + j2] = acc;
        atomicAdd(&pool[DN + j2], acc);
    }
    __syncthreads();
    // state MLP
    for (int idx = tid; idx < CN * HM; idx += 512) {
        int c = idx >> 7, jj = idx & 127;
        float acc = sb1[g * HM + jj];
        const float* wr = w1s + (size_t)jj * F;
        for (int f = 0; f < DN; f++) acc = fmaf(wr[f],       base_h[(size_t)c * DN + f], acc);
        for (int f = 0; f < DN; f++) acc = fmaf(wr[64 + f],  o_msg[((size_t)bn * CN + c) * DN + f], acc);
        for (int f = 0; f < DN; f++) acc = fmaf(wr[128 + f], base_c[f], acc);
        Hs[idx] = gelu_f(acc);
    }
    __syncthreads();
    for (int idx = tid; idx < CN * DN; idx += 512) {
        int c = idx >> 6, j2 = idx & 63;
        float acc = sb2[g * DN + j2];
        const float* wr = w2s + (size_t)j2 * HM;
        const float* hr = Hs + (size_t)c * HM;
        for (int k = 0; k < HM; k++) acc = fmaf(wr[k], hr[k], acc);
        acc += base_h[(size_t)c * DN + j2];
        o_h[((size_t)bn * CN + c) * DN + j2] = acc;
        atomicAdd(&pool[j2], acc);
    }
    __syncthreads();
    if (tid < 2 * DN)
        g_pooled[(size_t)bn * 2 * DN + tid] = pool[tid] * (1.0f / CN);
#endif
}

// ---------------------------------------------------------------------------
// Slim modulation MLP: reads pooled stats only.
// ---------------------------------------------------------------------------
__global__ __launch_bounds__(128) void mod_kernel(
    const float* __restrict__ mw1,
    const float* __restrict__ mb1,
    const float* __restrict__ mw2,
    const float* __restrict__ mb2,
    float*       __restrict__ mod)
{
    __shared__ float pooled[2 * DN];
    __shared__ float phh[HMOD];

    int bn  = blockIdx.x;
    int n   = bn & (NC - 1);
    int tid = threadIdx.x;

    if (tid < 2 * DN) pooled[tid] = g_pooled[(size_t)bn * 2 * DN + tid];
    __syncthreads();

    if (tid < HMOD) {
        const float* w = mw1 + (size_t)n * (2 * DN) * HMOD + tid;
        float acc = mb1[n * HMOD + tid];
        #pragma unroll 8
        for (int f = 0; f < 2 * DN; f++) acc = fmaf(pooled[f], w[f * HMOD], acc);
        phh[tid] = gelu_f(acc);
    }
    __syncthreads();

    if (tid < MOD_OUT) {
        const float* w = mw2 + (size_t)n * HMOD * MOD_OUT + tid;
        float acc = mb2[n * MOD_OUT + tid];
        #pragma unroll 8
        for (int k = 0; k < HMOD; k++) acc = fmaf(phh[k], w[k * MOD_OUT], acc);
        mod[bn * MOD_OUT + tid] = acc;
    }
}

// ---------------------------------------------------------------------------
// Launch
// ---------------------------------------------------------------------------
extern "C" void kernel_launch(void* const* d_in, const int* in_sizes, int n_in,
                              void* d_out, int out_size)
{
    const float* h      = (const float*)d_in[0];
    const float* w_conn = (const float*)d_in[1];
    const float* ctx    = (const float*)d_in[2];
    const float* nid    = (const float*)d_in[3];
    const float* mw1    = (const float*)d_in[4];
    const float* mb1    = (const float*)d_in[5];
    const float* mw2    = (const float*)d_in[6];
    const float* mb2    = (const float*)d_in[7];
    const float* sw1    = (const float*)d_in[8];
    const float* sb1    = (const float*)d_in[9];
    const float* sw2    = (const float*)d_in[10];
    const float* sb2    = (const float*)d_in[11];
    const float* modw1  = (const float*)d_in[12];
    const float* modb1  = (const float*)d_in[13];
    const float* modw2  = (const float*)d_in[14];
    const float* modb2  = (const float*)d_in[15];
    const int*   conn   = (const int*)d_in[16];
    const int*   c2g    = (const int*)d_in[17];

    float* out   = (float*)d_out;
    float* o_h   = out;
    float* o_msg = out + (size_t)Bb * NC * CN * DN;
    float* o_mod = o_msg + (size_t)Bb * NC * CN * DN;

    const int grid = Bb * NC;  // 512

    static bool attr_done = false;
    if (!attr_done) {
        cudaFuncSetAttribute(agg_kernel, cudaFuncAttributeMaxDynamicSharedMemorySize, SMEM_AGG);
        cudaFuncSetAttribute(fused_mlp_kernel, cudaFuncAttributeMaxDynamicSharedMemorySize, SMEM_MLP);
        attr_done = true;
    }

    agg_kernel<<<grid, 512, SMEM_AGG>>>(h, w_conn, conn);
    fused_mlp_kernel<<<grid, 512, SMEM_MLP>>>(h, ctx, nid, mw1, mb1, mw2, mb2,
                                              sw1, sb1, sw2, sb2, c2g, o_msg, o_h);
    mod_kernel<<<grid, 128>>>(modw1, modb1, modw2, modb2, o_mod);
}

// round 12
// speedup vs baseline: 3.2216x; 1.1120x over previous
#include <cuda_runtime.h>
#include <cuda_bf16.h>
#include <cstdint>

typedef unsigned long long u64;

// Problem constants
constexpr int Bb  = 2;
constexpr int NC  = 256;
constexpr int CN  = 256;
constexpr int K   = 16;
constexpr int DN  = 64;
constexpr int HM  = 128;
constexpr int F   = 192;
constexpr int HMOD = 64;
constexpr int MOD_OUT = 5;

// Scratch
__device__ float g_agg[(size_t)Bb * NC * CN * DN];
__device__ float g_pooled[(size_t)Bb * NC * 2 * DN];   // [bn][h_mean|msg_mean]

// ---------------- SMEM layout (bytes), bf16 operands -----------------------
constexpr int OFF_TMEM  = 0;
constexpr int OFF_MBARA = 8;
constexpr int OFF_MBARB = 16;
constexpr int OFF_MBARC = 24;
constexpr int OFF_B1M   = 32;     // 128 f
constexpr int OFF_B2M   = 544;    // 64 f
constexpr int OFF_B1SS  = 800;    // 128 f
constexpr int OFF_B2SS  = 1312;   // 64 f
constexpr int OFF_POOL  = 1568;   // 128 f
constexpr int OFF_AH    = 3072;            // 16KB: W1-chunk [128x64] / W2 [64x128] bf16
constexpr int OFF_AL    = 3072 + 16384;    // 16KB
constexpr int OFF_BH    = 3072 + 32768;    // 32KB: feat [256x64] / hidden [128x128] bf16
constexpr int OFF_BL    = 3072 + 65536;    // 32KB
constexpr int SMEM_MLP  = 3072 + 98304;    // 101376 B -> 2 CTAs/SM

// agg kernel smem: h tile 64KB + conn 16KB + w_conn 16KB
constexpr int SMEM_AGG  = 65536 + 16384 + 16384;   // 98304 B

#if defined(__CUDA_ARCH_FEAT_SM103_ALL) || defined(__CUDA_ARCH_FEAT_SM100_ALL) || defined(__CUDA_ARCH_FEAT_SM101_ALL)
#define HAS_TCGEN05 1
#else
#define HAS_TCGEN05 0
#endif

__device__ __forceinline__ uint32_t smem_u32(const void* p) {
    uint32_t a;
    asm("{ .reg .u64 t; cvta.to.shared.u64 t, %1; cvt.u32.u64 %0, t; }"
        : "=r"(a) : "l"(p));
    return a;
}

#if HAS_TCGEN05
__device__ __forceinline__ uint32_t elect1() {
    uint32_t p;
    asm volatile("{ .reg .pred p; elect.sync _|p, 0xFFFFFFFF; selp.b32 %0, 1, 0, p; }"
                 : "=r"(p));
    return p;
}

#define TC_ALLOC(smem_addr, n) \
    asm volatile("tcgen05.alloc.cta_group::1.sync.aligned.shared::cta.b32 [%0], %1;" \
                 :: "r"((uint32_t)(smem_addr)), "r"((uint32_t)(n)) : "memory")
#define TC_RELINQ() \
    asm volatile("tcgen05.relinquish_alloc_permit.cta_group::1.sync.aligned;")
#define TC_DEALLOC(tmem, n) \
    asm volatile("tcgen05.dealloc.cta_group::1.sync.aligned.b32 %0, %1;" \
                 :: "r"(tmem), "r"((uint32_t)(n)))
#define TC_COMMIT(mbar) \
    asm volatile("tcgen05.commit.cta_group::1.mbarrier::arrive::one.shared::cluster.b64 [%0];" \
                 :: "r"((uint32_t)(mbar)) : "memory")
#define TC_FENCE_AFTER()  asm volatile("tcgen05.fence::after_thread_sync;" ::: "memory")
#define TC_WAIT_LD()      asm volatile("tcgen05.wait::ld.sync.aligned;" ::: "memory")

#define LDTM_X32(r, addr) \
    asm volatile( \
        "tcgen05.ld.sync.aligned.32x32b.x32.b32 " \
        "{%0, %1, %2, %3, %4, %5, %6, %7, " \
        " %8, %9, %10, %11, %12, %13, %14, %15, " \
        " %16, %17, %18, %19, %20, %21, %22, %23, " \
        " %24, %25, %26, %27, %28, %29, %30, %31}, [%32];" \
        : "=r"((r)[0]),  "=r"((r)[1]),  "=r"((r)[2]),  "=r"((r)[3]), \
          "=r"((r)[4]),  "=r"((r)[5]),  "=r"((r)[6]),  "=r"((r)[7]), \
          "=r"((r)[8]),  "=r"((r)[9]),  "=r"((r)[10]), "=r"((r)[11]), \
          "=r"((r)[12]), "=r"((r)[13]), "=r"((r)[14]), "=r"((r)[15]), \
          "=r"((r)[16]), "=r"((r)[17]), "=r"((r)[18]), "=r"((r)[19]), \
          "=r"((r)[20]), "=r"((r)[21]), "=r"((r)[22]), "=r"((r)[23]), \
          "=r"((r)[24]), "=r"((r)[25]), "=r"((r)[26]), "=r"((r)[27]), \
          "=r"((r)[28]), "=r"((r)[29]), "=r"((r)[30]), "=r"((r)[31]) \
        : "r"(addr))

__device__ __forceinline__ void mma_bf16_ss(uint32_t d_tmem, u64 a_desc, u64 b_desc,
                                            uint32_t idesc, uint32_t enable) {
    asm volatile(
        "{\n\t"
        ".reg .pred p;\n\t"
        "setp.ne.u32 p, %4, 0;\n\t"
        "tcgen05.mma.cta_group::1.kind::f16 [%0], %1, %2, %3, {%5, %5, %5, %5}, p;\n\t"
        "}"
        :: "r"(d_tmem), "l"(a_desc), "l"(b_desc), "r"(idesc), "r"(enable), "r"(0u)
        : "memory");
}
#endif  // HAS_TCGEN05

#define MBAR_INIT(mbar, cnt) \
    asm volatile("mbarrier.init.shared.b64 [%0], %1;" \
                 :: "r"((uint32_t)(mbar)), "r"((uint32_t)(cnt)) : "memory")

#define MBAR_WAIT(mbar, parity) do {                                           \
    uint32_t _m = (uint32_t)(mbar), _p = (uint32_t)(parity), _d;               \
    asm volatile("{ .reg .pred p;"                                             \
        " mbarrier.try_wait.parity.acquire.cta.shared::cta.b64 p, [%1], %2;"   \
        " selp.b32 %0, 1, 0, p; }" : "=r"(_d) : "r"(_m), "r"(_p) : "memory");  \
    while (!_d) {                                                              \
        asm volatile("{ .reg .pred p;"                                         \
            " mbarrier.try_wait.parity.acquire.cta.shared::cta.b64 p, [%1], %2, 0x989680;" \
            " selp.b32 %0, 1, 0, p; }" : "=r"(_d) : "r"(_m), "r"(_p) : "memory"); \
    }                                                                          \
} while (0)

constexpr u64 DESC_BASE = (2ull << 61) | (1ull << 46) | (64ull << 32) | (1ull << 16);
__device__ __forceinline__ u64 mk_desc(uint32_t addr) {
    return DESC_BASE | ((u64)(addr >> 4) & 0x3FFF);
}

// Blocked-atom + SW128 byte offset for bf16 tiles. atom = 8 rows x 64 bf16 (128B).
__device__ __forceinline__ uint32_t tile_off2(int row, int k, int atom_rows) {
    uint32_t o = ((uint32_t)((k >> 6) * atom_rows + (row >> 3)) << 10)
               + ((uint32_t)(row & 7) << 7) + ((uint32_t)(k & 63) << 1);
    return o ^ ((o >> 3) & 0x70);
}

// split float4 -> bf16 hi (8B) + bf16 lo (8B), store at swizzled offsets
__device__ __forceinline__ void split_sts2(char* smem, uint32_t off_hi, uint32_t lo_delta,
                                           float4 v) {
    __nv_bfloat162 h0 = __floats2bfloat162_rn(v.x, v.y);
    __nv_bfloat162 h1 = __floats2bfloat162_rn(v.z, v.w);
    float lx = v.x - __bfloat162float(__low2bfloat16(h0));
    float ly = v.y - __bfloat162float(__high2bfloat16(h0));
    float lz = v.z - __bfloat162float(__low2bfloat16(h1));
    float lw = v.w - __bfloat162float(__high2bfloat16(h1));
    __nv_bfloat162 l0 = __floats2bfloat162_rn(lx, ly);
    __nv_bfloat162 l1 = __floats2bfloat162_rn(lz, lw);
    uint2 hv, lv;
    hv.x = *reinterpret_cast<uint32_t*>(&h0);
    hv.y = *reinterpret_cast<uint32_t*>(&h1);
    lv.x = *reinterpret_cast<uint32_t*>(&l0);
    lv.y = *reinterpret_cast<uint32_t*>(&l1);
    *reinterpret_cast<uint2*>(smem + off_hi)            = hv;
    *reinterpret_cast<uint2*>(smem + off_hi + lo_delta) = lv;
}

__device__ __forceinline__ float gelu_f(float x) {
    float x3 = x * x * x;
    return 0.5f * x * (1.0f + tanhf(0.7978845608028654f * (x + 0.044715f * x3)));
}

__device__ __forceinline__ float gelu_fast(float x) {
    float z = x + 0.044715f * x * x * x;
    float a = 2.3022081852f * z;
    float e;
    asm("ex2.approx.f32 %0, %1;" : "=f"(e) : "f"(a));
    float r;
    asm("rcp.approx.f32 %0, %1;" : "=f"(r) : "f"(e + 1.0f));
    return x - x * r;
}

// idesc bf16 (M=128, N=64): dtype=F32@4, atype=BF16(1)@7, btype=BF16(1)@10,
// N>>3=8@17, M>>4=8@24  (field placement proven by the working tf32 kernel)
constexpr uint32_t ID_BF = (1u << 4) | (1u << 7) | (1u << 10) | (8u << 17) | (8u << 24);

// ---------------------------------------------------------------------------
// Kernel 1: connection-weighted aggregation (proven, unchanged).
// ---------------------------------------------------------------------------
__global__ __launch_bounds__(512) void agg_kernel(
    const float* __restrict__ h,
    const float* __restrict__ w_conn,
    const int*   __restrict__ conn)
{
    extern __shared__ float smf[];
    int*   ci_sm = (int*)(smf + CN * DN);
    float* wc_sm = (float*)(ci_sm + CN * K);

    int bn   = blockIdx.x;
    int n    = bn & (NC - 1);
    int tid  = threadIdx.x;
    int wid  = tid >> 5;
    int lane = tid & 31;

    const float4* hg = reinterpret_cast<const float4*>(h) + (size_t)bn * CN * DN / 4;
    float4* h_sm4 = reinterpret_cast<float4*>(smf);
    #pragma unroll
    for (int p = 0; p < 8; p++) h_sm4[p * 512 + tid] = hg[p * 512 + tid];

    const int4*   cg4 = reinterpret_cast<const int4*>(conn   + (size_t)n  * CN * K);
    const float4* wg4 = reinterpret_cast<const float4*>(w_conn + (size_t)bn * CN * K);
    int4*   ci4 = reinterpret_cast<int4*>(ci_sm);
    float4* wc4 = reinterpret_cast<float4*>(wc_sm);
    #pragma unroll
    for (int p = 0; p < 2; p++) {
        ci4[p * 512 + tid] = cg4[p * 512 + tid];
        wc4[p * 512 + tid] = wg4[p * 512 + tid];
    }
    __syncthreads();

    #pragma unroll 2
    for (int it = 0; it < 8; it++) {
        int c0 = wid * 16 + it * 2;
        const int*   ci0 = ci_sm + c0 * K;
        const float* wc0 = wc_sm + c0 * K;

        float2 acc0 = {0.0f, 0.0f}, acc1 = {0.0f, 0.0f};
        const float* hl = smf + lane * 2;
        #pragma unroll
        for (int k = 0; k < K; k++) {
            int   i0 = ci0[k];
            int   i1 = ci0[K + k];
            float w0 = wc0[k];
            float w1 = wc0[K + k];
            float2 v0 = *reinterpret_cast<const float2*>(hl + (size_t)i0 * DN);
            float2 v1 = *reinterpret_cast<const float2*>(hl + (size_t)i1 * DN);
            acc0.x = fmaf(w0, v0.x, acc0.x);
            acc0.y = fmaf(w0, v0.y, acc0.y);
            acc1.x = fmaf(w1, v1.x, acc1.x);
            acc1.y = fmaf(w1, v1.y, acc1.y);
        }
        float* out = g_agg + ((size_t)bn * CN + c0) * DN + lane * 2;
        *reinterpret_cast<float2*>(out)      = acc0;
        *reinterpret_cast<float2*>(out + DN) = acc1;
    }
}

#if HAS_TCGEN05
// GEMM1 MMA for one K=64 tile: D1[j=128][c=256] over 4 N=64 chunks, bf16 K=16/step.
__device__ __forceinline__ void gemm1_mma(uint32_t sbase, uint32_t tmem, bool first) {
    u64 dah = mk_desc(sbase + OFF_AH), dal = mk_desc(sbase + OFF_AL);
    u64 dbh = mk_desc(sbase + OFF_BH), dbl = mk_desc(sbase + OFF_BL);
    if (elect1()) {
        #pragma unroll
        for (int pass = 0; pass < 3; pass++) {
            u64 da = (pass == 2) ? dal : dah;
            u64 db = (pass == 1) ? dbl : dbh;
            #pragma unroll
            for (int q = 0; q < 4; q++) {
                #pragma unroll
                for (int s = 0; s < 4; s++) {
                    u64 oa = (u64)(s * 2);
                    u64 ob = (u64)(s * 2 + q * 512);
                    mma_bf16_ss(tmem + q * 64, da + oa, db + ob, ID_BF,
                                (first && pass == 0 && s == 0) ? 0u : 1u);
                }
            }
        }
        TC_COMMIT(sbase + OFF_MBARA);
    }
}

// GEMM2 phase: hidden = gelu(D1 + b1) staged bf16 hi/lo into B buffers; D2
// chunks land in the consumed D1 columns: ch0 -> cols 0..63, ch1 -> 64..127.
// 8 warps: each handles cgrp = 2*cgrp2 + {0,1}.
__device__ __forceinline__ void gemm2_phase(
    char* smem, uint32_t sbase, uint32_t tmem,
    int wid, int lane, int sub, int cgrp2, float bj1, uint32_t parity)
{
    int j = sub * 32 + lane;
    // epilogue ch0: D1 cols 0..127 -> hidden rows 0..127
    #pragma unroll
    for (int q = 0; q < 2; q++) {
        int cg = cgrp2 * 2 + q;
        uint32_t r0[32];
        LDTM_X32(r0, tmem + cg * 32);
        TC_WAIT_LD();
        #pragma unroll
        for (int i2 = 0; i2 < 32; i2++) {
            float v = gelu_fast(__uint_as_float(r0[i2]) + bj1);
            __nv_bfloat16 hb = __float2bfloat16(v);
            __nv_bfloat16 lb = __float2bfloat16(v - __bfloat162float(hb));
            uint32_t off = tile_off2(cg * 32 + i2, j, 16);
            *reinterpret_cast<__nv_bfloat16*>(smem + OFF_BH + off) = hb;
            *reinterpret_cast<__nv_bfloat16*>(smem + OFF_BL + off) = lb;
        }
    }
    asm volatile("fence.proxy.async.shared::cta;" ::: "memory");
    __syncthreads();

    if (wid == 0) {
        u64 dah = mk_desc(sbase + OFF_BH), dal = mk_desc(sbase + OFF_BL);  // A = hidden
        u64 dbh = mk_desc(sbase + OFF_AH), dbl = mk_desc(sbase + OFF_AL);  // B = W2
        if (elect1()) {
            #pragma unroll
            for (int pass = 0; pass < 3; pass++) {
                u64 da = (pass == 2) ? dal : dah;
                u64 db = (pass == 1) ? dbl : dbh;
                #pragma unroll
                for (int s = 0; s < 8; s++) {
                    u64 oa = (u64)((s >> 2) * 1024 + (s & 3) * 2);
                    u64 ob = (u64)((s >> 2) * 512  + (s & 3) * 2);
                    mma_bf16_ss(tmem + 0, da + oa, db + ob, ID_BF, (pass | s) ? 1u : 0u);
                }
            }
            TC_COMMIT(sbase + OFF_MBARB);
        }
    }
    MBAR_WAIT(sbase + OFF_MBARB, parity);
    TC_FENCE_AFTER();

    // epilogue ch1: D1 cols 128..255
    #pragma unroll
    for (int q = 0; q < 2; q++) {
        int cg = cgrp2 * 2 + q;
        uint32_t r1[32];
        LDTM_X32(r1, tmem + 128 + cg * 32);
        TC_WAIT_LD();
        #pragma unroll
        for (int i2 = 0; i2 < 32; i2++) {
            float v = gelu_fast(__uint_as_float(r1[i2]) + bj1);
            __nv_bfloat16 hb = __float2bfloat16(v);
            __nv_bfloat16 lb = __float2bfloat16(v - __bfloat162float(hb));
            uint32_t off = tile_off2(cg * 32 + i2, j, 16);
            *reinterpret_cast<__nv_bfloat16*>(smem + OFF_BH + off) = hb;
            *reinterpret_cast<__nv_bfloat16*>(smem + OFF_BL + off) = lb;
        }
    }
    asm volatile("fence.proxy.async.shared::cta;" ::: "memory");
    __syncthreads();

    if (wid == 0) {
        u64 dah = mk_desc(sbase + OFF_BH), dal = mk_desc(sbase + OFF_BL);
        u64 dbh = mk_desc(sbase + OFF_AH), dbl = mk_desc(sbase + OFF_AL);
        if (elect1()) {
            #pragma unroll
            for (int pass = 0; pass < 3; pass++) {
                u64 da = (pass == 2) ? dal : dah;
                u64 db = (pass == 1) ? dbl : dbh;
                #pragma unroll
                for (int s = 0; s < 8; s++) {
                    u64 oa = (u64)((s >> 2) * 1024 + (s & 3) * 2);
                    u64 ob = (u64)((s >> 2) * 512  + (s & 3) * 2);
                    mma_bf16_ss(tmem + 64, da + oa, db + ob, ID_BF, (pass | s) ? 1u : 0u);
                }
            }
            TC_COMMIT(sbase + OFF_MBARC);
        }
    }
    MBAR_WAIT(sbase + OFF_MBARC, parity);
    TC_FENCE_AFTER();
}
#endif  // HAS_TCGEN05

// ---------------------------------------------------------------------------
// Fused per-(b,n) kernel: 256 threads, 2 CTAs/SM, bf16 3-pass tcgen05.
// ---------------------------------------------------------------------------
__global__ __launch_bounds__(256, 2)
void fused_mlp_kernel(
    const float* __restrict__ h,
    const float* __restrict__ ctx,
    const float* __restrict__ nid,
    const float* __restrict__ mw1, const float* __restrict__ mb1,
    const float* __restrict__ mw2, const float* __restrict__ mb2,
    const float* __restrict__ sw1, const float* __restrict__ sb1,
    const float* __restrict__ sw2, const float* __restrict__ sb2,
    const int*   __restrict__ c2g,
    float*       __restrict__ o_msg,
    float*       __restrict__ o_h)
{
    extern __shared__ char smem[];
    uint32_t sbase = smem_u32(smem);

    int tid  = threadIdx.x;
    int wid  = tid >> 5;
    int lane = tid & 31;
    int bn   = blockIdx.x;
    int n    = bn & (NC - 1);
    int g    = c2g[n];

    const float* w1m    = mw1 + (size_t)g * HM * F;
    const float* w2m    = mw2 + (size_t)g * DN * HM;
    const float* w1s    = sw1 + (size_t)g * HM * F;
    const float* w2s    = sw2 + (size_t)g * DN * HM;
    const float* base_h = h + (size_t)bn * CN * DN;
    const float* base_a = g_agg + (size_t)bn * CN * DN;
    const float* base_n = nid + (size_t)n * CN * DN;
    const float* base_c = ctx + (size_t)bn * DN;
    float* pool = (float*)(smem + OFF_POOL);

#if HAS_TCGEN05
    if (wid == 0) {
        TC_ALLOC(sbase + OFF_TMEM, 256);
        TC_RELINQ();
    }
    if (tid == 0) {
        MBAR_INIT(sbase + OFF_MBARA, 1);
        MBAR_INIT(sbase + OFF_MBARB, 1);
        MBAR_INIT(sbase + OFF_MBARC, 1);
    }
    if (tid < HM) {
        ((float*)(smem + OFF_B1M))[tid]  = mb1[g * HM + tid];
        ((float*)(smem + OFF_B1SS))[tid] = sb1[g * HM + tid];
    }
    if (tid < DN) {
        ((float*)(smem + OFF_B2M))[tid]  = mb2[g * DN + tid];
        ((float*)(smem + OFF_B2SS))[tid] = sb2[g * DN + tid];
    }
    if (tid < 2 * DN) pool[tid] = 0.0f;
    __syncthreads();

    uint32_t tmem;
    asm("ld.shared.b32 %0, [%1];" : "=r"(tmem) : "r"(sbase + OFF_TMEM));

    uint32_t ph = 0;
    int sub   = wid & 3;
    int cgrp2 = wid >> 2;     // 0..1
    int j     = sub * 32 + lane;

    // ===================== MSG GEMM1 (3 K-tiles of 64) =====================
    for (int t = 0; t < 3; t++) {
        if (t > 0) { MBAR_WAIT(sbase + OFF_MBARA, ph); ph ^= 1; TC_FENCE_AFTER(); }
        // A = W1m chunk [128 x 64]
        #pragma unroll
        for (int p = 0; p < 8; p++) {
            int i = p * 256 + tid; int r = i >> 4, k4 = i & 15;
            float4 v = *reinterpret_cast<const float4*>(w1m + (size_t)r * F + t * 64 + k4 * 4);
            split_sts2(smem, OFF_AH + tile_off2(r, k4 * 4, 16), 16384, v);
        }
        // B = feat chunk [256 x 64]
        #pragma unroll
        for (int p = 0; p < 16; p++) {
            int i = p * 256 + tid; int r = i >> 4, k4 = i & 15;
            float4 v;
            if (t == 0)      v = *reinterpret_cast<const float4*>(base_h + (size_t)r * DN + k4 * 4);
            else if (t == 1) v = *reinterpret_cast<const float4*>(base_a + (size_t)r * DN + k4 * 4);
            else             v = *reinterpret_cast<const float4*>(base_n + (size_t)r * DN + k4 * 4);
            split_sts2(smem, OFF_BH + tile_off2(r, k4 * 4, 32), 32768, v);
        }
        asm volatile("fence.proxy.async.shared::cta;" ::: "memory");
        __syncthreads();
        if (wid == 0) gemm1_mma(sbase, tmem, t == 0);
    }
    MBAR_WAIT(sbase + OFF_MBARA, ph); ph ^= 1;
    TC_FENCE_AFTER();

    // ===================== MSG GEMM2 =====================
    // stage W2m [64 x 128] into A buffers
    #pragma unroll
    for (int p = 0; p < 8; p++) {
        int i = p * 256 + tid; int r = i >> 5, k4 = i & 31;
        float4 v = *reinterpret_cast<const float4*>(w2m + (size_t)r * HM + k4 * 4);
        split_sts2(smem, OFF_AH + tile_off2(r, k4 * 4, 8), 16384, v);
    }
    float bj1m = ((float*)(smem + OFF_B1M))[j];
    gemm2_phase(smem, sbase, tmem, wid, lane, sub, cgrp2, bj1m, 0);

    // ---- msg epilogue: D2 -> o_msg, pooled, state feat tile in B ----
    #pragma unroll
    for (int q = 0; q < 2; q++) {
        int cgrp = cgrp2 * 2 + q;
        int ch   = cgrp >> 1;
        int jh2  = cgrp & 1;
        uint32_t r[32];
        LDTM_X32(r, tmem + ch * 64 + jh2 * 32);
        TC_WAIT_LD();
        int c  = ch * 128 + sub * 32 + lane;
        int jb = jh2 * 32;
        const float* b2s = (float*)(smem + OFF_B2M);
        float mv[32];
        #pragma unroll
        for (int i2 = 0; i2 < 32; i2++)
            mv[i2] = __uint_as_float(r[i2]) + b2s[jb + i2];
        float* op = o_msg + ((size_t)bn * CN + c) * DN + jb;
        #pragma unroll
        for (int i4 = 0; i4 < 8; i4++)
            *reinterpret_cast<float4*>(op + i4 * 4) =
                make_float4(mv[i4 * 4], mv[i4 * 4 + 1], mv[i4 * 4 + 2], mv[i4 * 4 + 3]);
        // stage as state feat B tile: row=c (atoms 32), k=jb+i2
        #pragma unroll
        for (int i2 = 0; i2 < 32; i2++) {
            __nv_bfloat16 hb = __float2bfloat16(mv[i2]);
            __nv_bfloat16 lb = __float2bfloat16(mv[i2] - __bfloat162float(hb));
            uint32_t off = tile_off2(c, jb + i2, 32);
            *reinterpret_cast<__nv_bfloat16*>(smem + OFF_BH + off) = hb;
            *reinterpret_cast<__nv_bfloat16*>(smem + OFF_BL + off) = lb;
        }
        float psum = 0.0f;
        #pragma unroll
        for (int i2 = 0; i2 < 32; i2++) {
            float v = mv[i2];
            v += __shfl_xor_sync(0xFFFFFFFFu, v, 16);
            v += __shfl_xor_sync(0xFFFFFFFFu, v, 8);
            v += __shfl_xor_sync(0xFFFFFFFFu, v, 4);
            v += __shfl_xor_sync(0xFFFFFFFFu, v, 2);
            v += __shfl_xor_sync(0xFFFFFFFFu, v, 1);
            if (lane == i2) psum = v;
        }
        atomicAdd(&pool[DN + jb + lane], psum);
    }
    asm volatile("fence.proxy.async.shared::cta;" ::: "memory");
    __syncthreads();

    // ===================== STATE GEMM1 =====================
    // t=0: B = msg tile (already staged), A = W1s cols 64:128
    #pragma unroll
    for (int p = 0; p < 8; p++) {
        int i = p * 256 + tid; int r = i >> 4, k4 = i & 15;
        float4 v = *reinterpret_cast<const float4*>(w1s + (size_t)r * F + 64 + k4 * 4);
        split_sts2(smem, OFF_AH + tile_off2(r, k4 * 4, 16), 16384, v);
    }
    asm volatile("fence.proxy.async.shared::cta;" ::: "memory");
    __syncthreads();
    if (wid == 0) gemm1_mma(sbase, tmem, true);

    for (int t = 1; t < 3; t++) {
        MBAR_WAIT(sbase + OFF_MBARA, ph); ph ^= 1; TC_FENCE_AFTER();
        // A = W1s chunk: t=1 -> cols 0:64 (h), t=2 -> cols 128:192 (ctx)
        int fo = (t == 1) ? 0 : 128;
        #pragma unroll
        for (int p = 0; p < 8; p++) {
            int i = p * 256 + tid; int r = i >> 4, k4 = i & 15;
            float4 v = *reinterpret_cast<const float4*>(w1s + (size_t)r * F + fo + k4 * 4);
            split_sts2(smem, OFF_AH + tile_off2(r, k4 * 4, 16), 16384, v);
        }
        #pragma unroll
        for (int p = 0; p < 16; p++) {
            int i = p * 256 + tid; int r = i >> 4, k4 = i & 15;
            float4 v;
            if (t == 1) v = *reinterpret_cast<const float4*>(base_h + (size_t)r * DN + k4 * 4);
            else        v = *reinterpret_cast<const float4*>(base_c + k4 * 4);   // ctx bcast
            split_sts2(smem, OFF_BH + tile_off2(r, k4 * 4, 32), 32768, v);
        }
        asm volatile("fence.proxy.async.shared::cta;" ::: "memory");
        __syncthreads();
        if (wid == 0) gemm1_mma(sbase, tmem, false);
    }
    MBAR_WAIT(sbase + OFF_MBARA, ph); ph ^= 1;
    TC_FENCE_AFTER();

    // ===================== STATE GEMM2 =====================
    #pragma unroll
    for (int p = 0; p < 8; p++) {
        int i = p * 256 + tid; int r = i >> 5, k4 = i & 31;
        float4 v = *reinterpret_cast<const float4*>(w2s + (size_t)r * HM + k4 * 4);
        split_sts2(smem, OFF_AH + tile_off2(r, k4 * 4, 8), 16384, v);
    }
    float bj1s = ((float*)(smem + OFF_B1SS))[j];
    gemm2_phase(smem, sbase, tmem, wid, lane, sub, cgrp2, bj1s, 1);

    // ---- state epilogue: D2 + b2s + h residual -> o_h, pooled ----
    #pragma unroll
    for (int q = 0; q < 2; q++) {
        int cgrp = cgrp2 * 2 + q;
        int ch   = cgrp >> 1;
        int jh2  = cgrp & 1;
        uint32_t r[32];
        LDTM_X32(r, tmem + ch * 64 + jh2 * 32);
        TC_WAIT_LD();
        int c  = ch * 128 + sub * 32 + lane;
        int jb = jh2 * 32;
        const float* b2s = (float*)(smem + OFF_B2SS);
        const float* hp = base_h + (size_t)c * DN + jb;
        float hv[32];
        #pragma unroll
        for (int i4 = 0; i4 < 8; i4++) {
            float4 hr = *reinterpret_cast<const float4*>(hp + i4 * 4);
            hv[i4 * 4 + 0] = __uint_as_float(r[i4 * 4 + 0]) + b2s[jb + i4 * 4 + 0] + hr.x;
            hv[i4 * 4 + 1] = __uint_as_float(r[i4 * 4 + 1]) + b2s[jb + i4 * 4 + 1] + hr.y;
            hv[i4 * 4 + 2] = __uint_as_float(r[i4 * 4 + 2]) + b2s[jb + i4 * 4 + 2] + hr.z;
            hv[i4 * 4 + 3] = __uint_as_float(r[i4 * 4 + 3]) + b2s[jb + i4 * 4 + 3] + hr.w;
        }
        float* op = o_h + ((size_t)bn * CN + c) * DN + jb;
        #pragma unroll
        for (int i4 = 0; i4 < 8; i4++)
            *reinterpret_cast<float4*>(op + i4 * 4) =
                make_float4(hv[i4 * 4], hv[i4 * 4 + 1], hv[i4 * 4 + 2], hv[i4 * 4 + 3]);
        float psum = 0.0f;
        #pragma unroll
        for (int i2 = 0; i2 < 32; i2++) {
            float v = hv[i2];
            v += __shfl_xor_sync(0xFFFFFFFFu, v, 16);
            v += __shfl_xor_sync(0xFFFFFFFFu, v, 8);
            v += __shfl_xor_sync(0xFFFFFFFFu, v, 4);
            v += __shfl_xor_sync(0xFFFFFFFFu, v, 2);
            v += __shfl_xor_sync(0xFFFFFFFFu, v, 1);
            if (lane == i2) psum = v;
        }
        atomicAdd(&pool[jb + lane], psum);
    }

    __syncthreads();
    if (tid < 2 * DN)
        g_pooled[(size_t)bn * 2 * DN + tid] = pool[tid] * (1.0f / CN);
    if (wid == 0) TC_DEALLOC(tmem, 256);

#else  // ---------------- SIMT fallback (plain compute_103 pass only) -------
    float* Hs = (float*)(smem + OFF_AH);   // [128][HM] = 64KB, two c-halves
    if (tid < 2 * DN) pool[tid] = 0.0f;
    __syncthreads();

    for (int half = 0; half < 2; half++) {
        int cb = half * 128;
        for (int idx = tid; idx < 128 * HM; idx += 256) {
            int c = cb + (idx >> 7), jj = idx & 127;
            float acc = mb1[g * HM + jj];
            const float* wr = w1m + (size_t)jj * F;
            for (int f = 0; f < DN; f++) acc = fmaf(wr[f],       base_h[(size_t)c * DN + f], acc);
            for (int f = 0; f < DN; f++) acc = fmaf(wr[64 + f],  base_a[(size_t)c * DN + f], acc);
            for (int f = 0; f < DN; f++) acc = fmaf(wr[128 + f], base_n[(size_t)c * DN + f], acc);
            Hs[idx] = gelu_f(acc);
        }
        __syncthreads();
        for (int idx = tid; idx < 128 * DN; idx += 256) {
            int c = cb + (idx >> 6), j2 = idx & 63;
            float acc = mb2[g * DN + j2];
            const float* wr = w2m + (size_t)j2 * HM;
            const float* hr = Hs + (size_t)(idx >> 6) * HM;
            for (int k = 0; k < HM; k++) acc = fmaf(wr[k], hr[k], acc);
            o_msg[((size_t)bn * CN + c) * DN + j2] = acc;
            atomicAdd(&pool[DN + j2], acc);
        }
        __syncthreads();
    }
    for (int half = 0; half < 2; half++) {
        int cb = half * 128;
        for (int idx = tid; idx < 128 * HM; idx += 256) {
            int c = cb + (idx >> 7), jj = idx & 127;
            float acc = sb1[g * HM + jj];
            const float* wr = w1s + (size_t)jj * F;
            for (int f = 0; f < DN; f++) acc = fmaf(wr[f],       base_h[(size_t)c * DN + f], acc);
            for (int f = 0; f < DN; f++) acc = fmaf(wr[64 + f],  o_msg[((size_t)bn * CN + c) * DN + f], acc);
            for (int f = 0; f < DN; f++) acc = fmaf(wr[128 + f], base_c[f], acc);
            Hs[idx] = gelu_f(acc);
        }
        __syncthreads();
        for (int idx = tid; idx < 128 * DN; idx += 256) {
            int c = cb + (idx >> 6), j2 = idx & 63;
            float acc = sb2[g * DN + j2];
            const float* wr = w2s + (size_t)j2 * HM;
            const float* hr = Hs + (size_t)(idx >> 6) * HM;
            for (int k = 0; k < HM; k++) acc = fmaf(wr[k], hr[k], acc);
            acc += base_h[(size_t)c * DN + j2];
            o_h[((size_t)bn * CN + c) * DN + j2] = acc;
            atomicAdd(&pool[j2], acc);
        }
        __syncthreads();
    }
    if (tid < 2 * DN)
        g_pooled[(size_t)bn * 2 * DN + tid] = pool[tid] * (1.0f / CN);
#endif
}

// ---------------------------------------------------------------------------
// Slim modulation MLP: reads pooled stats only.
// ---------------------------------------------------------------------------
__global__ __launch_bounds__(128) void mod_kernel(
    const float* __restrict__ mw1,
    const float* __restrict__ mb1,
    const float* __restrict__ mw2,
    const float* __restrict__ mb2,
    float*       __restrict__ mod)
{
    __shared__ float pooled[2 * DN];
    __shared__ float phh[HMOD];

    int bn  = blockIdx.x;
    int n   = bn & (NC - 1);
    int tid = threadIdx.x;

    if (tid < 2 * DN) pooled[tid] = g_pooled[(size_t)bn * 2 * DN + tid];
    __syncthreads();

    if (tid < HMOD) {
        const float* w = mw1 + (size_t)n * (2 * DN) * HMOD + tid;
        float acc = mb1[n * HMOD + tid];
        #pragma unroll 8
        for (int f = 0; f < 2 * DN; f++) acc = fmaf(pooled[f], w[f * HMOD], acc);
        phh[tid] = gelu_f(acc);
    }
    __syncthreads();

    if (tid < MOD_OUT) {
        const float* w = mw2 + (size_t)n * HMOD * MOD_OUT + tid;
        float acc = mb2[n * MOD_OUT + tid];
        #pragma unroll 8
        for (int k = 0; k < HMOD; k++) acc = fmaf(phh[k], w[k * MOD_OUT], acc);
        mod[bn * MOD_OUT + tid] = acc;
    }
}

// ---------------------------------------------------------------------------
// Launch
// ---------------------------------------------------------------------------
extern "C" void kernel_launch(void* const* d_in, const int* in_sizes, int n_in,
                              void* d_out, int out_size)
{
    const float* h      = (const float*)d_in[0];
    const float* w_conn = (const float*)d_in[1];
    const float* ctx    = (const float*)d_in[2];
    const float* nid    = (const float*)d_in[3];
    const float* mw1    = (const float*)d_in[4];
    const float* mb1    = (const float*)d_in[5];
    const float* mw2    = (const float*)d_in[6];
    const float* mb2    = (const float*)d_in[7];
    const float* sw1    = (const float*)d_in[8];
    const float* sb1    = (const float*)d_in[9];
    const float* sw2    = (const float*)d_in[10];
    const float* sb2    = (const float*)d_in[11];
    const float* modw1  = (const float*)d_in[12];
    const float* modb1  = (const float*)d_in[13];
    const float* modw2  = (const float*)d_in[14];
    const float* modb2  = (const float*)d_in[15];
    const int*   conn   = (const int*)d_in[16];
    const int*   c2g    = (const int*)d_in[17];

    float* out   = (float*)d_out;
    float* o_h   = out;
    float* o_msg = out + (size_t)Bb * NC * CN * DN;
    float* o_mod = o_msg + (size_t)Bb * NC * CN * DN;

    const int grid = Bb * NC;  // 512

    static bool attr_done = false;
    if (!attr_done) {
        cudaFuncSetAttribute(agg_kernel, cudaFuncAttributeMaxDynamicSharedMemorySize, SMEM_AGG);
        cudaFuncSetAttribute(fused_mlp_kernel, cudaFuncAttributeMaxDynamicSharedMemorySize, SMEM_MLP);
        attr_done = true;
    }

    agg_kernel<<<grid, 512, SMEM_AGG>>>(h, w_conn, conn);
    fused_mlp_kernel<<<grid, 256, SMEM_MLP>>>(h, ctx, nid, mw1, mb1, mw2, mb2,
                                              sw1, sb1, sw2, sb2, c2g, o_msg, o_h);
    mod_kernel<<<grid, 128>>>(modw1, modb1, modw2, modb2, o_mod);
}

// round 13
// speedup vs baseline: 3.2639x; 1.0131x over previous
#include <cuda_runtime.h>
#include <cuda_bf16.h>
#include <cstdint>

typedef unsigned long long u64;

// Problem constants
constexpr int Bb  = 2;
constexpr int NC  = 256;
constexpr int CN  = 256;
constexpr int K   = 16;
constexpr int DN  = 64;
constexpr int HM  = 128;
constexpr int F   = 192;
constexpr int HMOD = 64;
constexpr int MOD_OUT = 5;

// Scratch
__device__ float g_agg[(size_t)Bb * NC * CN * DN];
__device__ float g_pooled[(size_t)Bb * NC * 2 * DN];

// ---------------- SMEM layout (bytes), bf16 operands -----------------------
constexpr int OFF_TMEM  = 0;
constexpr int OFF_MBARA = 8;
constexpr int OFF_MBARB = 16;
constexpr int OFF_MBARC = 24;
constexpr int OFF_B1M   = 32;     // 128 f
constexpr int OFF_B2M   = 544;    // 64 f
constexpr int OFF_B1SS  = 800;    // 128 f
constexpr int OFF_B2SS  = 1312;   // 64 f
constexpr int OFF_POOL  = 1568;   // 128 f
constexpr int OFF_AH    = 3072;            // 16KB
constexpr int OFF_AL    = 3072 + 16384;    // 16KB
constexpr int OFF_BH    = 3072 + 32768;    // 32KB
constexpr int OFF_BL    = 3072 + 65536;    // 32KB
constexpr int SMEM_MLP  = 3072 + 98304;    // 101376 B -> 2 CTAs/SM

constexpr int SMEM_AGG  = 65536 + 16384 + 16384;   // 98304 B

#if defined(__CUDA_ARCH_FEAT_SM103_ALL) || defined(__CUDA_ARCH_FEAT_SM100_ALL) || defined(__CUDA_ARCH_FEAT_SM101_ALL)
#define HAS_TCGEN05 1
#else
#define HAS_TCGEN05 0
#endif

__device__ __forceinline__ uint32_t smem_u32(const void* p) {
    uint32_t a;
    asm("{ .reg .u64 t; cvta.to.shared.u64 t, %1; cvt.u32.u64 %0, t; }"
        : "=r"(a) : "l"(p));
    return a;
}

#if HAS_TCGEN05
__device__ __forceinline__ uint32_t elect1() {
    uint32_t p;
    asm volatile("{ .reg .pred p; elect.sync _|p, 0xFFFFFFFF; selp.b32 %0, 1, 0, p; }"
                 : "=r"(p));
    return p;
}

#define TC_ALLOC(smem_addr, n) \
    asm volatile("tcgen05.alloc.cta_group::1.sync.aligned.shared::cta.b32 [%0], %1;" \
                 :: "r"((uint32_t)(smem_addr)), "r"((uint32_t)(n)) : "memory")
#define TC_RELINQ() \
    asm volatile("tcgen05.relinquish_alloc_permit.cta_group::1.sync.aligned;")
#define TC_DEALLOC(tmem, n) \
    asm volatile("tcgen05.dealloc.cta_group::1.sync.aligned.b32 %0, %1;" \
                 :: "r"(tmem), "r"((uint32_t)(n)))
#define TC_COMMIT(mbar) \
    asm volatile("tcgen05.commit.cta_group::1.mbarrier::arrive::one.shared::cluster.b64 [%0];" \
                 :: "r"((uint32_t)(mbar)) : "memory")
#define TC_FENCE_AFTER()  asm volatile("tcgen05.fence::after_thread_sync;" ::: "memory")
#define TC_WAIT_LD()      asm volatile("tcgen05.wait::ld.sync.aligned;" ::: "memory")

#define LDTM_X32(r, addr) \
    asm volatile( \
        "tcgen05.ld.sync.aligned.32x32b.x32.b32 " \
        "{%0, %1, %2, %3, %4, %5, %6, %7, " \
        " %8, %9, %10, %11, %12, %13, %14, %15, " \
        " %16, %17, %18, %19, %20, %21, %22, %23, " \
        " %24, %25, %26, %27, %28, %29, %30, %31}, [%32];" \
        : "=r"((r)[0]),  "=r"((r)[1]),  "=r"((r)[2]),  "=r"((r)[3]), \
          "=r"((r)[4]),  "=r"((r)[5]),  "=r"((r)[6]),  "=r"((r)[7]), \
          "=r"((r)[8]),  "=r"((r)[9]),  "=r"((r)[10]), "=r"((r)[11]), \
          "=r"((r)[12]), "=r"((r)[13]), "=r"((r)[14]), "=r"((r)[15]), \
          "=r"((r)[16]), "=r"((r)[17]), "=r"((r)[18]), "=r"((r)[19]), \
          "=r"((r)[20]), "=r"((r)[21]), "=r"((r)[22]), "=r"((r)[23]), \
          "=r"((r)[24]), "=r"((r)[25]), "=r"((r)[26]), "=r"((r)[27]), \
          "=r"((r)[28]), "=r"((r)[29]), "=r"((r)[30]), "=r"((r)[31]) \
        : "r"(addr))

__device__ __forceinline__ void mma_bf16_ss(uint32_t d_tmem, u64 a_desc, u64 b_desc,
                                            uint32_t idesc, uint32_t enable) {
    asm volatile(
        "{\n\t"
        ".reg .pred p;\n\t"
        "setp.ne.u32 p, %4, 0;\n\t"
        "tcgen05.mma.cta_group::1.kind::f16 [%0], %1, %2, %3, {%5, %5, %5, %5}, p;\n\t"
        "}"
        :: "r"(d_tmem), "l"(a_desc), "l"(b_desc), "r"(idesc), "r"(enable), "r"(0u)
        : "memory");
}
#endif  // HAS_TCGEN05

#define MBAR_INIT(mbar, cnt) \
    asm volatile("mbarrier.init.shared.b64 [%0], %1;" \
                 :: "r"((uint32_t)(mbar)), "r"((uint32_t)(cnt)) : "memory")

#define MBAR_WAIT(mbar, parity) do {                                           \
    uint32_t _m = (uint32_t)(mbar), _p = (uint32_t)(parity), _d;               \
    asm volatile("{ .reg .pred p;"                                             \
        " mbarrier.try_wait.parity.acquire.cta.shared::cta.b64 p, [%1], %2;"   \
        " selp.b32 %0, 1, 0, p; }" : "=r"(_d) : "r"(_m), "r"(_p) : "memory");  \
    while (!_d) {                                                              \
        asm volatile("{ .reg .pred p;"                                         \
            " mbarrier.try_wait.parity.acquire.cta.shared::cta.b64 p, [%1], %2, 0x989680;" \
            " selp.b32 %0, 1, 0, p; }" : "=r"(_d) : "r"(_m), "r"(_p) : "memory"); \
    }                                                                          \
} while (0)

constexpr u64 DESC_BASE = (2ull << 61) | (1ull << 46) | (64ull << 32) | (1ull << 16);
__device__ __forceinline__ u64 mk_desc(uint32_t addr) {
    return DESC_BASE | ((u64)(addr >> 4) & 0x3FFF);
}

// Blocked-atom + SW128 byte offset for bf16 tiles. atom = 8 rows x 64 bf16 (128B).
__device__ __forceinline__ uint32_t tile_off2(int row, int k, int atom_rows) {
    uint32_t o = ((uint32_t)((k >> 6) * atom_rows + (row >> 3)) << 10)
               + ((uint32_t)(row & 7) << 7) + ((uint32_t)(k & 63) << 1);
    return o ^ ((o >> 3) & 0x70);
}

__device__ __forceinline__ void split_sts2(char* smem, uint32_t off_hi, uint32_t lo_delta,
                                           float4 v) {
    __nv_bfloat162 h0 = __floats2bfloat162_rn(v.x, v.y);
    __nv_bfloat162 h1 = __floats2bfloat162_rn(v.z, v.w);
    float lx = v.x - __bfloat162float(__low2bfloat16(h0));
    float ly = v.y - __bfloat162float(__high2bfloat16(h0));
    float lz = v.z - __bfloat162float(__low2bfloat16(h1));
    float lw = v.w - __bfloat162float(__high2bfloat16(h1));
    __nv_bfloat162 l0 = __floats2bfloat162_rn(lx, ly);
    __nv_bfloat162 l1 = __floats2bfloat162_rn(lz, lw);
    uint2 hv, lv;
    hv.x = *reinterpret_cast<uint32_t*>(&h0);
    hv.y = *reinterpret_cast<uint32_t*>(&h1);
    lv.x = *reinterpret_cast<uint32_t*>(&l0);
    lv.y = *reinterpret_cast<uint32_t*>(&l1);
    *reinterpret_cast<uint2*>(smem + off_hi)            = hv;
    *reinterpret_cast<uint2*>(smem + off_hi + lo_delta) = lv;
}

__device__ __forceinline__ float gelu_f(float x) {
    float x3 = x * x * x;
    return 0.5f * x * (1.0f + tanhf(0.7978845608028654f * (x + 0.044715f * x3)));
}

__device__ __forceinline__ float gelu_fast(float x) {
    float z = x + 0.044715f * x * x * x;
    float a = 2.3022081852f * z;
    float e;
    asm("ex2.approx.f32 %0, %1;" : "=f"(e) : "f"(a));
    float r;
    asm("rcp.approx.f32 %0, %1;" : "=f"(r) : "f"(e + 1.0f));
    return x - x * r;
}

constexpr uint32_t ID_BF = (1u << 4) | (1u << 7) | (1u << 10) | (8u << 17) | (8u << 24);

// ---------------------------------------------------------------------------
// Kernel 1: connection-weighted aggregation. 4 c-streams per warp iteration.
// ---------------------------------------------------------------------------
__global__ __launch_bounds__(512) void agg_kernel(
    const float* __restrict__ h,
    const float* __restrict__ w_conn,
    const int*   __restrict__ conn)
{
    extern __shared__ float smf[];
    int*   ci_sm = (int*)(smf + CN * DN);
    float* wc_sm = (float*)(ci_sm + CN * K);

    int bn   = blockIdx.x;
    int n    = bn & (NC - 1);
    int tid  = threadIdx.x;
    int wid  = tid >> 5;
    int lane = tid & 31;

    const float4* hg = reinterpret_cast<const float4*>(h) + (size_t)bn * CN * DN / 4;
    float4* h_sm4 = reinterpret_cast<float4*>(smf);
    #pragma unroll
    for (int p = 0; p < 8; p++) h_sm4[p * 512 + tid] = hg[p * 512 + tid];

    const int4*   cg4 = reinterpret_cast<const int4*>(conn   + (size_t)n  * CN * K);
    const float4* wg4 = reinterpret_cast<const float4*>(w_conn + (size_t)bn * CN * K);
    int4*   ci4 = reinterpret_cast<int4*>(ci_sm);
    float4* wc4 = reinterpret_cast<float4*>(wc_sm);
    #pragma unroll
    for (int p = 0; p < 2; p++) {
        ci4[p * 512 + tid] = cg4[p * 512 + tid];
        wc4[p * 512 + tid] = wg4[p * 512 + tid];
    }
    __syncthreads();

    // 16 warps x 4 iterations x 4 c = 256 c
    #pragma unroll
    for (int it = 0; it < 4; it++) {
        int c0 = wid * 16 + it * 4;
        const int*   ci0 = ci_sm + c0 * K;
        const float* wc0 = wc_sm + c0 * K;

        float2 a0 = {0,0}, a1 = {0,0}, a2 = {0,0}, a3 = {0,0};
        const float* hl = smf + lane * 2;
        #pragma unroll
        for (int k = 0; k < K; k++) {
            int i0 = ci0[k], i1 = ci0[K + k], i2 = ci0[2 * K + k], i3 = ci0[3 * K + k];
            float w0 = wc0[k], w1 = wc0[K + k], w2 = wc0[2 * K + k], w3 = wc0[3 * K + k];
            float2 v0 = *reinterpret_cast<const float2*>(hl + (size_t)i0 * DN);
            float2 v1 = *reinterpret_cast<const float2*>(hl + (size_t)i1 * DN);
            float2 v2 = *reinterpret_cast<const float2*>(hl + (size_t)i2 * DN);
            float2 v3 = *reinterpret_cast<const float2*>(hl + (size_t)i3 * DN);
            a0.x = fmaf(w0, v0.x, a0.x); a0.y = fmaf(w0, v0.y, a0.y);
            a1.x = fmaf(w1, v1.x, a1.x); a1.y = fmaf(w1, v1.y, a1.y);
            a2.x = fmaf(w2, v2.x, a2.x); a2.y = fmaf(w2, v2.y, a2.y);
            a3.x = fmaf(w3, v3.x, a3.x); a3.y = fmaf(w3, v3.y, a3.y);
        }
        float* out = g_agg + ((size_t)bn * CN + c0) * DN + lane * 2;
        *reinterpret_cast<float2*>(out)          = a0;
        *reinterpret_cast<float2*>(out + DN)     = a1;
        *reinterpret_cast<float2*>(out + 2 * DN) = a2;
        *reinterpret_cast<float2*>(out + 3 * DN) = a3;
    }
}

#if HAS_TCGEN05
// GEMM1 MMA for one K=64 tile: D1[j=128][c=256] over 4 N=64 chunks.
__device__ __forceinline__ void gemm1_mma(uint32_t sbase, uint32_t tmem, bool first) {
    u64 dah = mk_desc(sbase + OFF_AH), dal = mk_desc(sbase + OFF_AL);
    u64 dbh = mk_desc(sbase + OFF_BH), dbl = mk_desc(sbase + OFF_BL);
    if (elect1()) {
        #pragma unroll
        for (int pass = 0; pass < 3; pass++) {
            u64 da = (pass == 2) ? dal : dah;
            u64 db = (pass == 1) ? dbl : dbh;
            #pragma unroll
            for (int q = 0; q < 4; q++) {
                #pragma unroll
                for (int s = 0; s < 4; s++) {
                    u64 oa = (u64)(s * 2);
                    u64 ob = (u64)(s * 2 + q * 512);
                    mma_bf16_ss(tmem + q * 64, da + oa, db + ob, ID_BF,
                                (first && pass == 0 && s == 0) ? 0u : 1u);
                }
            }
        }
        TC_COMMIT(sbase + OFF_MBARA);
    }
}

// GEMM2 phase: hidden = gelu(D1 + b1) -> B buffers; D2 in consumed D1 cols
// (ch0 -> 0..63, ch1 -> 64..127). ch1-q0 LDTM+gelu overlaps the ch0 MMA.
__device__ __forceinline__ void gemm2_phase(
    char* smem, uint32_t sbase, uint32_t tmem,
    int wid, int lane, int sub, int cgrp2, float bj1, uint32_t parity)
{
    int j = sub * 32 + lane;
    // epilogue ch0 (both q)
    #pragma unroll
    for (int q = 0; q < 2; q++) {
        int cg = cgrp2 * 2 + q;
        uint32_t r0[32];
        LDTM_X32(r0, tmem + cg * 32);
        TC_WAIT_LD();
        #pragma unroll
        for (int i2 = 0; i2 < 32; i2++) {
            float v = gelu_fast(__uint_as_float(r0[i2]) + bj1);
            __nv_bfloat16 hb = __float2bfloat16(v);
            __nv_bfloat16 lb = __float2bfloat16(v - __bfloat162float(hb));
            uint32_t off = tile_off2(cg * 32 + i2, j, 16);
            *reinterpret_cast<__nv_bfloat16*>(smem + OFF_BH + off) = hb;
            *reinterpret_cast<__nv_bfloat16*>(smem + OFF_BL + off) = lb;
        }
    }
    asm volatile("fence.proxy.async.shared::cta;" ::: "memory");
    __syncthreads();

    if (wid == 0) {
        u64 dah = mk_desc(sbase + OFF_BH), dal = mk_desc(sbase + OFF_BL);
        u64 dbh = mk_desc(sbase + OFF_AH), dbl = mk_desc(sbase + OFF_AL);
        if (elect1()) {
            #pragma unroll
            for (int pass = 0; pass < 3; pass++) {
                u64 da = (pass == 2) ? dal : dah;
                u64 db = (pass == 1) ? dbl : dbh;
                #pragma unroll
                for (int s = 0; s < 8; s++) {
                    u64 oa = (u64)((s >> 2) * 1024 + (s & 3) * 2);
                    u64 ob = (u64)((s >> 2) * 512  + (s & 3) * 2);
                    mma_bf16_ss(tmem + 0, da + oa, db + ob, ID_BF, (pass | s) ? 1u : 0u);
                }
            }
            TC_COMMIT(sbase + OFF_MBARB);
        }
    }

    // overlap: ch1 q0 LDTM+gelu into regs while ch0 MMA runs (disjoint TMEM)
    float fv0[32];
    {
        uint32_t r[32];
        LDTM_X32(r, tmem + 128 + (cgrp2 * 2) * 32);
        TC_WAIT_LD();
        #pragma unroll
        for (int i2 = 0; i2 < 32; i2++)
            fv0[i2] = gelu_fast(__uint_as_float(r[i2]) + bj1);
    }
    MBAR_WAIT(sbase + OFF_MBARB, parity);
    TC_FENCE_AFTER();

    // STS ch1 q0
    {
        int cg = cgrp2 * 2;
        #pragma unroll
        for (int i2 = 0; i2 < 32; i2++) {
            __nv_bfloat16 hb = __float2bfloat16(fv0[i2]);
            __nv_bfloat16 lb = __float2bfloat16(fv0[i2] - __bfloat162float(hb));
            uint32_t off = tile_off2(cg * 32 + i2, j, 16);
            *reinterpret_cast<__nv_bfloat16*>(smem + OFF_BH + off) = hb;
            *reinterpret_cast<__nv_bfloat16*>(smem + OFF_BL + off) = lb;
        }
    }
    // ch1 q1: LDTM + gelu + STS
    {
        int cg = cgrp2 * 2 + 1;
        uint32_t r[32];
        LDTM_X32(r, tmem + 128 + cg * 32);
        TC_WAIT_LD();
        #pragma unroll
        for (int i2 = 0; i2 < 32; i2++) {
            float v = gelu_fast(__uint_as_float(r[i2]) + bj1);
            __nv_bfloat16 hb = __float2bfloat16(v);
            __nv_bfloat16 lb = __float2bfloat16(v - __bfloat162float(hb));
            uint32_t off = tile_off2(cg * 32 + i2, j, 16);
            *reinterpret_cast<__nv_bfloat16*>(smem + OFF_BH + off) = hb;
            *reinterpret_cast<__nv_bfloat16*>(smem + OFF_BL + off) = lb;
        }
    }
    asm volatile("fence.proxy.async.shared::cta;" ::: "memory");
    __syncthreads();

    if (wid == 0) {
        u64 dah = mk_desc(sbase + OFF_BH), dal = mk_desc(sbase + OFF_BL);
        u64 dbh = mk_desc(sbase + OFF_AH), dbl = mk_desc(sbase + OFF_AL);
        if (elect1()) {
            #pragma unroll
            for (int pass = 0; pass < 3; pass++) {
                u64 da = (pass == 2) ? dal : dah;
                u64 db = (pass == 1) ? dbl : dbh;
                #pragma unroll
                for (int s = 0; s < 8; s++) {
                    u64 oa = (u64)((s >> 2) * 1024 + (s & 3) * 2);
                    u64 ob = (u64)((s >> 2) * 512  + (s & 3) * 2);
                    mma_bf16_ss(tmem + 64, da + oa, db + ob, ID_BF, (pass | s) ? 1u : 0u);
                }
            }
            TC_COMMIT(sbase + OFF_MBARC);
        }
    }
    MBAR_WAIT(sbase + OFF_MBARC, parity);
    TC_FENCE_AFTER();
}
#endif  // HAS_TCGEN05

// ---------------------------------------------------------------------------
// Fused per-(b,n) kernel: 256 threads, 2 CTAs/SM, bf16 3-pass tcgen05.
// ctx folded into state layer-1 bias (rank-1) -> state GEMM1 has 2 K-tiles.
// ---------------------------------------------------------------------------
__global__ __launch_bounds__(256, 2)
void fused_mlp_kernel(
    const float* __restrict__ h,
    const float* __restrict__ ctx,
    const float* __restrict__ nid,
    const float* __restrict__ mw1, const float* __restrict__ mb1,
    const float* __restrict__ mw2, const float* __restrict__ mb2,
    const float* __restrict__ sw1, const float* __restrict__ sb1,
    const float* __restrict__ sw2, const float* __restrict__ sb2,
    const int*   __restrict__ c2g,
    float*       __restrict__ o_msg,
    float*       __restrict__ o_h)
{
    extern __shared__ char smem[];
    uint32_t sbase = smem_u32(smem);

    int tid  = threadIdx.x;
    int wid  = tid >> 5;
    int lane = tid & 31;
    int bn   = blockIdx.x;
    int n    = bn & (NC - 1);
    int g    = c2g[n];

    const float* w1m    = mw1 + (size_t)g * HM * F;
    const float* w2m    = mw2 + (size_t)g * DN * HM;
    const float* w1s    = sw1 + (size_t)g * HM * F;
    const float* w2s    = sw2 + (size_t)g * DN * HM;
    const float* base_h = h + (size_t)bn * CN * DN;
    const float* base_a = g_agg + (size_t)bn * CN * DN;
    const float* base_n = nid + (size_t)n * CN * DN;
    const float* base_c = ctx + (size_t)bn * DN;
    float* pool = (float*)(smem + OFF_POOL);

#if HAS_TCGEN05
    if (wid == 0) {
        TC_ALLOC(sbase + OFF_TMEM, 256);
        TC_RELINQ();
    }
    if (tid == 0) {
        MBAR_INIT(sbase + OFF_MBARA, 1);
        MBAR_INIT(sbase + OFF_MBARB, 1);
        MBAR_INIT(sbase + OFF_MBARC, 1);
    }
    if (tid < HM) {
        ((float*)(smem + OFF_B1M))[tid]  = mb1[g * HM + tid];
        ((float*)(smem + OFF_B1SS))[tid] = sb1[g * HM + tid];
    }
    if (tid < DN) {
        ((float*)(smem + OFF_B2M))[tid]  = mb2[g * DN + tid];
        ((float*)(smem + OFF_B2SS))[tid] = sb2[g * DN + tid];
    }
    if (tid < 2 * DN) pool[tid] = 0.0f;
    __syncthreads();

    // rank-1 ctx fold: B1SS[j] += dot(W1s[j][128:192], ctx)  (fp32, exact)
    {
        int jr = tid >> 1, fh = tid & 1;
        const float* wr = w1s + (size_t)jr * F + 128 + fh * 32;
        const float* cx = base_c + fh * 32;
        float partial = 0.0f;
        #pragma unroll
        for (int f = 0; f < 32; f++) partial = fmaf(wr[f], cx[f], partial);
        partial += __shfl_xor_sync(0xFFFFFFFFu, partial, 1);
        if (fh == 0) ((float*)(smem + OFF_B1SS))[jr] += partial;
    }

    uint32_t tmem;
    asm("ld.shared.b32 %0, [%1];" : "=r"(tmem) : "r"(sbase + OFF_TMEM));

    uint32_t ph = 0;
    int sub   = wid & 3;
    int cgrp2 = wid >> 2;
    int j     = sub * 32 + lane;

    // ===================== MSG GEMM1 (3 K-tiles of 64) =====================
    for (int t = 0; t < 3; t++) {
        if (t > 0) { MBAR_WAIT(sbase + OFF_MBARA, ph); ph ^= 1; TC_FENCE_AFTER(); }
        #pragma unroll
        for (int p = 0; p < 8; p++) {
            int i = p * 256 + tid; int r = i >> 4, k4 = i & 15;
            float4 v = *reinterpret_cast<const float4*>(w1m + (size_t)r * F + t * 64 + k4 * 4);
            split_sts2(smem, OFF_AH + tile_off2(r, k4 * 4, 16), 16384, v);
        }
        #pragma unroll
        for (int p = 0; p < 16; p++) {
            int i = p * 256 + tid; int r = i >> 4, k4 = i & 15;
            float4 v;
            if (t == 0)      v = *reinterpret_cast<const float4*>(base_h + (size_t)r * DN + k4 * 4);
            else if (t == 1) v = *reinterpret_cast<const float4*>(base_a + (size_t)r * DN + k4 * 4);
            else             v = *reinterpret_cast<const float4*>(base_n + (size_t)r * DN + k4 * 4);
            split_sts2(smem, OFF_BH + tile_off2(r, k4 * 4, 32), 32768, v);
        }
        asm volatile("fence.proxy.async.shared::cta;" ::: "memory");
        __syncthreads();
        if (wid == 0) gemm1_mma(sbase, tmem, t == 0);
    }
    MBAR_WAIT(sbase + OFF_MBARA, ph); ph ^= 1;
    TC_FENCE_AFTER();

    // ===================== MSG GEMM2 =====================
    #pragma unroll
    for (int p = 0; p < 8; p++) {
        int i = p * 256 + tid; int r = i >> 5, k4 = i & 31;
        float4 v = *reinterpret_cast<const float4*>(w2m + (size_t)r * HM + k4 * 4);
        split_sts2(smem, OFF_AH + tile_off2(r, k4 * 4, 8), 16384, v);
    }
    float bj1m = ((float*)(smem + OFF_B1M))[j];
    gemm2_phase(smem, sbase, tmem, wid, lane, sub, cgrp2, bj1m, 0);

    // ---- msg epilogue: D2 -> o_msg, pooled, state feat tile in B ----
    #pragma unroll
    for (int q = 0; q < 2; q++) {
        int cgrp = cgrp2 * 2 + q;
        int ch   = cgrp >> 1;
        int jh2  = cgrp & 1;
        uint32_t r[32];
        LDTM_X32(r, tmem + ch * 64 + jh2 * 32);
        TC_WAIT_LD();
        int c  = ch * 128 + sub * 32 + lane;
        int jb = jh2 * 32;
        const float* b2s = (float*)(smem + OFF_B2M);
        float mv[32];
        #pragma unroll
        for (int i2 = 0; i2 < 32; i2++)
            mv[i2] = __uint_as_float(r[i2]) + b2s[jb + i2];
        float* op = o_msg + ((size_t)bn * CN + c) * DN + jb;
        #pragma unroll
        for (int i4 = 0; i4 < 8; i4++)
            *reinterpret_cast<float4*>(op + i4 * 4) =
                make_float4(mv[i4 * 4], mv[i4 * 4 + 1], mv[i4 * 4 + 2], mv[i4 * 4 + 3]);
        #pragma unroll
        for (int i2 = 0; i2 < 32; i2++) {
            __nv_bfloat16 hb = __float2bfloat16(mv[i2]);
            __nv_bfloat16 lb = __float2bfloat16(mv[i2] - __bfloat162float(hb));
            uint32_t off = tile_off2(c, jb + i2, 32);
            *reinterpret_cast<__nv_bfloat16*>(smem + OFF_BH + off) = hb;
            *reinterpret_cast<__nv_bfloat16*>(smem + OFF_BL + off) = lb;
        }
        float psum = 0.0f;
        #pragma unroll
        for (int i2 = 0; i2 < 32; i2++) {
            float v = mv[i2];
            v += __shfl_xor_sync(0xFFFFFFFFu, v, 16);
            v += __shfl_xor_sync(0xFFFFFFFFu, v, 8);
            v += __shfl_xor_sync(0xFFFFFFFFu, v, 4);
            v += __shfl_xor_sync(0xFFFFFFFFu, v, 2);
            v += __shfl_xor_sync(0xFFFFFFFFu, v, 1);
            if (lane == i2) psum = v;
        }
        atomicAdd(&pool[DN + jb + lane], psum);
    }
    asm volatile("fence.proxy.async.shared::cta;" ::: "memory");
    __syncthreads();

    // ===================== STATE GEMM1 (2 K-tiles: msg, h) =====================
    // t0: B = msg tile (already staged), A = W1s cols 64:128
    #pragma unroll
    for (int p = 0; p < 8; p++) {
        int i = p * 256 + tid; int r = i >> 4, k4 = i & 15;
        float4 v = *reinterpret_cast<const float4*>(w1s + (size_t)r * F + 64 + k4 * 4);
        split_sts2(smem, OFF_AH + tile_off2(r, k4 * 4, 16), 16384, v);
    }
    asm volatile("fence.proxy.async.shared::cta;" ::: "memory");
    __syncthreads();
    if (wid == 0) gemm1_mma(sbase, tmem, true);

    // t1: A = W1s cols 0:64, B = h
    MBAR_WAIT(sbase + OFF_MBARA, ph); ph ^= 1; TC_FENCE_AFTER();
    #pragma unroll
    for (int p = 0; p < 8; p++) {
        int i = p * 256 + tid; int r = i >> 4, k4 = i & 15;
        float4 v = *reinterpret_cast<const float4*>(w1s + (size_t)r * F + k4 * 4);
        split_sts2(smem, OFF_AH + tile_off2(r, k4 * 4, 16), 16384, v);
    }
    #pragma unroll
    for (int p = 0; p < 16; p++) {
        int i = p * 256 + tid; int r = i >> 4, k4 = i & 15;
        float4 v = *reinterpret_cast<const float4*>(base_h + (size_t)r * DN + k4 * 4);
        split_sts2(smem, OFF_BH + tile_off2(r, k4 * 4, 32), 32768, v);
    }
    asm volatile("fence.proxy.async.shared::cta;" ::: "memory");
    __syncthreads();
    if (wid == 0) gemm1_mma(sbase, tmem, false);
    MBAR_WAIT(sbase + OFF_MBARA, ph); ph ^= 1;
    TC_FENCE_AFTER();

    // ===================== STATE GEMM2 =====================
    #pragma unroll
    for (int p = 0; p < 8; p++) {
        int i = p * 256 + tid; int r = i >> 5, k4 = i & 31;
        float4 v = *reinterpret_cast<const float4*>(w2s + (size_t)r * HM + k4 * 4);
        split_sts2(smem, OFF_AH + tile_off2(r, k4 * 4, 8), 16384, v);
    }
    float bj1s = ((float*)(smem + OFF_B1SS))[j];
    gemm2_phase(smem, sbase, tmem, wid, lane, sub, cgrp2, bj1s, 1);

    // ---- state epilogue: D2 + b2s + h residual -> o_h, pooled ----
    #pragma unroll
    for (int q = 0; q < 2; q++) {
        int cgrp = cgrp2 * 2 + q;
        int ch   = cgrp >> 1;
        int jh2  = cgrp & 1;
        uint32_t r[32];
        LDTM_X32(r, tmem + ch * 64 + jh2 * 32);
        TC_WAIT_LD();
        int c  = ch * 128 + sub * 32 + lane;
        int jb = jh2 * 32;
        const float* b2s = (float*)(smem + OFF_B2SS);
        const float* hp = base_h + (size_t)c * DN + jb;
        float hv[32];
        #pragma unroll
        for (int i4 = 0; i4 < 8; i4++) {
            float4 hr = *reinterpret_cast<const float4*>(hp + i4 * 4);
            hv[i4 * 4 + 0] = __uint_as_float(r[i4 * 4 + 0]) + b2s[jb + i4 * 4 + 0] + hr.x;
            hv[i4 * 4 + 1] = __uint_as_float(r[i4 * 4 + 1]) + b2s[jb + i4 * 4 + 1] + hr.y;
            hv[i4 * 4 + 2] = __uint_as_float(r[i4 * 4 + 2]) + b2s[jb + i4 * 4 + 2] + hr.z;
            hv[i4 * 4 + 3] = __uint_as_float(r[i4 * 4 + 3]) + b2s[jb + i4 * 4 + 3] + hr.w;
        }
        float* op = o_h + ((size_t)bn * CN + c) * DN + jb;
        #pragma unroll
        for (int i4 = 0; i4 < 8; i4++)
            *reinterpret_cast<float4*>(op + i4 * 4) =
                make_float4(hv[i4 * 4], hv[i4 * 4 + 1], hv[i4 * 4 + 2], hv[i4 * 4 + 3]);
        float psum = 0.0f;
        #pragma unroll
        for (int i2 = 0; i2 < 32; i2++) {
            float v = hv[i2];
            v += __shfl_xor_sync(0xFFFFFFFFu, v, 16);
            v += __shfl_xor_sync(0xFFFFFFFFu, v, 8);
            v += __shfl_xor_sync(0xFFFFFFFFu, v, 4);
            v += __shfl_xor_sync(0xFFFFFFFFu, v, 2);
            v += __shfl_xor_sync(0xFFFFFFFFu, v, 1);
            if (lane == i2) psum = v;
        }
        atomicAdd(&pool[jb + lane], psum);
    }

    __syncthreads();
    if (tid < 2 * DN)
        g_pooled[(size_t)bn * 2 * DN + tid] = pool[tid] * (1.0f / CN);
    if (wid == 0) TC_DEALLOC(tmem, 256);

#else  // ---------------- SIMT fallback (plain compute_103 pass only) -------
    float* Hs = (float*)(smem + OFF_AH);   // [128][HM], two c-halves
    if (tid < 2 * DN) pool[tid] = 0.0f;
    __syncthreads();

    for (int half = 0; half < 2; half++) {
        int cb = half * 128;
        for (int idx = tid; idx < 128 * HM; idx += 256) {
            int c = cb + (idx >> 7), jj = idx & 127;
            float acc = mb1[g * HM + jj];
            const float* wr = w1m + (size_t)jj * F;
            for (int f = 0; f < DN; f++) acc = fmaf(wr[f],       base_h[(size_t)c * DN + f], acc);
            for (int f = 0; f < DN; f++) acc = fmaf(wr[64 + f],  base_a[(size_t)c * DN + f], acc);
            for (int f = 0; f < DN; f++) acc = fmaf(wr[128 + f], base_n[(size_t)c * DN + f], acc);
            Hs[idx] = gelu_f(acc);
        }
        __syncthreads();
        for (int idx = tid; idx < 128 * DN; idx += 256) {
            int c = cb + (idx >> 6), j2 = idx & 63;
            float acc = mb2[g * DN + j2];
            const float* wr = w2m + (size_t)j2 * HM;
            const float* hr = Hs + (size_t)(idx >> 6) * HM;
            for (int k = 0; k < HM; k++) acc = fmaf(wr[k], hr[k], acc);
            o_msg[((size_t)bn * CN + c) * DN + j2] = acc;
            atomicAdd(&pool[DN + j2], acc);
        }
        __syncthreads();
    }
    for (int half = 0; half < 2; half++) {
        int cb = half * 128;
        for (int idx = tid; idx < 128 * HM; idx += 256) {
            int c = cb + (idx >> 7), jj = idx & 127;
            float acc = sb1[g * HM + jj];
            const float* wr = w1s + (size_t)jj * F;
            for (int f = 0; f < DN; f++) acc = fmaf(wr[f],       base_h[(size_t)c * DN + f], acc);
            for (int f = 0; f < DN; f++) acc = fmaf(wr[64 + f],  o_msg[((size_t)bn * CN + c) * DN + f], acc);
            for (int f = 0; f < DN; f++) acc = fmaf(wr[128 + f], base_c[f], acc);
            Hs[idx] = gelu_f(acc);
        }
        __syncthreads();
        for (int idx = tid; idx < 128 * DN; idx += 256) {
            int c = cb + (idx >> 6), j2 = idx & 63;
            float acc = sb2[g * DN + j2];
            const float* wr = w2s + (size_t)j2 * HM;
            const float* hr = Hs + (size_t)(idx >> 6) * HM;
            for (int k = 0; k < HM; k++) acc = fmaf(wr[k], hr[k], acc);
            acc += base_h[(size_t)c * DN + j2];
            o_h[((size_t)bn * CN + c) * DN + j2] = acc;
            atomicAdd(&pool[j2], acc);
        }
        __syncthreads();
    }
    if (tid < 2 * DN)
        g_pooled[(size_t)bn * 2 * DN + tid] = pool[tid] * (1.0f / CN);
#endif
}

// ---------------------------------------------------------------------------
// Slim modulation MLP: reads pooled stats only.
// ---------------------------------------------------------------------------
__global__ __launch_bounds__(128) void mod_kernel(
    const float* __restrict__ mw1,
    const float* __restrict__ mb1,
    const float* __restrict__ mw2,
    const float* __restrict__ mb2,
    float*       __restrict__ mod)
{
    __shared__ float pooled[2 * DN];
    __shared__ float phh[HMOD];

    int bn  = blockIdx.x;
    int n   = bn & (NC - 1);
    int tid = threadIdx.x;

    if (tid < 2 * DN) pooled[tid] = g_pooled[(size_t)bn * 2 * DN + tid];
    __syncthreads();

    if (tid < HMOD) {
        const float* w = mw1 + (size_t)n * (2 * DN) * HMOD + tid;
        float acc = mb1[n * HMOD + tid];
        #pragma unroll 8
        for (int f = 0; f < 2 * DN; f++) acc = fmaf(pooled[f], w[f * HMOD], acc);
        phh[tid] = gelu_f(acc);
    }
    __syncthreads();

    if (tid < MOD_OUT) {
        const float* w = mw2 + (size_t)n * HMOD * MOD_OUT + tid;
        float acc = mb2[n * MOD_OUT + tid];
        #pragma unroll 8
        for (int k = 0; k < HMOD; k++) acc = fmaf(phh[k], w[k * MOD_OUT], acc);
        mod[bn * MOD_OUT + tid] = acc;
    }
}

// ---------------------------------------------------------------------------
// Launch
// ---------------------------------------------------------------------------
extern "C" void kernel_launch(void* const* d_in, const int* in_sizes, int n_in,
                              void* d_out, int out_size)
{
    const float* h      = (const float*)d_in[0];
    const float* w_conn = (const float*)d_in[1];
    const float* ctx    = (const float*)d_in[2];
    const float* nid    = (const float*)d_in[3];
    const float* mw1    = (const float*)d_in[4];
    const float* mb1    = (const float*)d_in[5];
    const float* mw2    = (const float*)d_in[6];
    const float* mb2    = (const float*)d_in[7];
    const float* sw1    = (const float*)d_in[8];
    const float* sb1    = (const float*)d_in[9];
    const float* sw2    = (const float*)d_in[10];
    const float* sb2    = (const float*)d_in[11];
    const float* modw1  = (const float*)d_in[12];
    const float* modb1  = (const float*)d_in[13];
    const float* modw2  = (const float*)d_in[14];
    const float* modb2  = (const float*)d_in[15];
    const int*   conn   = (const int*)d_in[16];
    const int*   c2g    = (const int*)d_in[17];

    float* out   = (float*)d_out;
    float* o_h   = out;
    float* o_msg = out + (size_t)Bb * NC * CN * DN;
    float* o_mod = o_msg + (size_t)Bb * NC * CN * DN;

    const int grid = Bb * NC;  // 512

    static bool attr_done = false;
    if (!attr_done) {
        cudaFuncSetAttribute(agg_kernel, cudaFuncAttributeMaxDynamicSharedMemorySize, SMEM_AGG);
        cudaFuncSetAttribute(fused_mlp_kernel, cudaFuncAttributeMaxDynamicSharedMemorySize, SMEM_MLP);
        attr_done = true;
    }

    agg_kernel<<<grid, 512, SMEM_AGG>>>(h, w_conn, conn);
    fused_mlp_kernel<<<grid, 256, SMEM_MLP>>>(h, ctx, nid, mw1, mb1, mw2, mb2,
                                              sw1, sb1, sw2, sb2, c2g, o_msg, o_h);
    mod_kernel<<<grid, 128>>>(modw1, modb1, modw2, modb2, o_mod);
}

// round 14
// speedup vs baseline: 3.2823x; 1.0056x over previous
#include <cuda_runtime.h>
#include <cuda_bf16.h>
#include <cstdint>

typedef unsigned long long u64;

// Problem constants
constexpr int Bb  = 2;
constexpr int NC  = 256;
constexpr int CN  = 256;
constexpr int K   = 16;
constexpr int DN  = 64;
constexpr int HM  = 128;
constexpr int F   = 192;
constexpr int HMOD = 64;
constexpr int MOD_OUT = 5;

// Scratch
__device__ float g_agg[(size_t)Bb * NC * CN * DN];
__device__ float g_pooled[(size_t)Bb * NC * 2 * DN];

// ---------------- SMEM layout (bytes), bf16 operands -----------------------
constexpr int OFF_TMEM  = 0;
constexpr int OFF_MBARA = 8;
constexpr int OFF_MBARB = 16;
constexpr int OFF_MBARC = 24;
constexpr int OFF_B1M   = 32;     // 128 f
constexpr int OFF_B2M   = 544;    // 64 f
constexpr int OFF_B1SS  = 800;    // 128 f
constexpr int OFF_B2SS  = 1312;   // 64 f
constexpr int OFF_POOL  = 1568;   // 128 f
constexpr int OFF_AH    = 3072;            // 16KB
constexpr int OFF_AL    = 3072 + 16384;    // 16KB
constexpr int OFF_BH    = 3072 + 32768;    // 32KB
constexpr int OFF_BL    = 3072 + 65536;    // 32KB
constexpr int SMEM_MLP  = 3072 + 98304;    // 101376 B -> 2 CTAs/SM

constexpr int SMEM_AGG  = 65536 + 16384 + 16384;   // 98304 B

#if defined(__CUDA_ARCH_FEAT_SM103_ALL) || defined(__CUDA_ARCH_FEAT_SM100_ALL) || defined(__CUDA_ARCH_FEAT_SM101_ALL)
#define HAS_TCGEN05 1
#else
#define HAS_TCGEN05 0
#endif

__device__ __forceinline__ uint32_t smem_u32(const void* p) {
    uint32_t a;
    asm("{ .reg .u64 t; cvta.to.shared.u64 t, %1; cvt.u32.u64 %0, t; }"
        : "=r"(a) : "l"(p));
    return a;
}

#if HAS_TCGEN05
__device__ __forceinline__ uint32_t elect1() {
    uint32_t p;
    asm volatile("{ .reg .pred p; elect.sync _|p, 0xFFFFFFFF; selp.b32 %0, 1, 0, p; }"
                 : "=r"(p));
    return p;
}

#define TC_ALLOC(smem_addr, n) \
    asm volatile("tcgen05.alloc.cta_group::1.sync.aligned.shared::cta.b32 [%0], %1;" \
                 :: "r"((uint32_t)(smem_addr)), "r"((uint32_t)(n)) : "memory")
#define TC_RELINQ() \
    asm volatile("tcgen05.relinquish_alloc_permit.cta_group::1.sync.aligned;")
#define TC_DEALLOC(tmem, n) \
    asm volatile("tcgen05.dealloc.cta_group::1.sync.aligned.b32 %0, %1;" \
                 :: "r"(tmem), "r"((uint32_t)(n)))
#define TC_COMMIT(mbar) \
    asm volatile("tcgen05.commit.cta_group::1.mbarrier::arrive::one.shared::cluster.b64 [%0];" \
                 :: "r"((uint32_t)(mbar)) : "memory")
#define TC_FENCE_AFTER()  asm volatile("tcgen05.fence::after_thread_sync;" ::: "memory")
#define TC_WAIT_LD()      asm volatile("tcgen05.wait::ld.sync.aligned;" ::: "memory")

#define LDTM_X32(r, addr) \
    asm volatile( \
        "tcgen05.ld.sync.aligned.32x32b.x32.b32 " \
        "{%0, %1, %2, %3, %4, %5, %6, %7, " \
        " %8, %9, %10, %11, %12, %13, %14, %15, " \
        " %16, %17, %18, %19, %20, %21, %22, %23, " \
        " %24, %25, %26, %27, %28, %29, %30, %31}, [%32];" \
        : "=r"((r)[0]),  "=r"((r)[1]),  "=r"((r)[2]),  "=r"((r)[3]), \
          "=r"((r)[4]),  "=r"((r)[5]),  "=r"((r)[6]),  "=r"((r)[7]), \
          "=r"((r)[8]),  "=r"((r)[9]),  "=r"((r)[10]), "=r"((r)[11]), \
          "=r"((r)[12]), "=r"((r)[13]), "=r"((r)[14]), "=r"((r)[15]), \
          "=r"((r)[16]), "=r"((r)[17]), "=r"((r)[18]), "=r"((r)[19]), \
          "=r"((r)[20]), "=r"((r)[21]), "=r"((r)[22]), "=r"((r)[23]), \
          "=r"((r)[24]), "=r"((r)[25]), "=r"((r)[26]), "=r"((r)[27]), \
          "=r"((r)[28]), "=r"((r)[29]), "=r"((r)[30]), "=r"((r)[31]) \
        : "r"(addr))

__device__ __forceinline__ void mma_bf16_ss(uint32_t d_tmem, u64 a_desc, u64 b_desc,
                                            uint32_t idesc, uint32_t enable) {
    asm volatile(
        "{\n\t"
        ".reg .pred p;\n\t"
        "setp.ne.u32 p, %4, 0;\n\t"
        "tcgen05.mma.cta_group::1.kind::f16 [%0], %1, %2, %3, {%5, %5, %5, %5}, p;\n\t"
        "}"
        :: "r"(d_tmem), "l"(a_desc), "l"(b_desc), "r"(idesc), "r"(enable), "r"(0u)
        : "memory");
}
#endif  // HAS_TCGEN05

#define MBAR_INIT(mbar, cnt) \
    asm volatile("mbarrier.init.shared.b64 [%0], %1;" \
                 :: "r"((uint32_t)(mbar)), "r"((uint32_t)(cnt)) : "memory")

#define MBAR_WAIT(mbar, parity) do {                                           \
    uint32_t _m = (uint32_t)(mbar), _p = (uint32_t)(parity), _d;               \
    asm volatile("{ .reg .pred p;"                                             \
        " mbarrier.try_wait.parity.acquire.cta.shared::cta.b64 p, [%1], %2;"   \
        " selp.b32 %0, 1, 0, p; }" : "=r"(_d) : "r"(_m), "r"(_p) : "memory");  \
    while (!_d) {                                                              \
        asm volatile("{ .reg .pred p;"                                         \
            " mbarrier.try_wait.parity.acquire.cta.shared::cta.b64 p, [%1], %2, 0x989680;" \
            " selp.b32 %0, 1, 0, p; }" : "=r"(_d) : "r"(_m), "r"(_p) : "memory"); \
    }                                                                          \
} while (0)

constexpr u64 DESC_BASE = (2ull << 61) | (1ull << 46) | (64ull << 32) | (1ull << 16);
__device__ __forceinline__ u64 mk_desc(uint32_t addr) {
    return DESC_BASE | ((u64)(addr >> 4) & 0x3FFF);
}

// Blocked-atom + SW128 byte offset for bf16 tiles. atom = 8 rows x 64 bf16 (128B).
__device__ __forceinline__ uint32_t tile_off2(int row, int k, int atom_rows) {
    uint32_t o = ((uint32_t)((k >> 6) * atom_rows + (row >> 3)) << 10)
               + ((uint32_t)(row & 7) << 7) + ((uint32_t)(k & 63) << 1);
    return o ^ ((o >> 3) & 0x70);
}

__device__ __forceinline__ void split_sts2(char* smem, uint32_t off_hi, uint32_t lo_delta,
                                           float4 v) {
    __nv_bfloat162 h0 = __floats2bfloat162_rn(v.x, v.y);
    __nv_bfloat162 h1 = __floats2bfloat162_rn(v.z, v.w);
    float lx = v.x - __bfloat162float(__low2bfloat16(h0));
    float ly = v.y - __bfloat162float(__high2bfloat16(h0));
    float lz = v.z - __bfloat162float(__low2bfloat16(h1));
    float lw = v.w - __bfloat162float(__high2bfloat16(h1));
    __nv_bfloat162 l0 = __floats2bfloat162_rn(lx, ly);
    __nv_bfloat162 l1 = __floats2bfloat162_rn(lz, lw);
    uint2 hv, lv;
    hv.x = *reinterpret_cast<uint32_t*>(&h0);
    hv.y = *reinterpret_cast<uint32_t*>(&h1);
    lv.x = *reinterpret_cast<uint32_t*>(&l0);
    lv.y = *reinterpret_cast<uint32_t*>(&l1);
    *reinterpret_cast<uint2*>(smem + off_hi)            = hv;
    *reinterpret_cast<uint2*>(smem + off_hi + lo_delta) = lv;
}

__device__ __forceinline__ float gelu_f(float x) {
    float x3 = x * x * x;
    return 0.5f * x * (1.0f + tanhf(0.7978845608028654f * (x + 0.044715f * x3)));
}

__device__ __forceinline__ float gelu_fast(float x) {
    float z = x + 0.044715f * x * x * x;
    float a = 2.3022081852f * z;
    float e;
    asm("ex2.approx.f32 %0, %1;" : "=f"(e) : "f"(a));
    float r;
    asm("rcp.approx.f32 %0, %1;" : "=f"(r) : "f"(e + 1.0f));
    return x - x * r;
}

constexpr uint32_t ID_BF = (1u << 4) | (1u << 7) | (1u << 10) | (8u << 17) | (8u << 24);

// ---------------------------------------------------------------------------
// Kernel 1: connection-weighted aggregation (proven; unchanged).
// ---------------------------------------------------------------------------
__global__ __launch_bounds__(512) void agg_kernel(
    const float* __restrict__ h,
    const float* __restrict__ w_conn,
    const int*   __restrict__ conn)
{
    extern __shared__ float smf[];
    int*   ci_sm = (int*)(smf + CN * DN);
    float* wc_sm = (float*)(ci_sm + CN * K);

    int bn   = blockIdx.x;
    int n    = bn & (NC - 1);
    int tid  = threadIdx.x;
    int wid  = tid >> 5;
    int lane = tid & 31;

    const float4* hg = reinterpret_cast<const float4*>(h) + (size_t)bn * CN * DN / 4;
    float4* h_sm4 = reinterpret_cast<float4*>(smf);
    #pragma unroll
    for (int p = 0; p < 8; p++) h_sm4[p * 512 + tid] = hg[p * 512 + tid];

    const int4*   cg4 = reinterpret_cast<const int4*>(conn   + (size_t)n  * CN * K);
    const float4* wg4 = reinterpret_cast<const float4*>(w_conn + (size_t)bn * CN * K);
    int4*   ci4 = reinterpret_cast<int4*>(ci_sm);
    float4* wc4 = reinterpret_cast<float4*>(wc_sm);
    #pragma unroll
    for (int p = 0; p < 2; p++) {
        ci4[p * 512 + tid] = cg4[p * 512 + tid];
        wc4[p * 512 + tid] = wg4[p * 512 + tid];
    }
    __syncthreads();

    #pragma unroll
    for (int it = 0; it < 4; it++) {
        int c0 = wid * 16 + it * 4;
        const int*   ci0 = ci_sm + c0 * K;
        const float* wc0 = wc_sm + c0 * K;

        float2 a0 = {0,0}, a1 = {0,0}, a2 = {0,0}, a3 = {0,0};
        const float* hl = smf + lane * 2;
        #pragma unroll
        for (int k = 0; k < K; k++) {
            int i0 = ci0[k], i1 = ci0[K + k], i2 = ci0[2 * K + k], i3 = ci0[3 * K + k];
            float w0 = wc0[k], w1 = wc0[K + k], w2 = wc0[2 * K + k], w3 = wc0[3 * K + k];
            float2 v0 = *reinterpret_cast<const float2*>(hl + (size_t)i0 * DN);
            float2 v1 = *reinterpret_cast<const float2*>(hl + (size_t)i1 * DN);
            float2 v2 = *reinterpret_cast<const float2*>(hl + (size_t)i2 * DN);
            float2 v3 = *reinterpret_cast<const float2*>(hl + (size_t)i3 * DN);
            a0.x = fmaf(w0, v0.x, a0.x); a0.y = fmaf(w0, v0.y, a0.y);
            a1.x = fmaf(w1, v1.x, a1.x); a1.y = fmaf(w1, v1.y, a1.y);
            a2.x = fmaf(w2, v2.x, a2.x); a2.y = fmaf(w2, v2.y, a2.y);
            a3.x = fmaf(w3, v3.x, a3.x); a3.y = fmaf(w3, v3.y, a3.y);
        }
        float* out = g_agg + ((size_t)bn * CN + c0) * DN + lane * 2;
        *reinterpret_cast<float2*>(out)          = a0;
        *reinterpret_cast<float2*>(out + DN)     = a1;
        *reinterpret_cast<float2*>(out + 2 * DN) = a2;
        *reinterpret_cast<float2*>(out + 3 * DN) = a3;
    }
}

#if HAS_TCGEN05
// GEMM1 MMA for one K=64 tile: D1[j=128][c=256] over 4 N=64 chunks.
__device__ __forceinline__ void gemm1_mma(uint32_t sbase, uint32_t tmem, bool first) {
    u64 dah = mk_desc(sbase + OFF_AH), dal = mk_desc(sbase + OFF_AL);
    u64 dbh = mk_desc(sbase + OFF_BH), dbl = mk_desc(sbase + OFF_BL);
    if (elect1()) {
        #pragma unroll
        for (int pass = 0; pass < 3; pass++) {
            u64 da = (pass == 2) ? dal : dah;
            u64 db = (pass == 1) ? dbl : dbh;
            #pragma unroll
            for (int q = 0; q < 4; q++) {
                #pragma unroll
                for (int s = 0; s < 4; s++) {
                    u64 oa = (u64)(s * 2);
                    u64 ob = (u64)(s * 2 + q * 512);
                    mma_bf16_ss(tmem + q * 64, da + oa, db + ob, ID_BF,
                                (first && pass == 0 && s == 0) ? 0u : 1u);
                }
            }
        }
        TC_COMMIT(sbase + OFF_MBARA);
    }
}

// GEMM2 phase (proven round-13 structure w/ ch1-q0 overlap).
__device__ __forceinline__ void gemm2_phase(
    char* smem, uint32_t sbase, uint32_t tmem,
    int wid, int lane, int sub, int cgrp2, float bj1, uint32_t parity)
{
    int j = sub * 32 + lane;
    #pragma unroll
    for (int q = 0; q < 2; q++) {
        int cg = cgrp2 * 2 + q;
        uint32_t r0[32];
        LDTM_X32(r0, tmem + cg * 32);
        TC_WAIT_LD();
        #pragma unroll
        for (int i2 = 0; i2 < 32; i2++) {
            float v = gelu_fast(__uint_as_float(r0[i2]) + bj1);
            __nv_bfloat16 hb = __float2bfloat16(v);
            __nv_bfloat16 lb = __float2bfloat16(v - __bfloat162float(hb));
            uint32_t off = tile_off2(cg * 32 + i2, j, 16);
            *reinterpret_cast<__nv_bfloat16*>(smem + OFF_BH + off) = hb;
            *reinterpret_cast<__nv_bfloat16*>(smem + OFF_BL + off) = lb;
        }
    }
    asm volatile("fence.proxy.async.shared::cta;" ::: "memory");
    __syncthreads();

    if (wid == 0) {
        u64 dah = mk_desc(sbase + OFF_BH), dal = mk_desc(sbase + OFF_BL);
        u64 dbh = mk_desc(sbase + OFF_AH), dbl = mk_desc(sbase + OFF_AL);
        if (elect1()) {
            #pragma unroll
            for (int pass = 0; pass < 3; pass++) {
                u64 da = (pass == 2) ? dal : dah;
                u64 db = (pass == 1) ? dbl : dbh;
                #pragma unroll
                for (int s = 0; s < 8; s++) {
                    u64 oa = (u64)((s >> 2) * 1024 + (s & 3) * 2);
                    u64 ob = (u64)((s >> 2) * 512  + (s & 3) * 2);
                    mma_bf16_ss(tmem + 0, da + oa, db + ob, ID_BF, (pass | s) ? 1u : 0u);
                }
            }
            TC_COMMIT(sbase + OFF_MBARB);
        }
    }

    float fv0[32];
    {
        uint32_t r[32];
        LDTM_X32(r, tmem + 128 + (cgrp2 * 2) * 32);
        TC_WAIT_LD();
        #pragma unroll
        for (int i2 = 0; i2 < 32; i2++)
            fv0[i2] = gelu_fast(__uint_as_float(r[i2]) + bj1);
    }
    MBAR_WAIT(sbase + OFF_MBARB, parity);
    TC_FENCE_AFTER();

    {
        int cg = cgrp2 * 2;
        #pragma unroll
        for (int i2 = 0; i2 < 32; i2++) {
            __nv_bfloat16 hb = __float2bfloat16(fv0[i2]);
            __nv_bfloat16 lb = __float2bfloat16(fv0[i2] - __bfloat162float(hb));
            uint32_t off = tile_off2(cg * 32 + i2, j, 16);
            *reinterpret_cast<__nv_bfloat16*>(smem + OFF_BH + off) = hb;
            *reinterpret_cast<__nv_bfloat16*>(smem + OFF_BL + off) = lb;
        }
    }
    {
        int cg = cgrp2 * 2 + 1;
        uint32_t r[32];
        LDTM_X32(r, tmem + 128 + cg * 32);
        TC_WAIT_LD();
        #pragma unroll
        for (int i2 = 0; i2 < 32; i2++) {
            float v = gelu_fast(__uint_as_float(r[i2]) + bj1);
            __nv_bfloat16 hb = __float2bfloat16(v);
            __nv_bfloat16 lb = __float2bfloat16(v - __bfloat162float(hb));
            uint32_t off = tile_off2(cg * 32 + i2, j, 16);
            *reinterpret_cast<__nv_bfloat16*>(smem + OFF_BH + off) = hb;
            *reinterpret_cast<__nv_bfloat16*>(smem + OFF_BL + off) = lb;
        }
    }
    asm volatile("fence.proxy.async.shared::cta;" ::: "memory");
    __syncthreads();

    if (wid == 0) {
        u64 dah = mk_desc(sbase + OFF_BH), dal = mk_desc(sbase + OFF_BL);
        u64 dbh = mk_desc(sbase + OFF_AH), dbl = mk_desc(sbase + OFF_AL);
        if (elect1()) {
            #pragma unroll
            for (int pass = 0; pass < 3; pass++) {
                u64 da = (pass == 2) ? dal : dah;
                u64 db = (pass == 1) ? dbl : dbh;
                #pragma unroll
                for (int s = 0; s < 8; s++) {
                    u64 oa = (u64)((s >> 2) * 1024 + (s & 3) * 2);
                    u64 ob = (u64)((s >> 2) * 512  + (s & 3) * 2);
                    mma_bf16_ss(tmem + 64, da + oa, db + ob, ID_BF, (pass | s) ? 1u : 0u);
                }
            }
            TC_COMMIT(sbase + OFF_MBARC);
        }
    }
    MBAR_WAIT(sbase + OFF_MBARC, parity);
    TC_FENCE_AFTER();
}
#endif  // HAS_TCGEN05

// ---------------------------------------------------------------------------
// Fused per-(b,n) kernel: 256 threads, 2 CTAs/SM, bf16 3-pass tcgen05,
// register-prefetched staging (A full + B first half hidden behind MMA waits).
// ---------------------------------------------------------------------------
__global__ __launch_bounds__(256, 2)
void fused_mlp_kernel(
    const float* __restrict__ h,
    const float* __restrict__ ctx,
    const float* __restrict__ nid,
    const float* __restrict__ mw1, const float* __restrict__ mb1,
    const float* __restrict__ mw2, const float* __restrict__ mb2,
    const float* __restrict__ sw1, const float* __restrict__ sb1,
    const float* __restrict__ sw2, const float* __restrict__ sb2,
    const int*   __restrict__ c2g,
    float*       __restrict__ o_msg,
    float*       __restrict__ o_h)
{
    extern __shared__ char smem[];
    uint32_t sbase = smem_u32(smem);

    int tid  = threadIdx.x;
    int wid  = tid >> 5;
    int lane = tid & 31;
    int bn   = blockIdx.x;
    int n    = bn & (NC - 1);
    int g    = c2g[n];

    const float* w1m    = mw1 + (size_t)g * HM * F;
    const float* w2m    = mw2 + (size_t)g * DN * HM;
    const float* w1s    = sw1 + (size_t)g * HM * F;
    const float* w2s    = sw2 + (size_t)g * DN * HM;
    const float* base_h = h + (size_t)bn * CN * DN;
    const float* base_a = g_agg + (size_t)bn * CN * DN;
    const float* base_n = nid + (size_t)n * CN * DN;
    const float* base_c = ctx + (size_t)bn * DN;
    float* pool = (float*)(smem + OFF_POOL);

#if HAS_TCGEN05
    if (wid == 0) {
        TC_ALLOC(sbase + OFF_TMEM, 256);
        TC_RELINQ();
    }
    if (tid == 0) {
        MBAR_INIT(sbase + OFF_MBARA, 1);
        MBAR_INIT(sbase + OFF_MBARB, 1);
        MBAR_INIT(sbase + OFF_MBARC, 1);
    }
    if (tid < HM) {
        ((float*)(smem + OFF_B1M))[tid]  = mb1[g * HM + tid];
        ((float*)(smem + OFF_B1SS))[tid] = sb1[g * HM + tid];
    }
    if (tid < DN) {
        ((float*)(smem + OFF_B2M))[tid]  = mb2[g * DN + tid];
        ((float*)(smem + OFF_B2SS))[tid] = sb2[g * DN + tid];
    }
    if (tid < 2 * DN) pool[tid] = 0.0f;
    __syncthreads();

    // rank-1 ctx fold: B1SS[j] += dot(W1s[j][128:192], ctx)  (fp32, exact)
    {
        int jr = tid >> 1, fh = tid & 1;
        const float* wr = w1s + (size_t)jr * F + 128 + fh * 32;
        const float* cx = base_c + fh * 32;
        float partial = 0.0f;
        #pragma unroll
        for (int f = 0; f < 32; f++) partial = fmaf(wr[f], cx[f], partial);
        partial += __shfl_xor_sync(0xFFFFFFFFu, partial, 1);
        if (fh == 0) ((float*)(smem + OFF_B1SS))[jr] += partial;
    }

    uint32_t tmem;
    asm("ld.shared.b32 %0, [%1];" : "=r"(tmem) : "r"(sbase + OFF_TMEM));

    uint32_t ph = 0;
    int sub   = wid & 3;
    int cgrp2 = wid >> 2;
    int j     = sub * 32 + lane;

    // per-thread staging indices
    const int rA  = tid >> 4, kA = (tid & 15) * 4;     // A/B chunks, rows 0..127 part
    const int rW2 = tid >> 3, kW2 = (tid & 7) * 4;     // unused name guard

    float4 va[8], vbh[8];

    // ---- prefetch msg t0: A = W1m cols 0:64, B half = h rows 0..127 ----
    #pragma unroll
    for (int p = 0; p < 8; p++) {
        int i = p * 256 + tid; int r = i >> 4, k4 = (i & 15) * 4;
        va[p]  = *reinterpret_cast<const float4*>(w1m + (size_t)r * F + k4);
        vbh[p] = *reinterpret_cast<const float4*>(base_h + (size_t)r * DN + k4);
    }

    // ===================== MSG GEMM1 (3 K-tiles of 64) =====================
    for (int t = 0; t < 3; t++) {
        if (t > 0) { MBAR_WAIT(sbase + OFF_MBARA, ph); ph ^= 1; TC_FENCE_AFTER(); }
        // STS A + B-first-half from prefetched regs
        #pragma unroll
        for (int p = 0; p < 8; p++) {
            int i = p * 256 + tid; int r = i >> 4, k4 = (i & 15) * 4;
            split_sts2(smem, OFF_AH + tile_off2(r, k4, 16), 16384, va[p]);
            split_sts2(smem, OFF_BH + tile_off2(r, k4, 32), 32768, vbh[p]);
        }
        // B second half (rows 128..255): LDG + STS
        const float* src = (t == 0) ? base_h : ((t == 1) ? base_a : base_n);
        #pragma unroll
        for (int p = 8; p < 16; p++) {
            int i = p * 256 + tid; int r = i >> 4, k4 = (i & 15) * 4;
            float4 v = *reinterpret_cast<const float4*>(src + (size_t)r * DN + k4);
            split_sts2(smem, OFF_BH + tile_off2(r, k4, 32), 32768, v);
        }
        asm volatile("fence.proxy.async.shared::cta;" ::: "memory");
        __syncthreads();
        if (wid == 0) gemm1_mma(sbase, tmem, t == 0);

        // prefetch next phase (overlaps MMA)
        if (t < 2) {
            const float* nsrc = (t == 0) ? base_a : base_n;
            #pragma unroll
            for (int p = 0; p < 8; p++) {
                int i = p * 256 + tid; int r = i >> 4, k4 = (i & 15) * 4;
                va[p]  = *reinterpret_cast<const float4*>(w1m + (size_t)r * F + (t + 1) * 64 + k4);
                vbh[p] = *reinterpret_cast<const float4*>(nsrc + (size_t)r * DN + k4);
            }
        } else {
            // prefetch W2m [64 x 128]
            #pragma unroll
            for (int p = 0; p < 8; p++) {
                int i = p * 256 + tid; int r = i >> 5, k4 = (i & 31) * 4;
                va[p] = *reinterpret_cast<const float4*>(w2m + (size_t)r * HM + k4);
            }
        }
    }
    MBAR_WAIT(sbase + OFF_MBARA, ph); ph ^= 1;
    TC_FENCE_AFTER();

    // ===================== MSG GEMM2 =====================
    #pragma unroll
    for (int p = 0; p < 8; p++) {
        int i = p * 256 + tid; int r = i >> 5, k4 = (i & 31) * 4;
        split_sts2(smem, OFF_AH + tile_off2(r, k4, 8), 16384, va[p]);
    }
    float bj1m = ((float*)(smem + OFF_B1M))[j];
    gemm2_phase(smem, sbase, tmem, wid, lane, sub, cgrp2, bj1m, 0);

    // prefetch state t0 A: W1s cols 64:128 (overlaps msg epilogue LDTMs)
    #pragma unroll
    for (int p = 0; p < 8; p++) {
        int i = p * 256 + tid; int r = i >> 4, k4 = (i & 15) * 4;
        va[p] = *reinterpret_cast<const float4*>(w1s + (size_t)r * F + 64 + k4);
    }

    // ---- msg epilogue: D2 -> o_msg, pooled, state feat tile in B ----
    #pragma unroll
    for (int q = 0; q < 2; q++) {
        int cgrp = cgrp2 * 2 + q;
        int ch   = cgrp >> 1;
        int jh2  = cgrp & 1;
        uint32_t r[32];
        LDTM_X32(r, tmem + ch * 64 + jh2 * 32);
        TC_WAIT_LD();
        int c  = ch * 128 + sub * 32 + lane;
        int jb = jh2 * 32;
        const float* b2s = (float*)(smem + OFF_B2M);
        float mv[32];
        #pragma unroll
        for (int i2 = 0; i2 < 32; i2++)
            mv[i2] = __uint_as_float(r[i2]) + b2s[jb + i2];
        float* op = o_msg + ((size_t)bn * CN + c) * DN + jb;
        #pragma unroll
        for (int i4 = 0; i4 < 8; i4++)
            *reinterpret_cast<float4*>(op + i4 * 4) =
                make_float4(mv[i4 * 4], mv[i4 * 4 + 1], mv[i4 * 4 + 2], mv[i4 * 4 + 3]);
        #pragma unroll
        for (int i2 = 0; i2 < 32; i2++) {
            __nv_bfloat16 hb = __float2bfloat16(mv[i2]);
            __nv_bfloat16 lb = __float2bfloat16(mv[i2] - __bfloat162float(hb));
            uint32_t off = tile_off2(c, jb + i2, 32);
            *reinterpret_cast<__nv_bfloat16*>(smem + OFF_BH + off) = hb;
            *reinterpret_cast<__nv_bfloat16*>(smem + OFF_BL + off) = lb;
        }
        float psum = 0.0f;
        #pragma unroll
        for (int i2 = 0; i2 < 32; i2++) {
            float v = mv[i2];
            v += __shfl_xor_sync(0xFFFFFFFFu, v, 16);
            v += __shfl_xor_sync(0xFFFFFFFFu, v, 8);
            v += __shfl_xor_sync(0xFFFFFFFFu, v, 4);
            v += __shfl_xor_sync(0xFFFFFFFFu, v, 2);
            v += __shfl_xor_sync(0xFFFFFFFFu, v, 1);
            if (lane == i2) psum = v;
        }
        atomicAdd(&pool[DN + jb + lane], psum);
    }
    asm volatile("fence.proxy.async.shared::cta;" ::: "memory");
    __syncthreads();

    // ===================== STATE GEMM1 (2 K-tiles: msg, h) =====================
    // t0: B = msg tile (already staged), A = W1s cols 64:128 (prefetched)
    #pragma unroll
    for (int p = 0; p < 8; p++) {
        int i = p * 256 + tid; int r = i >> 4, k4 = (i & 15) * 4;
        split_sts2(smem, OFF_AH + tile_off2(r, k4, 16), 16384, va[p]);
    }
    asm volatile("fence.proxy.async.shared::cta;" ::: "memory");
    __syncthreads();
    if (wid == 0) gemm1_mma(sbase, tmem, true);

    // prefetch t1: A = W1s cols 0:64, B half = h rows 0..127 (overlaps t0 MMA)
    #pragma unroll
    for (int p = 0; p < 8; p++) {
        int i = p * 256 + tid; int r = i >> 4, k4 = (i & 15) * 4;
        va[p]  = *reinterpret_cast<const float4*>(w1s + (size_t)r * F + k4);
        vbh[p] = *reinterpret_cast<const float4*>(base_h + (size_t)r * DN + k4);
    }

    MBAR_WAIT(sbase + OFF_MBARA, ph); ph ^= 1; TC_FENCE_AFTER();
    #pragma unroll
    for (int p = 0; p < 8; p++) {
        int i = p * 256 + tid; int r = i >> 4, k4 = (i & 15) * 4;
        split_sts2(smem, OFF_AH + tile_off2(r, k4, 16), 16384, va[p]);
        split_sts2(smem, OFF_BH + tile_off2(r, k4, 32), 32768, vbh[p]);
    }
    #pragma unroll
    for (int p = 8; p < 16; p++) {
        int i = p * 256 + tid; int r = i >> 4, k4 = (i & 15) * 4;
        float4 v = *reinterpret_cast<const float4*>(base_h + (size_t)r * DN + k4);
        split_sts2(smem, OFF_BH + tile_off2(r, k4, 32), 32768, v);
    }
    asm volatile("fence.proxy.async.shared::cta;" ::: "memory");
    __syncthreads();
    if (wid == 0) gemm1_mma(sbase, tmem, false);

    // prefetch W2s (overlaps t1 MMA)
    #pragma unroll
    for (int p = 0; p < 8; p++) {
        int i = p * 256 + tid; int r = i >> 5, k4 = (i & 31) * 4;
        va[p] = *reinterpret_cast<const float4*>(w2s + (size_t)r * HM + k4);
    }

    MBAR_WAIT(sbase + OFF_MBARA, ph); ph ^= 1;
    TC_FENCE_AFTER();

    // ===================== STATE GEMM2 =====================
    #pragma unroll
    for (int p = 0; p < 8; p++) {
        int i = p * 256 + tid; int r = i >> 5, k4 = (i & 31) * 4;
        split_sts2(smem, OFF_AH + tile_off2(r, k4, 8), 16384, va[p]);
    }
    float bj1s = ((float*)(smem + OFF_B1SS))[j];
    gemm2_phase(smem, sbase, tmem, wid, lane, sub, cgrp2, bj1s, 1);

    // ---- state epilogue: D2 + b2s + h residual -> o_h, pooled ----
    #pragma unroll
    for (int q = 0; q < 2; q++) {
        int cgrp = cgrp2 * 2 + q;
        int ch   = cgrp >> 1;
        int jh2  = cgrp & 1;
        uint32_t r[32];
        LDTM_X32(r, tmem + ch * 64 + jh2 * 32);
        TC_WAIT_LD();
        int c  = ch * 128 + sub * 32 + lane;
        int jb = jh2 * 32;
        const float* b2s = (float*)(smem + OFF_B2SS);
        const float* hp = base_h + (size_t)c * DN + jb;
        float hv[32];
        #pragma unroll
        for (int i4 = 0; i4 < 8; i4++) {
            float4 hr = *reinterpret_cast<const float4*>(hp + i4 * 4);
            hv[i4 * 4 + 0] = __uint_as_float(r[i4 * 4 + 0]) + b2s[jb + i4 * 4 + 0] + hr.x;
            hv[i4 * 4 + 1] = __uint_as_float(r[i4 * 4 + 1]) + b2s[jb + i4 * 4 + 1] + hr.y;
            hv[i4 * 4 + 2] = __uint_as_float(r[i4 * 4 + 2]) + b2s[jb + i4 * 4 + 2] + hr.z;
            hv[i4 * 4 + 3] = __uint_as_float(r[i4 * 4 + 3]) + b2s[jb + i4 * 4 + 3] + hr.w;
        }
        float* op = o_h + ((size_t)bn * CN + c) * DN + jb;
        #pragma unroll
        for (int i4 = 0; i4 < 8; i4++)
            *reinterpret_cast<float4*>(op + i4 * 4) =
                make_float4(hv[i4 * 4], hv[i4 * 4 + 1], hv[i4 * 4 + 2], hv[i4 * 4 + 3]);
        float psum = 0.0f;
        #pragma unroll
        for (int i2 = 0; i2 < 32; i2++) {
            float v = hv[i2];
            v += __shfl_xor_sync(0xFFFFFFFFu, v, 16);
            v += __shfl_xor_sync(0xFFFFFFFFu, v, 8);
            v += __shfl_xor_sync(0xFFFFFFFFu, v, 4);
            v += __shfl_xor_sync(0xFFFFFFFFu, v, 2);
            v += __shfl_xor_sync(0xFFFFFFFFu, v, 1);
            if (lane == i2) psum = v;
        }
        atomicAdd(&pool[jb + lane], psum);
    }

    __syncthreads();
    if (tid < 2 * DN)
        g_pooled[(size_t)bn * 2 * DN + tid] = pool[tid] * (1.0f / CN);
    if (wid == 0) TC_DEALLOC(tmem, 256);

#else  // ---------------- SIMT fallback (plain compute_103 pass only) -------
    float* Hs = (float*)(smem + OFF_AH);   // [128][HM], two c-halves
    if (tid < 2 * DN) pool[tid] = 0.0f;
    __syncthreads();

    for (int half = 0; half < 2; half++) {
        int cb = half * 128;
        for (int idx = tid; idx < 128 * HM; idx += 256) {
            int c = cb + (idx >> 7), jj = idx & 127;
            float acc = mb1[g * HM + jj];
            const float* wr = w1m + (size_t)jj * F;
            for (int f = 0; f < DN; f++) acc = fmaf(wr[f],       base_h[(size_t)c * DN + f], acc);
            for (int f = 0; f < DN; f++) acc = fmaf(wr[64 + f],  base_a[(size_t)c * DN + f], acc);
            for (int f = 0; f < DN; f++) acc = fmaf(wr[128 + f], base_n[(size_t)c * DN + f], acc);
            Hs[idx] = gelu_f(acc);
        }
        __syncthreads();
        for (int idx = tid; idx < 128 * DN; idx += 256) {
            int c = cb + (idx >> 6), j2 = idx & 63;
            float acc = mb2[g * DN + j2];
            const float* wr = w2m + (size_t)j2 * HM;
            const float* hr = Hs + (size_t)(idx >> 6) * HM;
            for (int k = 0; k < HM; k++) acc = fmaf(wr[k], hr[k], acc);
            o_msg[((size_t)bn * CN + c) * DN + j2] = acc;
            atomicAdd(&pool[DN + j2], acc);
        }
        __syncthreads();
    }
    for (int half = 0; half < 2; half++) {
        int cb = half * 128;
        for (int idx = tid; idx < 128 * HM; idx += 256) {
            int c = cb + (idx >> 7), jj = idx & 127;
            float acc = sb1[g * HM + jj];
            const float* wr = w1s + (size_t)jj * F;
            for (int f = 0; f < DN; f++) acc = fmaf(wr[f],       base_h[(size_t)c * DN + f], acc);
            for (int f = 0; f < DN; f++) acc = fmaf(wr[64 + f],  o_msg[((size_t)bn * CN + c) * DN + f], acc);
            for (int f = 0; f < DN; f++) acc = fmaf(wr[128 + f], base_c[f], acc);
            Hs[idx] = gelu_f(acc);
        }
        __syncthreads();
        for (int idx = tid; idx < 128 * DN; idx += 256) {
            int c = cb + (idx >> 6), j2 = idx & 63;
            float acc = sb2[g * DN + j2];
            const float* wr = w2s + (size_t)j2 * HM;
            const float* hr = Hs + (size_t)(idx >> 6) * HM;
            for (int k = 0; k < HM; k++) acc = fmaf(wr[k], hr[k], acc);
            acc += base_h[(size_t)c * DN + j2];
            o_h[((size_t)bn * CN + c) * DN + j2] = acc;
            atomicAdd(&pool[j2], acc);
        }
        __syncthreads();
    }
    if (tid < 2 * DN)
        g_pooled[(size_t)bn * 2 * DN + tid] = pool[tid] * (1.0f / CN);
#endif
}

// ---------------------------------------------------------------------------
// Slim modulation MLP: reads pooled stats only.
// ---------------------------------------------------------------------------
__global__ __launch_bounds__(128) void mod_kernel(
    const float* __restrict__ mw1,
    const float* __restrict__ mb1,
    const float* __restrict__ mw2,
    const float* __restrict__ mb2,
    float*       __restrict__ mod)
{
    __shared__ float pooled[2 * DN];
    __shared__ float phh[HMOD];

    int bn  = blockIdx.x;
    int n   = bn & (NC - 1);
    int tid = threadIdx.x;

    if (tid < 2 * DN) pooled[tid] = g_pooled[(size_t)bn * 2 * DN + tid];
    __syncthreads();

    if (tid < HMOD) {
        const float* w = mw1 + (size_t)n * (2 * DN) * HMOD + tid;
        float acc = mb1[n * HMOD + tid];
        #pragma unroll 8
        for (int f = 0; f < 2 * DN; f++) acc = fmaf(pooled[f], w[f * HMOD], acc);
        phh[tid] = gelu_f(acc);
    }
    __syncthreads();

    if (tid < MOD_OUT) {
        const float* w = mw2 + (size_t)n * HMOD * MOD_OUT + tid;
        float acc = mb2[n * MOD_OUT + tid];
        #pragma unroll 8
        for (int k = 0; k < HMOD; k++) acc = fmaf(phh[k], w[k * MOD_OUT], acc);
        mod[bn * MOD_OUT + tid] = acc;
    }
}

// ---------------------------------------------------------------------------
// Launch
// ---------------------------------------------------------------------------
extern "C" void kernel_launch(void* const* d_in, const int* in_sizes, int n_in,
                              void* d_out, int out_size)
{
    const float* h      = (const float*)d_in[0];
    const float* w_conn = (const float*)d_in[1];
    const float* ctx    = (const float*)d_in[2];
    const float* nid    = (const float*)d_in[3];
    const float* mw1    = (const float*)d_in[4];
    const float* mb1    = (const float*)d_in[5];
    const float* mw2    = (const float*)d_in[6];
    const float* mb2    = (const float*)d_in[7];
    const float* sw1    = (const float*)d_in[8];
    const float* sb1    = (const float*)d_in[9];
    const float* sw2    = (const float*)d_in[10];
    const float* sb2    = (const float*)d_in[11];
    const float* modw1  = (const float*)d_in[12];
    const float* modb1  = (const float*)d_in[13];
    const float* modw2  = (const float*)d_in[14];
    const float* modb2  = (const float*)d_in[15];
    const int*   conn   = (const int*)d_in[16];
    const int*   c2g    = (const int*)d_in[17];

    float* out   = (float*)d_out;
    float* o_h   = out;
    float* o_msg = out + (size_t)Bb * NC * CN * DN;
    float* o_mod = o_msg + (size_t)Bb * NC * CN * DN;

    const int grid = Bb * NC;  // 512

    static bool attr_done = false;
    if (!attr_done) {
        cudaFuncSetAttribute(agg_kernel, cudaFuncAttributeMaxDynamicSharedMemorySize, SMEM_AGG);
        cudaFuncSetAttribute(fused_mlp_kernel, cudaFuncAttributeMaxDynamicSharedMemorySize, SMEM_MLP);
        attr_done = true;
    }

    agg_kernel<<<grid, 512, SMEM_AGG>>>(h, w_conn, conn);
    fused_mlp_kernel<<<grid, 256, SMEM_MLP>>>(h, ctx, nid, mw1, mb1, mw2, mb2,
                                              sw1, sb1, sw2, sb2, c2g, o_msg, o_h);
    mod_kernel<<<grid, 128>>>(modw1, modb1, modw2, modb2, o_mod);
}